// round 1
// baseline (speedup 1.0000x reference)
#include <cuda_runtime.h>
#include <math.h>

#define Bn   2
#define Sn   2048
#define HIDn 1536
#define Hn   12
#define HDn  128
#define TOKn (Bn*Sn)

// ---------------- scratch (device globals; no allocations allowed) ----------
__device__ float g_kvd[TOKn*192];
__device__ float g_qd [TOKn*192];
__device__ float g_kc [TOKn*768];
__device__ float g_qc [TOKn*768];
__device__ float g_kr [TOKn*768];
__device__ float g_qr [TOKn*768];
__device__ float g_vf [TOKn*1536];
__device__ float g_q  [(size_t)Bn*Hn*Sn*HDn];
__device__ float g_k  [(size_t)Bn*Hn*Sn*HDn];
__device__ float g_v  [(size_t)Bn*Hn*Sn*HDn];
__device__ float g_at [(size_t)TOKn*HIDn];

// ---------------- SGEMM: C = A(MxK) @ B(KxN), row-major --------------------
// Requires M%128==0, N%64==0, K%16==0 (true for every call here).
__global__ __launch_bounds__(128)
void sgemm_kernel(const float* __restrict__ A, const float* __restrict__ B,
                  float* __restrict__ C, int M, int N, int K) {
  __shared__ float As[16*128];   // As[k][m]
  __shared__ float Bs[16*64];    // Bs[k][n]
  int tid = threadIdx.x;
  int bx = blockIdx.x, by = blockIdx.y;
  int tx = tid & 7, ty = tid >> 3;

  float acc[8][8];
  #pragma unroll
  for (int i=0;i<8;i++)
    #pragma unroll
    for (int j=0;j<8;j++) acc[i][j]=0.f;

  int ac  = (tid & 3) * 4;   // A k-offset (float4)
  int am  = tid >> 2;        // A row base 0..31
  int bn4 = (tid & 15) * 4;  // B n-offset (float4)
  int br  = tid >> 4;        // B k row base 0..7

  const float* Ab = A + (size_t)by*128*K;
  const float* Bb = B + (size_t)bx*64;

  for (int k0 = 0; k0 < K; k0 += 16) {
    #pragma unroll
    for (int p=0;p<4;p++) {
      int m = am + p*32;
      float4 v = *(const float4*)(Ab + (size_t)m*K + k0 + ac);
      As[(ac+0)*128 + m] = v.x;
      As[(ac+1)*128 + m] = v.y;
      As[(ac+2)*128 + m] = v.z;
      As[(ac+3)*128 + m] = v.w;
    }
    #pragma unroll
    for (int p=0;p<2;p++) {
      int r = br + p*8;
      float4 v = *(const float4*)(Bb + (size_t)(k0+r)*N + bn4);
      *(float4*)&Bs[r*64 + bn4] = v;
    }
    __syncthreads();
    #pragma unroll
    for (int kk=0;kk<16;kk++) {
      float a[8], b[8];
      *(float4*)&a[0] = *(float4*)&As[kk*128 + ty*8];
      *(float4*)&a[4] = *(float4*)&As[kk*128 + ty*8 + 4];
      *(float4*)&b[0] = *(float4*)&Bs[kk*64 + tx*8];
      *(float4*)&b[4] = *(float4*)&Bs[kk*64 + tx*8 + 4];
      #pragma unroll
      for (int i=0;i<8;i++)
        #pragma unroll
        for (int j=0;j<8;j++) acc[i][j] += a[i]*b[j];
    }
    __syncthreads();
  }
  #pragma unroll
  for (int i=0;i<8;i++) {
    float* Cr = C + (size_t)(by*128 + ty*8 + i)*N + (size_t)bx*64 + tx*8;
    *(float4*)Cr     = make_float4(acc[i][0],acc[i][1],acc[i][2],acc[i][3]);
    *(float4*)(Cr+4) = make_float4(acc[i][4],acc[i][5],acc[i][6],acc[i][7]);
  }
}

// ---------------- assemble: RoPE + layout + fold 1/sqrt(128) into Q --------
__global__ __launch_bounds__(128)
void assemble_kernel(const float* __restrict__ qc, const float* __restrict__ kc,
                     const float* __restrict__ qr, const float* __restrict__ kr,
                     const float* __restrict__ vf, const float* __restrict__ rot,
                     float* __restrict__ Q, float* __restrict__ Kg,
                     float* __restrict__ Vg) {
  int h = blockIdx.x, s = blockIdx.y, b = blockIdx.z;
  int d = threadIdx.x;                     // 0..127
  int token = b*Sn + s;
  size_t off = ((size_t)(b*Hn + h)*Sn + s)*HDn + d;
  const float SCALE = 0.08838834764831845f;   // 1/sqrt(128)

  Vg[off] = vf[(size_t)token*1536 + h*HDn + d];

  float qv, kv;
  if (d < 64) {
    qv = qc[(size_t)token*768 + h*64 + d];
    kv = kc[(size_t)token*768 + h*64 + d];
  } else {
    int i = d - 64;
    const float* rrow = rot + (size_t)s*64;        // [0:32)=sin, [32:64)=cos
    const float* qrow = qr + (size_t)token*768 + h*64;
    const float* krow = kr + (size_t)token*768 + h*64;
    if (i < 32) {
      float sn = rrow[i], cs = rrow[32+i];
      qv = qrow[i]*cs - qrow[i+32]*sn;
      kv = krow[i]*cs - krow[i+32]*sn;
    } else {
      int ii = i - 32;
      float sn = rrow[ii], cs = rrow[32+ii];
      qv = qrow[ii]*sn + qrow[ii+32]*cs;
      kv = krow[ii]*sn + krow[ii+32]*cs;
    }
  }
  Q[off]  = qv * SCALE;
  Kg[off] = kv;
}

// ---------------- causal flash attention ------------------------------------
// grid (32, H, B), 256 threads. Q/K/V layout [b][h][s][128]. Output -> g_at
// in token-major (b,s, h*128+d) layout ready for the W_o GEMM.
#define QS_STRIDE 132
#define PS_STRIDE 68
#define FLASH_SMEM ((64*QS_STRIDE*2 + 64*128 + 64*PS_STRIDE)*4)

__global__ __launch_bounds__(256)
void flash_kernel(const float* __restrict__ Qg, const float* __restrict__ Kg,
                  const float* __restrict__ Vg, float* __restrict__ Og) {
  extern __shared__ float sm[];
  float* Qs = sm;                        // [64][132]
  float* Ks = Qs + 64*QS_STRIDE;         // [64][132]
  float* Vs = Ks + 64*QS_STRIDE;         // [64][128]
  float* Ps = Vs + 64*128;               // [64][68]  (PsT[j][r])

  int qt = 31 - blockIdx.x;              // longest blocks first
  int h  = blockIdx.y;
  int b  = blockIdx.z;
  int bh = b*Hn + h;
  const float* Qb = Qg + ((size_t)bh*Sn + qt*64)*HDn;
  const float* Kb = Kg + (size_t)bh*Sn*HDn;
  const float* Vb = Vg + (size_t)bh*Sn*HDn;

  int tid = threadIdx.x;
  int tx = tid & 15, ty = tid >> 4;      // 16x16 thread grid

  // load Q tile once
  #pragma unroll
  for (int p=0;p<8;p++) {
    int lin = tid + p*256;               // 0..2047
    int r = lin >> 5, c4 = (lin & 31)*4;
    float4 v = *(const float4*)(Qb + (size_t)r*HDn + c4);
    *(float4*)&Qs[r*QS_STRIDE + c4] = v;
  }
  __syncthreads();

  float m_[4], l_[4], o_[4][8];
  #pragma unroll
  for (int i=0;i<4;i++) {
    m_[i] = -1e30f; l_[i] = 0.f;
    #pragma unroll
    for (int u=0;u<8;u++) o_[i][u] = 0.f;
  }

  for (int jt = 0; jt <= qt; jt++) {
    // load K,V tiles
    #pragma unroll
    for (int p=0;p<8;p++) {
      int lin = tid + p*256;
      int r = lin >> 5, c4 = (lin & 31)*4;
      float4 kv = *(const float4*)(Kb + (size_t)(jt*64 + r)*HDn + c4);
      *(float4*)&Ks[r*QS_STRIDE + c4] = kv;
      float4 vv = *(const float4*)(Vb + (size_t)(jt*64 + r)*HDn + c4);
      *(float4*)&Vs[r*128 + c4] = vv;
    }
    __syncthreads();

    // S = Q @ K^T (4x4 microtile, scale already folded into Q)
    float acc[4][4];
    #pragma unroll
    for (int i=0;i<4;i++)
      #pragma unroll
      for (int j=0;j<4;j++) acc[i][j] = 0.f;

    #pragma unroll 4
    for (int d0=0; d0<128; d0+=4) {
      float4 qv[4], kv[4];
      #pragma unroll
      for (int i=0;i<4;i++) qv[i] = *(float4*)&Qs[(ty*4+i)*QS_STRIDE + d0];
      #pragma unroll
      for (int j=0;j<4;j++) kv[j] = *(float4*)&Ks[(tx*4+j)*QS_STRIDE + d0];
      #pragma unroll
      for (int i=0;i<4;i++)
        #pragma unroll
        for (int j=0;j<4;j++)
          acc[i][j] += qv[i].x*kv[j].x + qv[i].y*kv[j].y
                     + qv[i].z*kv[j].z + qv[i].w*kv[j].w;
    }

    if (jt == qt) {       // diagonal tile: causal mask (local indices suffice)
      #pragma unroll
      for (int i=0;i<4;i++) {
        int gr = ty*4 + i;
        #pragma unroll
        for (int j=0;j<4;j++)
          if (tx*4 + j > gr) acc[i][j] = -1e30f;
      }
    }

    // online softmax (row groups = 16 tx lanes within a warp half)
    float pv[4][4];
    #pragma unroll
    for (int i=0;i<4;i++) {
      float tm = fmaxf(fmaxf(acc[i][0],acc[i][1]), fmaxf(acc[i][2],acc[i][3]));
      #pragma unroll
      for (int off=8; off>=1; off>>=1)
        tm = fmaxf(tm, __shfl_xor_sync(0xffffffffu, tm, off));
      float mnew = fmaxf(m_[i], tm);
      float corr = __expf(m_[i] - mnew);
      float s = 0.f;
      #pragma unroll
      for (int j=0;j<4;j++) { float e = __expf(acc[i][j]-mnew); pv[i][j]=e; s+=e; }
      #pragma unroll
      for (int off=8; off>=1; off>>=1)
        s += __shfl_xor_sync(0xffffffffu, s, off);
      l_[i] = l_[i]*corr + s;
      m_[i] = mnew;
      #pragma unroll
      for (int u=0;u<8;u++) o_[i][u] *= corr;
    }

    // stage P transposed: Ps[j][r]
    #pragma unroll
    for (int j=0;j<4;j++)
      *(float4*)&Ps[(tx*4+j)*PS_STRIDE + ty*4] =
        make_float4(pv[0][j], pv[1][j], pv[2][j], pv[3][j]);
    __syncthreads();

    // O += P @ V (4 rows x 8 cols per thread)
    #pragma unroll 4
    for (int j=0;j<64;j++) {
      float4 a  = *(float4*)&Ps[j*PS_STRIDE + ty*4];
      float4 b0 = *(float4*)&Vs[j*128 + tx*8];
      float4 b1 = *(float4*)&Vs[j*128 + tx*8 + 4];
      float av[4] = {a.x,a.y,a.z,a.w};
      float bv[8] = {b0.x,b0.y,b0.z,b0.w,b1.x,b1.y,b1.z,b1.w};
      #pragma unroll
      for (int i=0;i<4;i++)
        #pragma unroll
        for (int u=0;u<8;u++) o_[i][u] += av[i]*bv[u];
    }
    __syncthreads();
  }

  // normalize + write to token-major attn buffer
  #pragma unroll
  for (int i=0;i<4;i++) {
    float inv = 1.f / l_[i];
    int token = b*Sn + qt*64 + ty*4 + i;
    float* dst = Og + (size_t)token*HIDn + h*HDn + tx*8;
    *(float4*)dst     = make_float4(o_[i][0]*inv,o_[i][1]*inv,o_[i][2]*inv,o_[i][3]*inv);
    *(float4*)(dst+4) = make_float4(o_[i][4]*inv,o_[i][5]*inv,o_[i][6]*inv,o_[i][7]*inv);
  }
}

// ---------------- launch -----------------------------------------------------
extern "C" void kernel_launch(void* const* d_in, const int* in_sizes, int n_in,
                              void* d_out, int out_size) {
  (void)in_sizes; (void)n_in; (void)out_size;
  const float* hs   = (const float*)d_in[0];
  const float* rot  = (const float*)d_in[1];
  const float* Wkvd = (const float*)d_in[2];
  const float* Wqd  = (const float*)d_in[3];
  const float* Wku  = (const float*)d_in[4];
  const float* Wqu  = (const float*)d_in[5];
  const float* Wvu  = (const float*)d_in[6];
  const float* Wrk  = (const float*)d_in[7];
  const float* Wrq  = (const float*)d_in[8];
  const float* Wo   = (const float*)d_in[9];
  float* out = (float*)d_out;

  float *kvd,*qd,*kc,*qc,*kr,*qr,*vf,*q,*k,*v,*at;
  cudaGetSymbolAddress((void**)&kvd, g_kvd);
  cudaGetSymbolAddress((void**)&qd , g_qd );
  cudaGetSymbolAddress((void**)&kc , g_kc );
  cudaGetSymbolAddress((void**)&qc , g_qc );
  cudaGetSymbolAddress((void**)&kr , g_kr );
  cudaGetSymbolAddress((void**)&qr , g_qr );
  cudaGetSymbolAddress((void**)&vf , g_vf );
  cudaGetSymbolAddress((void**)&q  , g_q  );
  cudaGetSymbolAddress((void**)&k  , g_k  );
  cudaGetSymbolAddress((void**)&v  , g_v  );
  cudaGetSymbolAddress((void**)&at , g_at );

  // projections
  sgemm_kernel<<<dim3( 3,32),128>>>(hs , Wkvd, kvd, 4096, 192, 1536);
  sgemm_kernel<<<dim3( 3,32),128>>>(hs , Wqd , qd , 4096, 192, 1536);
  sgemm_kernel<<<dim3(12,32),128>>>(kvd, Wku , kc , 4096, 768, 192);
  sgemm_kernel<<<dim3(12,32),128>>>(qd , Wqu , qc , 4096, 768, 192);
  sgemm_kernel<<<dim3(24,32),128>>>(kvd, Wvu , vf , 4096,1536, 192);
  sgemm_kernel<<<dim3(12,32),128>>>(hs , Wrk , kr , 4096, 768, 1536);
  sgemm_kernel<<<dim3(12,32),128>>>(qd , Wrq , qr , 4096, 768, 192);

  // rope + layout
  assemble_kernel<<<dim3(Hn, Sn, Bn),128>>>(qc,kc,qr,kr,vf,rot, q,k,v);

  // attention
  cudaFuncSetAttribute(flash_kernel, cudaFuncAttributeMaxDynamicSharedMemorySize,
                       FLASH_SMEM);
  flash_kernel<<<dim3(32, Hn, Bn), 256, FLASH_SMEM>>>(q,k,v,at);

  // output projection
  sgemm_kernel<<<dim3(24,32),128>>>(at, Wo, out, 4096,1536,1536);
}

// round 2
// speedup vs baseline: 1.2665x; 1.2665x over previous
#include <cuda_runtime.h>
#include <cuda_bf16.h>
#include <math.h>

#define Bn   2
#define Sn   2048
#define HIDn 1536
#define Hn   12
#define HDn  128
#define TOKn (Bn*Sn)   // 4096

// ---------------- scratch (device globals; no allocations allowed) ----------
// hi/lo split-bf16 buffers: layout [rows][2*K] halves, hi at col k, lo at K+k.
__device__ __nv_bfloat16 g_hsA2[(size_t)TOKn*3072];   // hidden_states split
__device__ __nv_bfloat16 g_Wqkv [(size_t)384*3072];   // W_kv_d|W_q_d  (Bt rows 0..191 kv, 192..383 q)
__device__ __nv_bfloat16 g_Wkv  [(size_t)2304*384];   // W_k_u|W_v_u  (rows 0..767 ku, 768.. vu)
__device__ __nv_bfloat16 g_Wq   [(size_t)1536*384];   // W_q_u|W_rope_q
__device__ __nv_bfloat16 g_Wrk  [(size_t)768*3072];   // W_rope_k
__device__ __nv_bfloat16 g_Wob  [(size_t)1536*3072];  // W_o
__device__ __nv_bfloat16 g_dA2  [(size_t)TOKn*768];   // [tok][2*384]: hi: kvd|qd, lo at +384
__device__ float g_kcvf[(size_t)TOKn*2304];           // [tok][kc(768)|vf(1536)]
__device__ float g_qcqr[(size_t)TOKn*1536];           // [tok][qc(768)|qr(768)]
__device__ float g_krb [(size_t)TOKn*768];
__device__ float g_q  [(size_t)Bn*Hn*Sn*HDn];
__device__ float g_k  [(size_t)Bn*Hn*Sn*HDn];
__device__ float g_v  [(size_t)Bn*Hn*Sn*HDn];
__device__ __nv_bfloat16 g_atA2[(size_t)TOKn*3072];   // attention out split

// ---------------- conversion kernels ----------------------------------------
// X [M][K] fp32 -> Y [M][2K] bf16 (hi|lo)
__global__ __launch_bounds__(256)
void convA_kernel(const float* __restrict__ X, __nv_bfloat16* __restrict__ Y, int K) {
  size_t i = (size_t)blockIdx.x*256 + threadIdx.x;
  float x = X[i];
  size_t row = i / K, col = i % K;
  __nv_bfloat16 hi = __float2bfloat16(x);
  float lo = x - __bfloat162float(hi);
  Y[row*(2*(size_t)K) + col]     = hi;
  Y[row*(2*(size_t)K) + K + col] = __float2bfloat16(lo);
}

// W [K][N] fp32 -> Bt [N][2K] bf16 transposed (hi at [n][k], lo at [n][K+k]).
// grid (N/32, K/32), block (32,8). Out pointer may be pre-offset by n0*ldb.
__global__ __launch_bounds__(256)
void convB_kernel(const float* __restrict__ W, __nv_bfloat16* __restrict__ Bt,
                  int K, int N, int ldb) {
  __shared__ float t[32][33];
  int n0 = blockIdx.x*32, k0 = blockIdx.y*32;
  #pragma unroll
  for (int i = threadIdx.y; i < 32; i += 8)
    t[i][threadIdx.x] = W[(size_t)(k0+i)*N + n0 + threadIdx.x];
  __syncthreads();
  #pragma unroll
  for (int i = threadIdx.y; i < 32; i += 8) {
    int n = n0 + i, k = k0 + threadIdx.x;
    float x = t[threadIdx.x][i];
    __nv_bfloat16 hi = __float2bfloat16(x);
    float lo = x - __bfloat162float(hi);
    Bt[(size_t)n*ldb + k]     = hi;
    Bt[(size_t)n*ldb + K + k] = __float2bfloat16(lo);
  }
}

// ---------------- split-bf16 tensor-core GEMM --------------------------------
// C[M][N] = (Ahi+Alo) @ (Bhi+Blo)^T  approx  (drops lo*lo)
// A layouts: [row][lda] halves; Bt: [n][ldb] halves (k contiguous).
// BM=128, BN=64, BK=32, 256 threads (8 warps, 4x2), warp tile 32x32.
// outmode 0: C fp32 [M][N].  outmode 1: Cb bf16 [M][2N] hi|lo.
#define MMA16816(d0,d1,d2,d3,a0,a1,a2,a3,b0,b1)                           \
  asm volatile("mma.sync.aligned.m16n8k16.row.col.f32.bf16.bf16.f32 "      \
    "{%0,%1,%2,%3},{%4,%5,%6,%7},{%8,%9},{%0,%1,%2,%3};"                   \
    : "+f"(d0),"+f"(d1),"+f"(d2),"+f"(d3)                                   \
    : "r"(a0),"r"(a1),"r"(a2),"r"(a3),"r"(b0),"r"(b1))

__global__ __launch_bounds__(256)
void bfgemm_kernel(const __nv_bfloat16* __restrict__ Ahi,
                   const __nv_bfloat16* __restrict__ Alo, int lda,
                   const __nv_bfloat16* __restrict__ Bhi,
                   const __nv_bfloat16* __restrict__ Blo, int ldb,
                   float* __restrict__ C, __nv_bfloat16* __restrict__ Cb,
                   int N, int K, int outmode) {
  __shared__ __nv_bfloat16 As[2][128*40];   // row stride 40 halves (20 u32)
  __shared__ __nv_bfloat16 Bs[2][64*40];

  int tid = threadIdx.x;
  int bx = blockIdx.x, by = blockIdx.y;
  int KIT = K >> 5, NIT = 3*KIT;

  auto load_tiles = [&](int it, int buf) {
    int seg = (it >= KIT) + (it >= 2*KIT);
    int kk  = (it - seg*KIT) << 5;
    const __nv_bfloat16* Aseg = (seg == 2) ? Alo : Ahi;
    const __nv_bfloat16* Bseg = (seg == 1) ? Blo : Bhi;
    #pragma unroll
    for (int p = 0; p < 2; p++) {
      int c = tid + (p << 8);
      int row = c >> 2, kc = (c & 3) << 3;
      const __nv_bfloat16* src = Aseg + (size_t)(by*128 + row)*lda + kk + kc;
      unsigned d = (unsigned)__cvta_generic_to_shared(&As[buf][row*40 + kc]);
      asm volatile("cp.async.cg.shared.global [%0],[%1],16;" :: "r"(d), "l"(src));
    }
    {
      int row = tid >> 2, kc = (tid & 3) << 3;
      const __nv_bfloat16* src = Bseg + (size_t)(bx*64 + row)*ldb + kk + kc;
      unsigned d = (unsigned)__cvta_generic_to_shared(&Bs[buf][row*40 + kc]);
      asm volatile("cp.async.cg.shared.global [%0],[%1],16;" :: "r"(d), "l"(src));
    }
    asm volatile("cp.async.commit_group;");
  };

  int wid = tid >> 5, lane = tid & 31;
  int wm = wid >> 1, wn = wid & 1;
  int g = lane >> 2, tig = lane & 3;

  float acc[2][4][4];
  #pragma unroll
  for (int mt=0; mt<2; mt++)
    #pragma unroll
    for (int nt=0; nt<4; nt++)
      #pragma unroll
      for (int r=0; r<4; r++) acc[mt][nt][r] = 0.f;

  load_tiles(0, 0);

  for (int it = 0; it < NIT; ++it) {
    if (it + 1 < NIT) {
      load_tiles(it + 1, (it + 1) & 1);
      asm volatile("cp.async.wait_group 1;");
    } else {
      asm volatile("cp.async.wait_group 0;");
    }
    __syncthreads();
    const unsigned* A32 = (const unsigned*)As[it & 1];
    const unsigned* B32 = (const unsigned*)Bs[it & 1];
    #pragma unroll
    for (int ks = 0; ks < 2; ks++) {
      unsigned a[2][4], bf[4][2];
      #pragma unroll
      for (int mt = 0; mt < 2; mt++) {
        int r0 = wm*32 + mt*16;
        a[mt][0] = A32[(r0+g  )*20 + ks*8 + tig  ];
        a[mt][1] = A32[(r0+g+8)*20 + ks*8 + tig  ];
        a[mt][2] = A32[(r0+g  )*20 + ks*8 + tig+4];
        a[mt][3] = A32[(r0+g+8)*20 + ks*8 + tig+4];
      }
      #pragma unroll
      for (int nt = 0; nt < 4; nt++) {
        int n = wn*32 + nt*8 + g;
        bf[nt][0] = B32[n*20 + ks*8 + tig  ];
        bf[nt][1] = B32[n*20 + ks*8 + tig+4];
      }
      #pragma unroll
      for (int mt = 0; mt < 2; mt++)
        #pragma unroll
        for (int nt = 0; nt < 4; nt++)
          MMA16816(acc[mt][nt][0],acc[mt][nt][1],acc[mt][nt][2],acc[mt][nt][3],
                   a[mt][0],a[mt][1],a[mt][2],a[mt][3],
                   bf[nt][0],bf[nt][1]);
    }
    __syncthreads();
  }

  // epilogue
  #pragma unroll
  for (int mt = 0; mt < 2; mt++) {
    #pragma unroll
    for (int nt = 0; nt < 4; nt++) {
      int row = by*128 + wm*32 + mt*16 + g;
      int col = bx*64  + wn*32 + nt*8 + 2*tig;
      if (outmode == 0) {
        float2 v0 = make_float2(acc[mt][nt][0], acc[mt][nt][1]);
        float2 v1 = make_float2(acc[mt][nt][2], acc[mt][nt][3]);
        *(float2*)&C[(size_t)row    *N + col] = v0;
        *(float2*)&C[(size_t)(row+8)*N + col] = v1;
      } else {
        size_t ldc = 2*(size_t)N;
        #pragma unroll
        for (int rr = 0; rr < 2; rr++) {
          float c0 = acc[mt][nt][2*rr], c1 = acc[mt][nt][2*rr+1];
          __nv_bfloat16 h0 = __float2bfloat16(c0), h1 = __float2bfloat16(c1);
          __nv_bfloat16 l0 = __float2bfloat16(c0 - __bfloat162float(h0));
          __nv_bfloat16 l1 = __float2bfloat16(c1 - __bfloat162float(h1));
          size_t base = (size_t)(row + rr*8)*ldc + col;
          *(__nv_bfloat162*)&Cb[base]     = __halves2bfloat162(h0, h1);
          *(__nv_bfloat162*)&Cb[base + N] = __halves2bfloat162(l0, l1);
        }
      }
    }
  }
}

// ---------------- assemble: RoPE + layout + fold 1/sqrt(128) into Q --------
__global__ __launch_bounds__(128)
void assemble_kernel(const float* __restrict__ qcqr, const float* __restrict__ kcvf,
                     const float* __restrict__ krb, const float* __restrict__ rot,
                     float* __restrict__ Q, float* __restrict__ Kg,
                     float* __restrict__ Vg) {
  int h = blockIdx.x, s = blockIdx.y, b = blockIdx.z;
  int d = threadIdx.x;                     // 0..127
  int token = b*Sn + s;
  size_t off = ((size_t)(b*Hn + h)*Sn + s)*HDn + d;
  const float SCALE = 0.08838834764831845f;   // 1/sqrt(128)

  Vg[off] = kcvf[(size_t)token*2304 + 768 + h*HDn + d];

  float qv, kv;
  if (d < 64) {
    qv = qcqr[(size_t)token*1536 + h*64 + d];
    kv = kcvf[(size_t)token*2304 + h*64 + d];
  } else {
    int i = d - 64;
    const float* rrow = rot + (size_t)s*64;        // [0:32)=sin, [32:64)=cos
    const float* qrow = qcqr + (size_t)token*1536 + 768 + h*64;
    const float* krow = krb + (size_t)token*768 + h*64;
    if (i < 32) {
      float sn = rrow[i], cs = rrow[32+i];
      qv = qrow[i]*cs - qrow[i+32]*sn;
      kv = krow[i]*cs - krow[i+32]*sn;
    } else {
      int ii = i - 32;
      float sn = rrow[ii], cs = rrow[32+ii];
      qv = qrow[ii]*sn + qrow[ii+32]*cs;
      kv = krow[ii]*sn + krow[ii+32]*cs;
    }
  }
  Q[off]  = qv * SCALE;
  Kg[off] = kv;
}

// ---------------- causal flash attention ------------------------------------
#define QS_STRIDE 132
#define PS_STRIDE 68
#define FLASH_SMEM ((64*QS_STRIDE*2 + 64*128 + 64*PS_STRIDE)*4)

__global__ __launch_bounds__(256)
void flash_kernel(const float* __restrict__ Qg, const float* __restrict__ Kg,
                  const float* __restrict__ Vg, __nv_bfloat16* __restrict__ At) {
  extern __shared__ float sm[];
  float* Qs = sm;                        // [64][132]
  float* Ks = Qs + 64*QS_STRIDE;         // [64][132]
  float* Vs = Ks + 64*QS_STRIDE;         // [64][128]
  float* Ps = Vs + 64*128;               // [64][68]

  int qt = 31 - blockIdx.x;
  int h  = blockIdx.y;
  int b  = blockIdx.z;
  int bh = b*Hn + h;
  const float* Qb = Qg + ((size_t)bh*Sn + qt*64)*HDn;
  const float* Kb = Kg + (size_t)bh*Sn*HDn;
  const float* Vb = Vg + (size_t)bh*Sn*HDn;

  int tid = threadIdx.x;
  int tx = tid & 15, ty = tid >> 4;

  #pragma unroll
  for (int p=0;p<8;p++) {
    int lin = tid + p*256;
    int r = lin >> 5, c4 = (lin & 31)*4;
    float4 v = *(const float4*)(Qb + (size_t)r*HDn + c4);
    *(float4*)&Qs[r*QS_STRIDE + c4] = v;
  }
  __syncthreads();

  float m_[4], l_[4], o_[4][8];
  #pragma unroll
  for (int i=0;i<4;i++) {
    m_[i] = -1e30f; l_[i] = 0.f;
    #pragma unroll
    for (int u=0;u<8;u++) o_[i][u] = 0.f;
  }

  for (int jt = 0; jt <= qt; jt++) {
    #pragma unroll
    for (int p=0;p<8;p++) {
      int lin = tid + p*256;
      int r = lin >> 5, c4 = (lin & 31)*4;
      float4 kv = *(const float4*)(Kb + (size_t)(jt*64 + r)*HDn + c4);
      *(float4*)&Ks[r*QS_STRIDE + c4] = kv;
      float4 vv = *(const float4*)(Vb + (size_t)(jt*64 + r)*HDn + c4);
      *(float4*)&Vs[r*128 + c4] = vv;
    }
    __syncthreads();

    float acc[4][4];
    #pragma unroll
    for (int i=0;i<4;i++)
      #pragma unroll
      for (int j=0;j<4;j++) acc[i][j] = 0.f;

    #pragma unroll 4
    for (int d0=0; d0<128; d0+=4) {
      float4 qv[4], kv[4];
      #pragma unroll
      for (int i=0;i<4;i++) qv[i] = *(float4*)&Qs[(ty*4+i)*QS_STRIDE + d0];
      #pragma unroll
      for (int j=0;j<4;j++) kv[j] = *(float4*)&Ks[(tx*4+j)*QS_STRIDE + d0];
      #pragma unroll
      for (int i=0;i<4;i++)
        #pragma unroll
        for (int j=0;j<4;j++)
          acc[i][j] += qv[i].x*kv[j].x + qv[i].y*kv[j].y
                     + qv[i].z*kv[j].z + qv[i].w*kv[j].w;
    }

    if (jt == qt) {
      #pragma unroll
      for (int i=0;i<4;i++) {
        int gr = ty*4 + i;
        #pragma unroll
        for (int j=0;j<4;j++)
          if (tx*4 + j > gr) acc[i][j] = -1e30f;
      }
    }

    float pv[4][4];
    #pragma unroll
    for (int i=0;i<4;i++) {
      float tm = fmaxf(fmaxf(acc[i][0],acc[i][1]), fmaxf(acc[i][2],acc[i][3]));
      #pragma unroll
      for (int off=8; off>=1; off>>=1)
        tm = fmaxf(tm, __shfl_xor_sync(0xffffffffu, tm, off));
      float mnew = fmaxf(m_[i], tm);
      float corr = __expf(m_[i] - mnew);
      float s = 0.f;
      #pragma unroll
      for (int j=0;j<4;j++) { float e = __expf(acc[i][j]-mnew); pv[i][j]=e; s+=e; }
      #pragma unroll
      for (int off=8; off>=1; off>>=1)
        s += __shfl_xor_sync(0xffffffffu, s, off);
      l_[i] = l_[i]*corr + s;
      m_[i] = mnew;
      #pragma unroll
      for (int u=0;u<8;u++) o_[i][u] *= corr;
    }

    #pragma unroll
    for (int j=0;j<4;j++)
      *(float4*)&Ps[(tx*4+j)*PS_STRIDE + ty*4] =
        make_float4(pv[0][j], pv[1][j], pv[2][j], pv[3][j]);
    __syncthreads();

    #pragma unroll 4
    for (int j=0;j<64;j++) {
      float4 a  = *(float4*)&Ps[j*PS_STRIDE + ty*4];
      float4 b0 = *(float4*)&Vs[j*128 + tx*8];
      float4 b1 = *(float4*)&Vs[j*128 + tx*8 + 4];
      float av[4] = {a.x,a.y,a.z,a.w};
      float bv[8] = {b0.x,b0.y,b0.z,b0.w,b1.x,b1.y,b1.z,b1.w};
      #pragma unroll
      for (int i=0;i<4;i++)
        #pragma unroll
        for (int u=0;u<8;u++) o_[i][u] += av[i]*bv[u];
    }
    __syncthreads();
  }

  // normalize + write split-bf16 token-major attn buffer [tok][2*1536]
  #pragma unroll
  for (int i=0;i<4;i++) {
    float inv = 1.f / l_[i];
    int token = b*Sn + qt*64 + ty*4 + i;
    __nv_bfloat16* hi = At + (size_t)token*3072 + h*HDn + tx*8;
    __nv_bfloat16* lo = hi + 1536;
    #pragma unroll
    for (int u=0; u<8; u+=2) {
      float v0 = o_[i][u]*inv, v1 = o_[i][u+1]*inv;
      __nv_bfloat16 h0 = __float2bfloat16(v0), h1 = __float2bfloat16(v1);
      *(__nv_bfloat162*)(hi+u) = __halves2bfloat162(h0, h1);
      *(__nv_bfloat162*)(lo+u) = __halves2bfloat162(
          __float2bfloat16(v0 - __bfloat162float(h0)),
          __float2bfloat16(v1 - __bfloat162float(h1)));
    }
  }
}

// ---------------- launch -----------------------------------------------------
extern "C" void kernel_launch(void* const* d_in, const int* in_sizes, int n_in,
                              void* d_out, int out_size) {
  (void)in_sizes; (void)n_in; (void)out_size;
  const float* hs   = (const float*)d_in[0];
  const float* rot  = (const float*)d_in[1];
  const float* Wkvd = (const float*)d_in[2];
  const float* Wqd  = (const float*)d_in[3];
  const float* Wku  = (const float*)d_in[4];
  const float* Wqu  = (const float*)d_in[5];
  const float* Wvu  = (const float*)d_in[6];
  const float* Wrk  = (const float*)d_in[7];
  const float* Wrq  = (const float*)d_in[8];
  const float* Wo   = (const float*)d_in[9];
  float* out = (float*)d_out;

  __nv_bfloat16 *hsA2,*wqkv,*wkv,*wq,*wrk,*wob,*dA2,*atA2;
  float *kcvf,*qcqr,*krb,*q,*k,*v;
  cudaGetSymbolAddress((void**)&hsA2, g_hsA2);
  cudaGetSymbolAddress((void**)&wqkv, g_Wqkv);
  cudaGetSymbolAddress((void**)&wkv , g_Wkv);
  cudaGetSymbolAddress((void**)&wq  , g_Wq);
  cudaGetSymbolAddress((void**)&wrk , g_Wrk);
  cudaGetSymbolAddress((void**)&wob , g_Wob);
  cudaGetSymbolAddress((void**)&dA2 , g_dA2);
  cudaGetSymbolAddress((void**)&kcvf, g_kcvf);
  cudaGetSymbolAddress((void**)&qcqr, g_qcqr);
  cudaGetSymbolAddress((void**)&krb , g_krb);
  cudaGetSymbolAddress((void**)&q   , g_q);
  cudaGetSymbolAddress((void**)&k   , g_k);
  cudaGetSymbolAddress((void**)&v   , g_v);
  cudaGetSymbolAddress((void**)&atA2, g_atA2);

  // --- input conversions (split-bf16) ---
  convA_kernel<<<(TOKn*1536)/256, 256>>>(hs, hsA2, 1536);
  convB_kernel<<<dim3( 6,48), dim3(32,8)>>>(Wkvd, wqkv,                    1536,  192, 3072);
  convB_kernel<<<dim3( 6,48), dim3(32,8)>>>(Wqd , wqkv + (size_t)192*3072, 1536,  192, 3072);
  convB_kernel<<<dim3(24, 6), dim3(32,8)>>>(Wku , wkv,                      192,  768,  384);
  convB_kernel<<<dim3(48, 6), dim3(32,8)>>>(Wvu , wkv + (size_t)768*384,    192, 1536,  384);
  convB_kernel<<<dim3(24, 6), dim3(32,8)>>>(Wqu , wq,                       192,  768,  384);
  convB_kernel<<<dim3(24, 6), dim3(32,8)>>>(Wrq , wq  + (size_t)768*384,    192,  768,  384);
  convB_kernel<<<dim3(24,48), dim3(32,8)>>>(Wrk , wrk,                     1536,  768, 3072);
  convB_kernel<<<dim3(48,48), dim3(32,8)>>>(Wo  , wob,                     1536, 1536, 3072);

  // --- projections on tensor cores (split-bf16) ---
  // qkvd: [4096][384] = hs @ [Wkvd|Wqd],  out split-bf16
  bfgemm_kernel<<<dim3( 6,32),256>>>(hsA2, hsA2+1536, 3072, wqkv, wqkv+1536, 3072,
                                     nullptr, dA2, 384, 1536, 1);
  // kc|vf: [4096][2304] = kvd @ [Wku|Wvu]
  bfgemm_kernel<<<dim3(36,32),256>>>(dA2, dA2+384, 768, wkv, wkv+192, 384,
                                     kcvf, nullptr, 2304, 192, 0);
  // qc|qr: [4096][1536] = qd @ [Wqu|Wrq]
  bfgemm_kernel<<<dim3(24,32),256>>>(dA2+192, dA2+576, 768, wq, wq+192, 384,
                                     qcqr, nullptr, 1536, 192, 0);
  // kr: [4096][768] = hs @ Wrk
  bfgemm_kernel<<<dim3(12,32),256>>>(hsA2, hsA2+1536, 3072, wrk, wrk+1536, 3072,
                                     krb, nullptr, 768, 1536, 0);

  // rope + layout
  assemble_kernel<<<dim3(Hn, Sn, Bn),128>>>(qcqr, kcvf, krb, rot, q, k, v);

  // attention (fp32, emits split-bf16 attn buffer)
  cudaFuncSetAttribute(flash_kernel, cudaFuncAttributeMaxDynamicSharedMemorySize,
                       FLASH_SMEM);
  flash_kernel<<<dim3(32, Hn, Bn), 256, FLASH_SMEM>>>(q, k, v, atA2);

  // output projection
  bfgemm_kernel<<<dim3(24,32),256>>>(atA2, atA2+1536, 3072, wob, wob+1536, 3072,
                                     out, nullptr, 1536, 1536, 0);
}

// round 3
// speedup vs baseline: 2.8403x; 2.2426x over previous
#include <cuda_runtime.h>
#include <cuda_bf16.h>
#include <math.h>

#define Bn   2
#define Sn   2048
#define HIDn 1536
#define Hn   12
#define HDn  128
#define TOKn (Bn*Sn)   // 4096

// ---------------- scratch (device globals; no allocations allowed) ----------
__device__ __nv_bfloat16 g_hsA2[(size_t)TOKn*3072];   // hidden_states split
__device__ __nv_bfloat16 g_Wqkv [(size_t)384*3072];
__device__ __nv_bfloat16 g_Wkv  [(size_t)2304*384];
__device__ __nv_bfloat16 g_Wq   [(size_t)1536*384];
__device__ __nv_bfloat16 g_Wrk  [(size_t)768*3072];
__device__ __nv_bfloat16 g_Wob  [(size_t)1536*3072];
__device__ __nv_bfloat16 g_dA2  [(size_t)TOKn*768];
__device__ float g_kcvf[(size_t)TOKn*2304];
__device__ float g_qcqr[(size_t)TOKn*1536];
__device__ float g_krb [(size_t)TOKn*768];
__device__ __nv_bfloat16 g_qb[(size_t)Bn*Hn*Sn*256];  // [bh][s][hi128|lo128]
__device__ __nv_bfloat16 g_kb[(size_t)Bn*Hn*Sn*256];
__device__ __nv_bfloat16 g_vb[(size_t)Bn*Hn*Sn*256];
__device__ __nv_bfloat16 g_atA2[(size_t)TOKn*3072];

// ---------------- conversion kernels ----------------------------------------
__global__ __launch_bounds__(256)
void convA_kernel(const float* __restrict__ X, __nv_bfloat16* __restrict__ Y, int K) {
  size_t i = (size_t)blockIdx.x*256 + threadIdx.x;
  float x = X[i];
  size_t row = i / K, col = i % K;
  __nv_bfloat16 hi = __float2bfloat16(x);
  float lo = x - __bfloat162float(hi);
  Y[row*(2*(size_t)K) + col]     = hi;
  Y[row*(2*(size_t)K) + K + col] = __float2bfloat16(lo);
}

__global__ __launch_bounds__(256)
void convB_kernel(const float* __restrict__ W, __nv_bfloat16* __restrict__ Bt,
                  int K, int N, int ldb) {
  __shared__ float t[32][33];
  int n0 = blockIdx.x*32, k0 = blockIdx.y*32;
  #pragma unroll
  for (int i = threadIdx.y; i < 32; i += 8)
    t[i][threadIdx.x] = W[(size_t)(k0+i)*N + n0 + threadIdx.x];
  __syncthreads();
  #pragma unroll
  for (int i = threadIdx.y; i < 32; i += 8) {
    int n = n0 + i, k = k0 + threadIdx.x;
    float x = t[threadIdx.x][i];
    __nv_bfloat16 hi = __float2bfloat16(x);
    float lo = x - __bfloat162float(hi);
    Bt[(size_t)n*ldb + k]     = hi;
    Bt[(size_t)n*ldb + K + k] = __float2bfloat16(lo);
  }
}

// ---------------- split-bf16 tensor-core GEMM --------------------------------
#define MMA16816(d0,d1,d2,d3,a0,a1,a2,a3,b0,b1)                           \
  asm volatile("mma.sync.aligned.m16n8k16.row.col.f32.bf16.bf16.f32 "      \
    "{%0,%1,%2,%3},{%4,%5,%6,%7},{%8,%9},{%0,%1,%2,%3};"                   \
    : "+f"(d0),"+f"(d1),"+f"(d2),"+f"(d3)                                   \
    : "r"(a0),"r"(a1),"r"(a2),"r"(a3),"r"(b0),"r"(b1))

__global__ __launch_bounds__(256)
void bfgemm_kernel(const __nv_bfloat16* __restrict__ Ahi,
                   const __nv_bfloat16* __restrict__ Alo, int lda,
                   const __nv_bfloat16* __restrict__ Bhi,
                   const __nv_bfloat16* __restrict__ Blo, int ldb,
                   float* __restrict__ C, __nv_bfloat16* __restrict__ Cb,
                   int N, int K, int outmode) {
  __shared__ __nv_bfloat16 As[2][128*40];
  __shared__ __nv_bfloat16 Bs[2][64*40];

  int tid = threadIdx.x;
  int bx = blockIdx.x, by = blockIdx.y;
  int KIT = K >> 5, NIT = 3*KIT;

  auto load_tiles = [&](int it, int buf) {
    int seg = (it >= KIT) + (it >= 2*KIT);
    int kk  = (it - seg*KIT) << 5;
    const __nv_bfloat16* Aseg = (seg == 2) ? Alo : Ahi;
    const __nv_bfloat16* Bseg = (seg == 1) ? Blo : Bhi;
    #pragma unroll
    for (int p = 0; p < 2; p++) {
      int c = tid + (p << 8);
      int row = c >> 2, kc = (c & 3) << 3;
      const __nv_bfloat16* src = Aseg + (size_t)(by*128 + row)*lda + kk + kc;
      unsigned d = (unsigned)__cvta_generic_to_shared(&As[buf][row*40 + kc]);
      asm volatile("cp.async.cg.shared.global [%0],[%1],16;" :: "r"(d), "l"(src));
    }
    {
      int row = tid >> 2, kc = (tid & 3) << 3;
      const __nv_bfloat16* src = Bseg + (size_t)(bx*64 + row)*ldb + kk + kc;
      unsigned d = (unsigned)__cvta_generic_to_shared(&Bs[buf][row*40 + kc]);
      asm volatile("cp.async.cg.shared.global [%0],[%1],16;" :: "r"(d), "l"(src));
    }
    asm volatile("cp.async.commit_group;");
  };

  int wid = tid >> 5, lane = tid & 31;
  int wm = wid >> 1, wn = wid & 1;
  int g = lane >> 2, tig = lane & 3;

  float acc[2][4][4];
  #pragma unroll
  for (int mt=0; mt<2; mt++)
    #pragma unroll
    for (int nt=0; nt<4; nt++)
      #pragma unroll
      for (int r=0; r<4; r++) acc[mt][nt][r] = 0.f;

  load_tiles(0, 0);

  for (int it = 0; it < NIT; ++it) {
    if (it + 1 < NIT) {
      load_tiles(it + 1, (it + 1) & 1);
      asm volatile("cp.async.wait_group 1;");
    } else {
      asm volatile("cp.async.wait_group 0;");
    }
    __syncthreads();
    const unsigned* A32 = (const unsigned*)As[it & 1];
    const unsigned* B32 = (const unsigned*)Bs[it & 1];
    #pragma unroll
    for (int ks = 0; ks < 2; ks++) {
      unsigned a[2][4], bf[4][2];
      #pragma unroll
      for (int mt = 0; mt < 2; mt++) {
        int r0 = wm*32 + mt*16;
        a[mt][0] = A32[(r0+g  )*20 + ks*8 + tig  ];
        a[mt][1] = A32[(r0+g+8)*20 + ks*8 + tig  ];
        a[mt][2] = A32[(r0+g  )*20 + ks*8 + tig+4];
        a[mt][3] = A32[(r0+g+8)*20 + ks*8 + tig+4];
      }
      #pragma unroll
      for (int nt = 0; nt < 4; nt++) {
        int n = wn*32 + nt*8 + g;
        bf[nt][0] = B32[n*20 + ks*8 + tig  ];
        bf[nt][1] = B32[n*20 + ks*8 + tig+4];
      }
      #pragma unroll
      for (int mt = 0; mt < 2; mt++)
        #pragma unroll
        for (int nt = 0; nt < 4; nt++)
          MMA16816(acc[mt][nt][0],acc[mt][nt][1],acc[mt][nt][2],acc[mt][nt][3],
                   a[mt][0],a[mt][1],a[mt][2],a[mt][3],
                   bf[nt][0],bf[nt][1]);
    }
    __syncthreads();
  }

  #pragma unroll
  for (int mt = 0; mt < 2; mt++) {
    #pragma unroll
    for (int nt = 0; nt < 4; nt++) {
      int row = by*128 + wm*32 + mt*16 + g;
      int col = bx*64  + wn*32 + nt*8 + 2*tig;
      if (outmode == 0) {
        float2 v0 = make_float2(acc[mt][nt][0], acc[mt][nt][1]);
        float2 v1 = make_float2(acc[mt][nt][2], acc[mt][nt][3]);
        *(float2*)&C[(size_t)row    *N + col] = v0;
        *(float2*)&C[(size_t)(row+8)*N + col] = v1;
      } else {
        size_t ldc = 2*(size_t)N;
        #pragma unroll
        for (int rr = 0; rr < 2; rr++) {
          float c0 = acc[mt][nt][2*rr], c1 = acc[mt][nt][2*rr+1];
          __nv_bfloat16 h0 = __float2bfloat16(c0), h1 = __float2bfloat16(c1);
          __nv_bfloat16 l0 = __float2bfloat16(c0 - __bfloat162float(h0));
          __nv_bfloat16 l1 = __float2bfloat16(c1 - __bfloat162float(h1));
          size_t base = (size_t)(row + rr*8)*ldc + col;
          *(__nv_bfloat162*)&Cb[base]     = __halves2bfloat162(h0, h1);
          *(__nv_bfloat162*)&Cb[base + N] = __halves2bfloat162(l0, l1);
        }
      }
    }
  }
}

// ---------------- assemble: RoPE + layout + scale, emit split-bf16 ----------
__global__ __launch_bounds__(128)
void assemble_kernel(const float* __restrict__ qcqr, const float* __restrict__ kcvf,
                     const float* __restrict__ krb, const float* __restrict__ rot,
                     __nv_bfloat16* __restrict__ Qh, __nv_bfloat16* __restrict__ Kh,
                     __nv_bfloat16* __restrict__ Vh) {
  int h = blockIdx.x, s = blockIdx.y, b = blockIdx.z;
  int d = threadIdx.x;
  int token = b*Sn + s;
  size_t base = ((size_t)(b*Hn + h)*Sn + s)*256 + d;
  const float SCALE = 0.08838834764831845f;

  float vv = kcvf[(size_t)token*2304 + 768 + h*HDn + d];
  __nv_bfloat16 vhi = __float2bfloat16(vv);
  Vh[base]     = vhi;
  Vh[base+128] = __float2bfloat16(vv - __bfloat162float(vhi));

  float qv, kv;
  if (d < 64) {
    qv = qcqr[(size_t)token*1536 + h*64 + d];
    kv = kcvf[(size_t)token*2304 + h*64 + d];
  } else {
    int i = d - 64;
    const float* rrow = rot + (size_t)s*64;
    const float* qrow = qcqr + (size_t)token*1536 + 768 + h*64;
    const float* krow = krb + (size_t)token*768 + h*64;
    if (i < 32) {
      float sn = rrow[i], cs = rrow[32+i];
      qv = qrow[i]*cs - qrow[i+32]*sn;
      kv = krow[i]*cs - krow[i+32]*sn;
    } else {
      int ii = i - 32;
      float sn = rrow[ii], cs = rrow[32+ii];
      qv = qrow[ii]*sn + qrow[ii+32]*cs;
      kv = krow[ii]*sn + krow[ii+32]*cs;
    }
  }
  qv *= SCALE;
  __nv_bfloat16 qhi = __float2bfloat16(qv);
  Qh[base]     = qhi;
  Qh[base+128] = __float2bfloat16(qv - __bfloat162float(qhi));
  __nv_bfloat16 khi = __float2bfloat16(kv);
  Kh[base]     = khi;
  Kh[base+128] = __float2bfloat16(kv - __bfloat162float(khi));
}

// ---------------- tensor-core causal flash attention ------------------------
// Q tile 128 rows, K tile 64 keys, 8 warps (16 S-rows each), split-bf16.
#define LDSM_X4T(r0,r1,r2,r3,addr)                                          \
  asm volatile("ldmatrix.sync.aligned.m8n8.x4.trans.shared.b16 "            \
    "{%0,%1,%2,%3},[%4];"                                                   \
    : "=r"(r0),"=r"(r1),"=r"(r2),"=r"(r3) : "r"(addr))

__device__ __forceinline__ unsigned pack2bf(float a, float b) {
  __nv_bfloat162 t = __floats2bfloat162_rn(a, b);
  return *(unsigned*)&t;
}
__device__ __forceinline__ float bfres(float x) {
  return x - __bfloat162float(__float2bfloat16(x));
}

#define FLASH_SMEM 208896   // (2*128*136 + 2*2*64*136 + 2*2*64*136) halves * 2B

__global__ __launch_bounds__(256)
void flash_kernel(const __nv_bfloat16* __restrict__ Qg,
                  const __nv_bfloat16* __restrict__ Kg,
                  const __nv_bfloat16* __restrict__ Vg,
                  __nv_bfloat16* __restrict__ At) {
  extern __shared__ __nv_bfloat16 fsm[];
  __nv_bfloat16* Qs = fsm;            // [2 plane][128][136]
  __nv_bfloat16* Ks = fsm + 34816;    // [2 buf][2 plane][64][136]
  __nv_bfloat16* Vs = fsm + 69632;    // [2 buf][2 plane][64][136]

  int qi = 15 - (int)blockIdx.x;      // longest first
  int h = blockIdx.y, b = blockIdx.z;
  int bh = b*Hn + h;
  int qbase = qi*128;
  const __nv_bfloat16* Qb = Qg + ((size_t)bh*Sn + qbase)*256;
  const __nv_bfloat16* Kb = Kg + (size_t)bh*Sn*256;
  const __nv_bfloat16* Vb = Vg + (size_t)bh*Sn*256;

  int tid = threadIdx.x;
  int wid = tid>>5, lane = tid&31, g = lane>>2, tig = lane&3;
  int jmax = 2*qi + 2;
  int r0 = wid*16;

  // Q load (joins first K/V commit group)
  #pragma unroll
  for (int p=0;p<16;p++){
    int lin = tid + p*256;
    int row = lin>>5, c = lin&31;
    const __nv_bfloat16* src = Qb + (size_t)row*256 + c*8;
    unsigned d = (unsigned)__cvta_generic_to_shared(Qs + (c>>4)*17408 + row*136 + (c&15)*8);
    asm volatile("cp.async.cg.shared.global [%0],[%1],16;" :: "r"(d), "l"(src));
  }
  auto load_kv = [&](int jt, int buf){
    #pragma unroll
    for (int p=0;p<8;p++){
      int lin = tid + p*256;
      int row = lin>>5, c = lin&31;
      size_t s_off = (size_t)(jt*64 + row)*256 + c*8;
      int doff = buf*17408 + (c>>4)*8704 + row*136 + (c&15)*8;
      unsigned dk = (unsigned)__cvta_generic_to_shared(Ks + doff);
      asm volatile("cp.async.cg.shared.global [%0],[%1],16;" :: "r"(dk), "l"(Kb + s_off));
      unsigned dv = (unsigned)__cvta_generic_to_shared(Vs + doff);
      asm volatile("cp.async.cg.shared.global [%0],[%1],16;" :: "r"(dv), "l"(Vb + s_off));
    }
    asm volatile("cp.async.commit_group;");
  };
  load_kv(0, 0);

  float o[16][4];
  #pragma unroll
  for (int nt=0;nt<16;nt++)
    #pragma unroll
    for (int r=0;r<4;r++) o[nt][r] = 0.f;
  float m0=-1e30f, m1=-1e30f, l0=0.f, l1=0.f;

  const unsigned* Q32 = (const unsigned*)Qs;

  for (int jt = 0; jt < jmax; jt++) {
    int buf = jt & 1;
    if (jt + 1 < jmax) {
      load_kv(jt+1, buf^1);
      asm volatile("cp.async.wait_group 1;");
    } else {
      asm volatile("cp.async.wait_group 0;");
    }
    __syncthreads();

    // ---- S = Q @ K^T (split-bf16, 3 passes fused in k-loop) ----
    const unsigned* K32 = (const unsigned*)(Ks + buf*17408);
    float acc[8][4];
    #pragma unroll
    for (int t=0;t<8;t++)
      #pragma unroll
      for (int r=0;r<4;r++) acc[t][r] = 0.f;

    #pragma unroll
    for (int ks=0; ks<8; ks++){
      unsigned ah[4], al[4];
      ah[0] = Q32[(r0+g  )*68 + ks*8 + tig  ];
      ah[1] = Q32[(r0+g+8)*68 + ks*8 + tig  ];
      ah[2] = Q32[(r0+g  )*68 + ks*8 + tig+4];
      ah[3] = Q32[(r0+g+8)*68 + ks*8 + tig+4];
      al[0] = Q32[8704 + (r0+g  )*68 + ks*8 + tig  ];
      al[1] = Q32[8704 + (r0+g+8)*68 + ks*8 + tig  ];
      al[2] = Q32[8704 + (r0+g  )*68 + ks*8 + tig+4];
      al[3] = Q32[8704 + (r0+g+8)*68 + ks*8 + tig+4];
      #pragma unroll
      for (int t=0;t<8;t++){
        unsigned bh0 = K32[(t*8+g)*68 + ks*8 + tig  ];
        unsigned bh1 = K32[(t*8+g)*68 + ks*8 + tig+4];
        unsigned bl0 = K32[4352 + (t*8+g)*68 + ks*8 + tig  ];
        unsigned bl1 = K32[4352 + (t*8+g)*68 + ks*8 + tig+4];
        MMA16816(acc[t][0],acc[t][1],acc[t][2],acc[t][3],
                 ah[0],ah[1],ah[2],ah[3], bh0,bh1);
        MMA16816(acc[t][0],acc[t][1],acc[t][2],acc[t][3],
                 ah[0],ah[1],ah[2],ah[3], bl0,bl1);
        MMA16816(acc[t][0],acc[t][1],acc[t][2],acc[t][3],
                 al[0],al[1],al[2],al[3], bh0,bh1);
      }
    }

    // ---- causal mask (only near diagonal) ----
    if (jt >= jmax-2) {
      int rg0 = qbase + r0 + g, rg1 = rg0 + 8;
      #pragma unroll
      for (int t=0;t<8;t++){
        int c0 = jt*64 + t*8 + 2*tig;
        if (c0   > rg0) acc[t][0] = -1e30f;
        if (c0+1 > rg0) acc[t][1] = -1e30f;
        if (c0   > rg1) acc[t][2] = -1e30f;
        if (c0+1 > rg1) acc[t][3] = -1e30f;
      }
    }

    // ---- online softmax (warp-local: quad shuffles) ----
    float mx0=-1e30f, mx1=-1e30f;
    #pragma unroll
    for (int t=0;t<8;t++){
      mx0 = fmaxf(mx0, fmaxf(acc[t][0],acc[t][1]));
      mx1 = fmaxf(mx1, fmaxf(acc[t][2],acc[t][3]));
    }
    mx0 = fmaxf(mx0, __shfl_xor_sync(0xffffffffu, mx0, 1));
    mx0 = fmaxf(mx0, __shfl_xor_sync(0xffffffffu, mx0, 2));
    mx1 = fmaxf(mx1, __shfl_xor_sync(0xffffffffu, mx1, 1));
    mx1 = fmaxf(mx1, __shfl_xor_sync(0xffffffffu, mx1, 2));
    float nm0 = fmaxf(m0, mx0), nm1 = fmaxf(m1, mx1);
    float cf0 = __expf(m0 - nm0), cf1 = __expf(m1 - nm1);
    m0 = nm0; m1 = nm1;
    float s0 = 0.f, s1 = 0.f;
    #pragma unroll
    for (int t=0;t<8;t++){
      acc[t][0] = __expf(acc[t][0]-nm0);
      acc[t][1] = __expf(acc[t][1]-nm0);
      acc[t][2] = __expf(acc[t][2]-nm1);
      acc[t][3] = __expf(acc[t][3]-nm1);
      s0 += acc[t][0]+acc[t][1];
      s1 += acc[t][2]+acc[t][3];
    }
    s0 += __shfl_xor_sync(0xffffffffu, s0, 1);
    s0 += __shfl_xor_sync(0xffffffffu, s0, 2);
    s1 += __shfl_xor_sync(0xffffffffu, s1, 1);
    s1 += __shfl_xor_sync(0xffffffffu, s1, 2);
    l0 = l0*cf0 + s0;
    l1 = l1*cf1 + s1;
    #pragma unroll
    for (int nt=0;nt<16;nt++){
      o[nt][0] *= cf0; o[nt][1] *= cf0;
      o[nt][2] *= cf1; o[nt][3] *= cf1;
    }

    // ---- O += P @ V (P from registers, V via ldmatrix.trans) ----
    const __nv_bfloat16* Vbuf = Vs + buf*17408;
    int vrow = ((lane>>3)&1)*8 + (lane&7);
    int vcol = (lane>>4)*8;
    #pragma unroll
    for (int u=0;u<4;u++){
      unsigned ph[4], pl[4];
      ph[0] = pack2bf(acc[2*u  ][0], acc[2*u  ][1]);
      ph[1] = pack2bf(acc[2*u  ][2], acc[2*u  ][3]);
      ph[2] = pack2bf(acc[2*u+1][0], acc[2*u+1][1]);
      ph[3] = pack2bf(acc[2*u+1][2], acc[2*u+1][3]);
      pl[0] = pack2bf(bfres(acc[2*u  ][0]), bfres(acc[2*u  ][1]));
      pl[1] = pack2bf(bfres(acc[2*u  ][2]), bfres(acc[2*u  ][3]));
      pl[2] = pack2bf(bfres(acc[2*u+1][0]), bfres(acc[2*u+1][1]));
      pl[3] = pack2bf(bfres(acc[2*u+1][2]), bfres(acc[2*u+1][3]));
      unsigned base_hi = (unsigned)__cvta_generic_to_shared(
          Vbuf + (u*16 + vrow)*136 + vcol);
      unsigned base_lo = base_hi + 17408;   // +plane (8704 halves)
      #pragma unroll
      for (int dt=0;dt<8;dt++){
        unsigned vh0,vh1,vh2,vh3, vl0,vl1,vl2,vl3;
        LDSM_X4T(vh0,vh1,vh2,vh3, base_hi + dt*32);
        LDSM_X4T(vl0,vl1,vl2,vl3, base_lo + dt*32);
        MMA16816(o[dt*2  ][0],o[dt*2  ][1],o[dt*2  ][2],o[dt*2  ][3],
                 ph[0],ph[1],ph[2],ph[3], vh0,vh1);
        MMA16816(o[dt*2  ][0],o[dt*2  ][1],o[dt*2  ][2],o[dt*2  ][3],
                 ph[0],ph[1],ph[2],ph[3], vl0,vl1);
        MMA16816(o[dt*2  ][0],o[dt*2  ][1],o[dt*2  ][2],o[dt*2  ][3],
                 pl[0],pl[1],pl[2],pl[3], vh0,vh1);
        MMA16816(o[dt*2+1][0],o[dt*2+1][1],o[dt*2+1][2],o[dt*2+1][3],
                 ph[0],ph[1],ph[2],ph[3], vh2,vh3);
        MMA16816(o[dt*2+1][0],o[dt*2+1][1],o[dt*2+1][2],o[dt*2+1][3],
                 ph[0],ph[1],ph[2],ph[3], vl2,vl3);
        MMA16816(o[dt*2+1][0],o[dt*2+1][1],o[dt*2+1][2],o[dt*2+1][3],
                 pl[0],pl[1],pl[2],pl[3], vh2,vh3);
      }
    }
    __syncthreads();
  }

  // ---- epilogue: normalize, split-bf16 token-major output ----
  float i0 = 1.f/l0, i1 = 1.f/l1;
  int tok0 = b*Sn + qbase + r0 + g;
  __nv_bfloat16* o0 = At + (size_t)tok0*3072 + h*128;
  __nv_bfloat16* o1 = At + (size_t)(tok0+8)*3072 + h*128;
  #pragma unroll
  for (int nt=0;nt<16;nt++){
    int col = nt*8 + 2*tig;
    float a0 = o[nt][0]*i0, a1 = o[nt][1]*i0;
    float a2 = o[nt][2]*i1, a3 = o[nt][3]*i1;
    __nv_bfloat162 h0 = __floats2bfloat162_rn(a0, a1);
    *(__nv_bfloat162*)(o0 + col) = h0;
    *(__nv_bfloat162*)(o0 + 1536 + col) = __floats2bfloat162_rn(
        a0 - __bfloat162float(h0.x), a1 - __bfloat162float(h0.y));
    __nv_bfloat162 h1 = __floats2bfloat162_rn(a2, a3);
    *(__nv_bfloat162*)(o1 + col) = h1;
    *(__nv_bfloat162*)(o1 + 1536 + col) = __floats2bfloat162_rn(
        a2 - __bfloat162float(h1.x), a3 - __bfloat162float(h1.y));
  }
}

// ---------------- launch -----------------------------------------------------
extern "C" void kernel_launch(void* const* d_in, const int* in_sizes, int n_in,
                              void* d_out, int out_size) {
  (void)in_sizes; (void)n_in; (void)out_size;
  const float* hs   = (const float*)d_in[0];
  const float* rot  = (const float*)d_in[1];
  const float* Wkvd = (const float*)d_in[2];
  const float* Wqd  = (const float*)d_in[3];
  const float* Wku  = (const float*)d_in[4];
  const float* Wqu  = (const float*)d_in[5];
  const float* Wvu  = (const float*)d_in[6];
  const float* Wrk  = (const float*)d_in[7];
  const float* Wrq  = (const float*)d_in[8];
  const float* Wo   = (const float*)d_in[9];
  float* out = (float*)d_out;

  __nv_bfloat16 *hsA2,*wqkv,*wkv,*wq,*wrk,*wob,*dA2,*atA2,*qb,*kb,*vb;
  float *kcvf,*qcqr,*krb;
  cudaGetSymbolAddress((void**)&hsA2, g_hsA2);
  cudaGetSymbolAddress((void**)&wqkv, g_Wqkv);
  cudaGetSymbolAddress((void**)&wkv , g_Wkv);
  cudaGetSymbolAddress((void**)&wq  , g_Wq);
  cudaGetSymbolAddress((void**)&wrk , g_Wrk);
  cudaGetSymbolAddress((void**)&wob , g_Wob);
  cudaGetSymbolAddress((void**)&dA2 , g_dA2);
  cudaGetSymbolAddress((void**)&kcvf, g_kcvf);
  cudaGetSymbolAddress((void**)&qcqr, g_qcqr);
  cudaGetSymbolAddress((void**)&krb , g_krb);
  cudaGetSymbolAddress((void**)&qb  , g_qb);
  cudaGetSymbolAddress((void**)&kb  , g_kb);
  cudaGetSymbolAddress((void**)&vb  , g_vb);
  cudaGetSymbolAddress((void**)&atA2, g_atA2);

  // --- input conversions (split-bf16) ---
  convA_kernel<<<(TOKn*1536)/256, 256>>>(hs, hsA2, 1536);
  convB_kernel<<<dim3( 6,48), dim3(32,8)>>>(Wkvd, wqkv,                    1536,  192, 3072);
  convB_kernel<<<dim3( 6,48), dim3(32,8)>>>(Wqd , wqkv + (size_t)192*3072, 1536,  192, 3072);
  convB_kernel<<<dim3(24, 6), dim3(32,8)>>>(Wku , wkv,                      192,  768,  384);
  convB_kernel<<<dim3(48, 6), dim3(32,8)>>>(Wvu , wkv + (size_t)768*384,    192, 1536,  384);
  convB_kernel<<<dim3(24, 6), dim3(32,8)>>>(Wqu , wq,                       192,  768,  384);
  convB_kernel<<<dim3(24, 6), dim3(32,8)>>>(Wrq , wq  + (size_t)768*384,    192,  768,  384);
  convB_kernel<<<dim3(24,48), dim3(32,8)>>>(Wrk , wrk,                     1536,  768, 3072);
  convB_kernel<<<dim3(48,48), dim3(32,8)>>>(Wo  , wob,                     1536, 1536, 3072);

  // --- projections on tensor cores (split-bf16) ---
  bfgemm_kernel<<<dim3( 6,32),256>>>(hsA2, hsA2+1536, 3072, wqkv, wqkv+1536, 3072,
                                     nullptr, dA2, 384, 1536, 1);
  bfgemm_kernel<<<dim3(36,32),256>>>(dA2, dA2+384, 768, wkv, wkv+192, 384,
                                     kcvf, nullptr, 2304, 192, 0);
  bfgemm_kernel<<<dim3(24,32),256>>>(dA2+192, dA2+576, 768, wq, wq+192, 384,
                                     qcqr, nullptr, 1536, 192, 0);
  bfgemm_kernel<<<dim3(12,32),256>>>(hsA2, hsA2+1536, 3072, wrk, wrk+1536, 3072,
                                     krb, nullptr, 768, 1536, 0);

  // rope + layout (emit split-bf16 q/k/v)
  assemble_kernel<<<dim3(Hn, Sn, Bn),128>>>(qcqr, kcvf, krb, rot, qb, kb, vb);

  // tensor-core flash attention
  cudaFuncSetAttribute(flash_kernel, cudaFuncAttributeMaxDynamicSharedMemorySize,
                       FLASH_SMEM);
  flash_kernel<<<dim3(16, Hn, Bn), 256, FLASH_SMEM>>>(qb, kb, vb, atA2);

  // output projection
  bfgemm_kernel<<<dim3(24,32),256>>>(atA2, atA2+1536, 3072, wob, wob+1536, 3072,
                                     out, nullptr, 1536, 1536, 0);
}

// round 6
// speedup vs baseline: 3.8749x; 1.3643x over previous
#include <cuda_runtime.h>
#include <cuda_fp16.h>
#include <cstdint>
#include <stdint.h>
#include <math.h>

#define Bn   2
#define Sn   2048
#define HIDn 1536
#define Hn   12
#define HDn  128
#define TOKn (Bn*Sn)   // 4096

// ---------------- scratch (device globals; no allocations allowed) ----------
__device__ __half g_hsA2[(size_t)TOKn*3072];     // hidden split fp16 [row][hi1536|lo1536]
__device__ __half g_Wqkv[(size_t)384*1536];      // [n][k] single fp16
__device__ __half g_Wkv [(size_t)2304*192];
__device__ __half g_Wq  [(size_t)1536*192];
__device__ __half g_Wrk [(size_t)768*1536];
__device__ __half g_Wob [(size_t)1536*1536];
__device__ __half g_dA2 [(size_t)TOKn*768];      // [tok][hi:kvd|qd, lo at +384]
__device__ float g_kcvf[(size_t)TOKn*2304];
__device__ float g_qcqr[(size_t)TOKn*1536];
__device__ float g_krb [(size_t)TOKn*768];
__device__ __half g_qb[(size_t)Bn*Hn*Sn*256];    // Q split [s][hi128|lo128]
__device__ __half g_kb[(size_t)Bn*Hn*Sn*128];    // K single
__device__ __half g_vb[(size_t)Bn*Hn*Sn*128];    // V single
__device__ __half g_atA2[(size_t)TOKn*3072];     // attn out split fp16

// ---------------- helpers ----------------------------------------------------
__device__ __forceinline__ unsigned pack2h(float a, float b) {
  __half2 t = __floats2half2_rn(a, b);
  return *(unsigned*)&t;
}
__device__ __forceinline__ float hres(float x) {
  return x - __half2float(__float2half(x));
}

#define MMAF16(d0,d1,d2,d3,a0,a1,a2,a3,b0,b1)                              \
  asm volatile("mma.sync.aligned.m16n8k16.row.col.f32.f16.f16.f32 "         \
    "{%0,%1,%2,%3},{%4,%5,%6,%7},{%8,%9},{%0,%1,%2,%3};"                    \
    : "+f"(d0),"+f"(d1),"+f"(d2),"+f"(d3)                                    \
    : "r"(a0),"r"(a1),"r"(a2),"r"(a3),"r"(b0),"r"(b1))
#define LDSM_X4T(r0,r1,r2,r3,addr)                                          \
  asm volatile("ldmatrix.sync.aligned.m8n8.x4.trans.shared.b16 "            \
    "{%0,%1,%2,%3},[%4];"                                                   \
    : "=r"(r0),"=r"(r1),"=r"(r2),"=r"(r3) : "r"(addr))

// ---------------- conversion kernels ----------------------------------------
__global__ __launch_bounds__(256)
void convA_kernel(const float* __restrict__ X, __half* __restrict__ Y, int K) {
  size_t i = (size_t)blockIdx.x*256 + threadIdx.x;
  float x = X[i];
  size_t row = i / K, col = i % K;
  __half hi = __float2half(x);
  float lo = x - __half2float(hi);
  Y[row*(2*(size_t)K) + col]     = hi;
  Y[row*(2*(size_t)K) + K + col] = __float2half(lo);
}

struct ConvJobs {
  const float* W[8];
  __half* Bt[8];
  int K[8], N[8];
  int bstart[9];
};
__global__ __launch_bounds__(256)
void convW_kernel(ConvJobs J) {
  __shared__ float t[32][33];
  int bx = blockIdx.x;
  int j = 0;
  while (bx >= J.bstart[j+1]) j++;
  int lb = bx - J.bstart[j];
  int nbn = J.N[j] >> 5;
  int n0 = (lb % nbn) << 5, k0 = (lb / nbn) << 5;
  const float* W = J.W[j];
  __half* Bt = J.Bt[j];
  int K = J.K[j], N = J.N[j];
  #pragma unroll
  for (int i = threadIdx.y; i < 32; i += 8)
    t[i][threadIdx.x] = W[(size_t)(k0+i)*N + n0 + threadIdx.x];
  __syncthreads();
  #pragma unroll
  for (int i = threadIdx.y; i < 32; i += 8) {
    int n = n0 + i, k = k0 + threadIdx.x;
    Bt[(size_t)n*K + k] = __float2half(t[threadIdx.x][i]);
  }
}

// ---------------- fp16 2-pass tensor-core GEMM -------------------------------
// C[M][N] = (Ahi+Alo) @ B16^T.  A: [row][lda] (hi ptr, lo ptr). B: [n][K] fp16.
// BM=128, BN=64, BK=32, 256 threads, warp tile 32x32.
// outmode 0: C fp32.  outmode 1: Cb split fp16 [row][2N] hi|lo.
__global__ __launch_bounds__(256)
void hgemm_kernel(const __half* __restrict__ Ahi,
                  const __half* __restrict__ Alo, int lda,
                  const __half* __restrict__ Bm,
                  float* __restrict__ C, __half* __restrict__ Cb,
                  int N, int K, int outmode) {
  __shared__ __half As[2][128*40];
  __shared__ __half Bs[2][64*40];

  int tid = threadIdx.x;
  int bx = blockIdx.x, by = blockIdx.y;
  int KIT = K >> 5, NIT = 2*KIT;

  auto load_tiles = [&](int it, int buf) {
    int seg = (it >= KIT);
    int kk  = (it - seg*KIT) << 5;
    const __half* Aseg = seg ? Alo : Ahi;
    #pragma unroll
    for (int p = 0; p < 2; p++) {
      int c = tid + (p << 8);
      int row = c >> 2, kc = (c & 3) << 3;
      const __half* src = Aseg + (size_t)(by*128 + row)*lda + kk + kc;
      unsigned d = (unsigned)__cvta_generic_to_shared(&As[buf][row*40 + kc]);
      asm volatile("cp.async.cg.shared.global [%0],[%1],16;" :: "r"(d), "l"(src));
    }
    {
      int row = tid >> 2, kc = (tid & 3) << 3;
      const __half* src = Bm + (size_t)(bx*64 + row)*K + kk + kc;
      unsigned d = (unsigned)__cvta_generic_to_shared(&Bs[buf][row*40 + kc]);
      asm volatile("cp.async.cg.shared.global [%0],[%1],16;" :: "r"(d), "l"(src));
    }
    asm volatile("cp.async.commit_group;");
  };

  int wid = tid >> 5, lane = tid & 31;
  int wm = wid >> 1, wn = wid & 1;
  int g = lane >> 2, tig = lane & 3;

  float acc[2][4][4];
  #pragma unroll
  for (int mt=0; mt<2; mt++)
    #pragma unroll
    for (int nt=0; nt<4; nt++)
      #pragma unroll
      for (int r=0; r<4; r++) acc[mt][nt][r] = 0.f;

  load_tiles(0, 0);

  for (int it = 0; it < NIT; ++it) {
    if (it + 1 < NIT) {
      load_tiles(it + 1, (it + 1) & 1);
      asm volatile("cp.async.wait_group 1;");
    } else {
      asm volatile("cp.async.wait_group 0;");
    }
    __syncthreads();
    const unsigned* A32 = (const unsigned*)As[it & 1];
    const unsigned* B32 = (const unsigned*)Bs[it & 1];
    #pragma unroll
    for (int ks = 0; ks < 2; ks++) {
      unsigned a[2][4], bf[4][2];
      #pragma unroll
      for (int mt = 0; mt < 2; mt++) {
        int r0 = wm*32 + mt*16;
        a[mt][0] = A32[(r0+g  )*20 + ks*8 + tig  ];
        a[mt][1] = A32[(r0+g+8)*20 + ks*8 + tig  ];
        a[mt][2] = A32[(r0+g  )*20 + ks*8 + tig+4];
        a[mt][3] = A32[(r0+g+8)*20 + ks*8 + tig+4];
      }
      #pragma unroll
      for (int nt = 0; nt < 4; nt++) {
        int n = wn*32 + nt*8 + g;
        bf[nt][0] = B32[n*20 + ks*8 + tig  ];
        bf[nt][1] = B32[n*20 + ks*8 + tig+4];
      }
      #pragma unroll
      for (int mt = 0; mt < 2; mt++)
        #pragma unroll
        for (int nt = 0; nt < 4; nt++)
          MMAF16(acc[mt][nt][0],acc[mt][nt][1],acc[mt][nt][2],acc[mt][nt][3],
                 a[mt][0],a[mt][1],a[mt][2],a[mt][3],
                 bf[nt][0],bf[nt][1]);
    }
    __syncthreads();
  }

  #pragma unroll
  for (int mt = 0; mt < 2; mt++) {
    #pragma unroll
    for (int nt = 0; nt < 4; nt++) {
      int row = by*128 + wm*32 + mt*16 + g;
      int col = bx*64  + wn*32 + nt*8 + 2*tig;
      if (outmode == 0) {
        float2 v0 = make_float2(acc[mt][nt][0], acc[mt][nt][1]);
        float2 v1 = make_float2(acc[mt][nt][2], acc[mt][nt][3]);
        *(float2*)&C[(size_t)row    *N + col] = v0;
        *(float2*)&C[(size_t)(row+8)*N + col] = v1;
      } else {
        size_t ldc = 2*(size_t)N;
        #pragma unroll
        for (int rr = 0; rr < 2; rr++) {
          float c0 = acc[mt][nt][2*rr], c1 = acc[mt][nt][2*rr+1];
          __half h0 = __float2half(c0), h1 = __float2half(c1);
          float l0 = c0 - __half2float(h0), l1 = c1 - __half2float(h1);
          size_t base = (size_t)(row + rr*8)*ldc + col;
          *(__half2*)&Cb[base]     = __halves2half2(h0, h1);
          *(__half2*)&Cb[base + N] = __floats2half2_rn(l0, l1);
        }
      }
    }
  }
}

// ---------------- assemble: RoPE + layout + scale ---------------------------
__global__ __launch_bounds__(128)
void assemble_kernel(const float* __restrict__ qcqr, const float* __restrict__ kcvf,
                     const float* __restrict__ krb, const float* __restrict__ rot,
                     __half* __restrict__ Qh, __half* __restrict__ Kh,
                     __half* __restrict__ Vh) {
  int h = blockIdx.x, s = blockIdx.y, b = blockIdx.z;
  int d = threadIdx.x;
  int token = b*Sn + s;
  size_t bhs = (size_t)(b*Hn + h)*Sn + s;
  const float SCALE = 0.08838834764831845f;

  Vh[bhs*128 + d] = __float2half(kcvf[(size_t)token*2304 + 768 + h*HDn + d]);

  float qv, kv;
  if (d < 64) {
    qv = qcqr[(size_t)token*1536 + h*64 + d];
    kv = kcvf[(size_t)token*2304 + h*64 + d];
  } else {
    int i = d - 64;
    const float* rrow = rot + (size_t)s*64;
    const float* qrow = qcqr + (size_t)token*1536 + 768 + h*64;
    const float* krow = krb + (size_t)token*768 + h*64;
    if (i < 32) {
      float sn = rrow[i], cs = rrow[32+i];
      qv = qrow[i]*cs - qrow[i+32]*sn;
      kv = krow[i]*cs - krow[i+32]*sn;
    } else {
      int ii = i - 32;
      float sn = rrow[ii], cs = rrow[32+ii];
      qv = qrow[ii]*sn + qrow[ii+32]*cs;
      kv = krow[ii]*sn + krow[ii+32]*cs;
    }
  }
  qv *= SCALE;
  __half qhi = __float2half(qv);
  Qh[bhs*256 + d]       = qhi;
  Qh[bhs*256 + 128 + d] = __float2half(qv - __half2float(qhi));
  Kh[bhs*128 + d] = __float2half(kv);
}

// ---------------- fp16 2-pass causal flash attention -------------------------
// Q tile 128 (split fp16 2 planes), K/V tiles 64 (single fp16), 8 warps.
#define FLASH_SMEM 139264   // (2*128*136 + 2*64*136 + 2*64*136) halves * 2B

__global__ __launch_bounds__(256)
void flash_kernel(const __half* __restrict__ Qg,
                  const __half* __restrict__ Kg,
                  const __half* __restrict__ Vg,
                  __half* __restrict__ At) {
  extern __shared__ __half fsm[];
  __half* Qs = fsm;              // [2 plane][128][136]
  __half* Ks = fsm + 34816;      // [2 buf][64][136]
  __half* Vs = fsm + 52224;      // [2 buf][64][136]

  int qi = 15 - (int)blockIdx.x;
  int h = blockIdx.y, b = blockIdx.z;
  int bh = b*Hn + h;
  int qbase = qi*128;
  const __half* Qb = Qg + ((size_t)bh*Sn + qbase)*256;
  const __half* Kb = Kg + (size_t)bh*Sn*128;
  const __half* Vb = Vg + (size_t)bh*Sn*128;

  int tid = threadIdx.x;
  int wid = tid>>5, lane = tid&31, g = lane>>2, tig = lane&3;
  int jmax = 2*qi + 2;
  int r0 = wid*16;

  // Q load (split: plane = c>>4)
  #pragma unroll
  for (int p=0;p<16;p++){
    int lin = tid + p*256;
    int row = lin>>5, c = lin&31;
    const __half* src = Qb + (size_t)row*256 + c*8;
    unsigned d = (unsigned)__cvta_generic_to_shared(Qs + (c>>4)*17408 + row*136 + (c&15)*8);
    asm volatile("cp.async.cg.shared.global [%0],[%1],16;" :: "r"(d), "l"(src));
  }
  auto load_kv = [&](int jt, int buf){
    #pragma unroll
    for (int p=0;p<4;p++){
      int lin = tid + p*256;
      int row = lin>>4, c = lin&15;
      size_t s_off = (size_t)(jt*64 + row)*128 + c*8;
      int doff = buf*8704 + row*136 + c*8;
      unsigned dk = (unsigned)__cvta_generic_to_shared(Ks + doff);
      asm volatile("cp.async.cg.shared.global [%0],[%1],16;" :: "r"(dk), "l"(Kb + s_off));
      unsigned dv = (unsigned)__cvta_generic_to_shared(Vs + doff);
      asm volatile("cp.async.cg.shared.global [%0],[%1],16;" :: "r"(dv), "l"(Vb + s_off));
    }
    asm volatile("cp.async.commit_group;");
  };
  load_kv(0, 0);

  float o[16][4];
  #pragma unroll
  for (int nt=0;nt<16;nt++)
    #pragma unroll
    for (int r=0;r<4;r++) o[nt][r] = 0.f;
  float m0=-1e30f, m1=-1e30f, l0=0.f, l1=0.f;

  const unsigned* Q32 = (const unsigned*)Qs;

  for (int jt = 0; jt < jmax; jt++) {
    int buf = jt & 1;
    if (jt + 1 < jmax) {
      load_kv(jt+1, buf^1);
      asm volatile("cp.async.wait_group 1;");
    } else {
      asm volatile("cp.async.wait_group 0;");
    }
    __syncthreads();

    // ---- S = Q @ K^T (2-pass: Qhi.K + Qlo.K) ----
    const unsigned* K32 = (const unsigned*)(Ks + buf*8704);
    float acc[8][4];
    #pragma unroll
    for (int t=0;t<8;t++)
      #pragma unroll
      for (int r=0;r<4;r++) acc[t][r] = 0.f;

    #pragma unroll
    for (int ks=0; ks<8; ks++){
      unsigned ah[4], al[4];
      ah[0] = Q32[(r0+g  )*68 + ks*8 + tig  ];
      ah[1] = Q32[(r0+g+8)*68 + ks*8 + tig  ];
      ah[2] = Q32[(r0+g  )*68 + ks*8 + tig+4];
      ah[3] = Q32[(r0+g+8)*68 + ks*8 + tig+4];
      al[0] = Q32[8704 + (r0+g  )*68 + ks*8 + tig  ];
      al[1] = Q32[8704 + (r0+g+8)*68 + ks*8 + tig  ];
      al[2] = Q32[8704 + (r0+g  )*68 + ks*8 + tig+4];
      al[3] = Q32[8704 + (r0+g+8)*68 + ks*8 + tig+4];
      #pragma unroll
      for (int t=0;t<8;t++){
        unsigned b0 = K32[(t*8+g)*68 + ks*8 + tig  ];
        unsigned b1 = K32[(t*8+g)*68 + ks*8 + tig+4];
        MMAF16(acc[t][0],acc[t][1],acc[t][2],acc[t][3],
               ah[0],ah[1],ah[2],ah[3], b0,b1);
        MMAF16(acc[t][0],acc[t][1],acc[t][2],acc[t][3],
               al[0],al[1],al[2],al[3], b0,b1);
      }
    }

    // ---- causal mask (near-diagonal tiles only) ----
    if (jt >= jmax-2) {
      int rg0 = qbase + r0 + g, rg1 = rg0 + 8;
      #pragma unroll
      for (int t=0;t<8;t++){
        int c0 = jt*64 + t*8 + 2*tig;
        if (c0   > rg0) acc[t][0] = -1e30f;
        if (c0+1 > rg0) acc[t][1] = -1e30f;
        if (c0   > rg1) acc[t][2] = -1e30f;
        if (c0+1 > rg1) acc[t][3] = -1e30f;
      }
    }

    // ---- online softmax (warp-local quad shuffles) ----
    float mx0=-1e30f, mx1=-1e30f;
    #pragma unroll
    for (int t=0;t<8;t++){
      mx0 = fmaxf(mx0, fmaxf(acc[t][0],acc[t][1]));
      mx1 = fmaxf(mx1, fmaxf(acc[t][2],acc[t][3]));
    }
    mx0 = fmaxf(mx0, __shfl_xor_sync(0xffffffffu, mx0, 1));
    mx0 = fmaxf(mx0, __shfl_xor_sync(0xffffffffu, mx0, 2));
    mx1 = fmaxf(mx1, __shfl_xor_sync(0xffffffffu, mx1, 1));
    mx1 = fmaxf(mx1, __shfl_xor_sync(0xffffffffu, mx1, 2));
    float nm0 = fmaxf(m0, mx0), nm1 = fmaxf(m1, mx1);
    float cf0 = __expf(m0 - nm0), cf1 = __expf(m1 - nm1);
    m0 = nm0; m1 = nm1;
    float s0 = 0.f, s1 = 0.f;
    #pragma unroll
    for (int t=0;t<8;t++){
      acc[t][0] = __expf(acc[t][0]-nm0);
      acc[t][1] = __expf(acc[t][1]-nm0);
      acc[t][2] = __expf(acc[t][2]-nm1);
      acc[t][3] = __expf(acc[t][3]-nm1);
      s0 += acc[t][0]+acc[t][1];
      s1 += acc[t][2]+acc[t][3];
    }
    s0 += __shfl_xor_sync(0xffffffffu, s0, 1);
    s0 += __shfl_xor_sync(0xffffffffu, s0, 2);
    s1 += __shfl_xor_sync(0xffffffffu, s1, 1);
    s1 += __shfl_xor_sync(0xffffffffu, s1, 2);
    l0 = l0*cf0 + s0;
    l1 = l1*cf1 + s1;
    #pragma unroll
    for (int nt=0;nt<16;nt++){
      o[nt][0] *= cf0; o[nt][1] *= cf0;
      o[nt][2] *= cf1; o[nt][3] *= cf1;
    }

    // ---- O += P @ V (2-pass: Phi.V + Plo.V) ----
    const __half* Vbuf = Vs + buf*8704;
    int vrow = ((lane>>3)&1)*8 + (lane&7);
    int vcol = (lane>>4)*8;
    #pragma unroll
    for (int u=0;u<4;u++){
      unsigned ph[4], pl[4];
      ph[0] = pack2h(acc[2*u  ][0], acc[2*u  ][1]);
      ph[1] = pack2h(acc[2*u  ][2], acc[2*u  ][3]);
      ph[2] = pack2h(acc[2*u+1][0], acc[2*u+1][1]);
      ph[3] = pack2h(acc[2*u+1][2], acc[2*u+1][3]);
      pl[0] = pack2h(hres(acc[2*u  ][0]), hres(acc[2*u  ][1]));
      pl[1] = pack2h(hres(acc[2*u  ][2]), hres(acc[2*u  ][3]));
      pl[2] = pack2h(hres(acc[2*u+1][0]), hres(acc[2*u+1][1]));
      pl[3] = pack2h(hres(acc[2*u+1][2]), hres(acc[2*u+1][3]));
      unsigned base = (unsigned)__cvta_generic_to_shared(
          Vbuf + (u*16 + vrow)*136 + vcol);
      #pragma unroll
      for (int dt=0;dt<8;dt++){
        unsigned v0,v1,v2,v3;
        LDSM_X4T(v0,v1,v2,v3, base + dt*32);
        MMAF16(o[dt*2  ][0],o[dt*2  ][1],o[dt*2  ][2],o[dt*2  ][3],
               ph[0],ph[1],ph[2],ph[3], v0,v1);
        MMAF16(o[dt*2  ][0],o[dt*2  ][1],o[dt*2  ][2],o[dt*2  ][3],
               pl[0],pl[1],pl[2],pl[3], v0,v1);
        MMAF16(o[dt*2+1][0],o[dt*2+1][1],o[dt*2+1][2],o[dt*2+1][3],
               ph[0],ph[1],ph[2],ph[3], v2,v3);
        MMAF16(o[dt*2+1][0],o[dt*2+1][1],o[dt*2+1][2],o[dt*2+1][3],
               pl[0],pl[1],pl[2],pl[3], v2,v3);
      }
    }
    __syncthreads();
  }

  // ---- epilogue: normalize, split-fp16 token-major output ----
  float i0 = 1.f/l0, i1 = 1.f/l1;
  int tok0 = b*Sn + qbase + r0 + g;
  __half* o0 = At + (size_t)tok0*3072 + h*128;
  __half* o1 = At + (size_t)(tok0+8)*3072 + h*128;
  #pragma unroll
  for (int nt=0;nt<16;nt++){
    int col = nt*8 + 2*tig;
    float a0 = o[nt][0]*i0, a1 = o[nt][1]*i0;
    float a2 = o[nt][2]*i1, a3 = o[nt][3]*i1;
    __half2 h0 = __floats2half2_rn(a0, a1);
    *(__half2*)(o0 + col) = h0;
    *(__half2*)(o0 + 1536 + col) = __floats2half2_rn(
        a0 - __half2float(__low2half(h0)), a1 - __half2float(__high2half(h0)));
    __half2 h1 = __floats2half2_rn(a2, a3);
    *(__half2*)(o1 + col) = h1;
    *(__half2*)(o1 + 1536 + col) = __floats2half2_rn(
        a2 - __half2float(__low2half(h1)), a3 - __half2float(__high2half(h1)));
  }
}

// ---------------- launch -----------------------------------------------------
extern "C" void kernel_launch(void* const* d_in, const int* in_sizes, int n_in,
                              void* d_out, int out_size) {
  (void)in_sizes; (void)n_in; (void)out_size;
  const float* hs   = (const float*)d_in[0];
  const float* rot  = (const float*)d_in[1];
  const float* Wkvd = (const float*)d_in[2];
  const float* Wqd  = (const float*)d_in[3];
  const float* Wku  = (const float*)d_in[4];
  const float* Wqu  = (const float*)d_in[5];
  const float* Wvu  = (const float*)d_in[6];
  const float* Wrk  = (const float*)d_in[7];
  const float* Wrq  = (const float*)d_in[8];
  const float* Wo   = (const float*)d_in[9];
  float* out = (float*)d_out;

  __half *hsA2,*wqkv,*wkv,*wq,*wrk,*wob,*dA2,*atA2,*qb,*kb,*vb;
  float *kcvf,*qcqr,*krb;
  cudaGetSymbolAddress((void**)&hsA2, g_hsA2);
  cudaGetSymbolAddress((void**)&wqkv, g_Wqkv);
  cudaGetSymbolAddress((void**)&wkv , g_Wkv);
  cudaGetSymbolAddress((void**)&wq  , g_Wq);
  cudaGetSymbolAddress((void**)&wrk , g_Wrk);
  cudaGetSymbolAddress((void**)&wob , g_Wob);
  cudaGetSymbolAddress((void**)&dA2 , g_dA2);
  cudaGetSymbolAddress((void**)&kcvf, g_kcvf);
  cudaGetSymbolAddress((void**)&qcqr, g_qcqr);
  cudaGetSymbolAddress((void**)&krb , g_krb);
  cudaGetSymbolAddress((void**)&qb  , g_qb);
  cudaGetSymbolAddress((void**)&kb  , g_kb);
  cudaGetSymbolAddress((void**)&vb  , g_vb);
  cudaGetSymbolAddress((void**)&atA2, g_atA2);

  // --- input conversions ---
  convA_kernel<<<(TOKn*1536)/256, 256>>>(hs, hsA2, 1536);
  {
    ConvJobs J;
    const float* Ws[8] = {Wkvd, Wqd, Wku, Wvu, Wqu, Wrq, Wrk, Wo};
    __half* Bs[8] = {wqkv, wqkv + (size_t)192*1536, wkv,
                     wkv + (size_t)768*192, wq, wq + (size_t)768*192,
                     wrk, wob};
    int Ks[8]  = {1536,1536,192,192,192,192,1536,1536};
    int Nsz[8] = {192,192,768,1536,768,768,768,1536};
    int acc = 0;
    for (int j = 0; j < 8; j++) {
      J.W[j] = Ws[j]; J.Bt[j] = Bs[j];
      J.K[j] = Ks[j]; J.N[j] = Nsz[j];
      J.bstart[j] = acc;
      acc += (Nsz[j]/32)*(Ks[j]/32);
    }
    J.bstart[8] = acc;
    convW_kernel<<<acc, dim3(32,8)>>>(J);
  }

  // --- projections (fp16 2-pass tensor cores) ---
  // dA2 [4096][hi384|lo384] = hs @ [Wkvd|Wqd]
  hgemm_kernel<<<dim3( 6,32),256>>>(hsA2, hsA2+1536, 3072, wqkv,
                                    nullptr, dA2, 384, 1536, 1);
  // kc|vf = kvd @ [Wku|Wvu]
  hgemm_kernel<<<dim3(36,32),256>>>(dA2, dA2+384, 768, wkv,
                                    kcvf, nullptr, 2304, 192, 0);
  // qc|qr = qd @ [Wqu|Wrq]
  hgemm_kernel<<<dim3(24,32),256>>>(dA2+192, dA2+576, 768, wq,
                                    qcqr, nullptr, 1536, 192, 0);
  // kr = hs @ Wrk
  hgemm_kernel<<<dim3(12,32),256>>>(hsA2, hsA2+1536, 3072, wrk,
                                    krb, nullptr, 768, 1536, 0);

  // rope + layout
  assemble_kernel<<<dim3(Hn, Sn, Bn),128>>>(qcqr, kcvf, krb, rot, qb, kb, vb);

  // flash attention
  cudaFuncSetAttribute(flash_kernel, cudaFuncAttributeMaxDynamicSharedMemorySize,
                       FLASH_SMEM);
  flash_kernel<<<dim3(16, Hn, Bn), 256, FLASH_SMEM>>>(qb, kb, vb, atA2);

  // output projection
  hgemm_kernel<<<dim3(24,32),256>>>(atA2, atA2+1536, 3072, wob,
                                    out, nullptr, 1536, 1536, 0);
}

// round 7
// speedup vs baseline: 4.0133x; 1.0357x over previous
#include <cuda_runtime.h>
#include <cuda_fp16.h>
#include <cstdint>
#include <stdint.h>
#include <math.h>

#define Bn   2
#define Sn   2048
#define HIDn 1536
#define Hn   12
#define HDn  128
#define TOKn (Bn*Sn)   // 4096

// ---------------- scratch (device globals; no allocations allowed) ----------
__device__ __half g_hsA2[(size_t)TOKn*3072];     // hidden split fp16 [row][hi1536|lo1536]
__device__ __half g_Wqkv[(size_t)384*1536];      // [n][k] single fp16
__device__ __half g_Wkv [(size_t)2304*192];
__device__ __half g_Wq  [(size_t)1536*192];
__device__ __half g_Wrk [(size_t)768*1536];
__device__ __half g_Wob [(size_t)1536*1536];
__device__ __half g_dA2 [(size_t)TOKn*768];      // [tok][hi:kvd|qd, lo at +384]
__device__ float g_kcvf[(size_t)TOKn*2304];
__device__ float g_qcqr[(size_t)TOKn*1536];
__device__ float g_krb [(size_t)TOKn*768];
__device__ __half g_qb[(size_t)Bn*Hn*Sn*256];    // Q split [s][hi128|lo128]
__device__ __half g_kb[(size_t)Bn*Hn*Sn*128];    // K single
__device__ __half g_vb[(size_t)Bn*Hn*Sn*128];    // V single
__device__ __half g_atA2[(size_t)TOKn*3072];     // attn out split fp16

// ---------------- helpers ----------------------------------------------------
__device__ __forceinline__ unsigned pack2h(float a, float b) {
  __half2 t = __floats2half2_rn(a, b);
  return *(unsigned*)&t;
}
__device__ __forceinline__ float hres(float x) {
  return x - __half2float(__float2half(x));
}

#define MMAF16(d0,d1,d2,d3,a0,a1,a2,a3,b0,b1)                              \
  asm volatile("mma.sync.aligned.m16n8k16.row.col.f32.f16.f16.f32 "         \
    "{%0,%1,%2,%3},{%4,%5,%6,%7},{%8,%9},{%0,%1,%2,%3};"                    \
    : "+f"(d0),"+f"(d1),"+f"(d2),"+f"(d3)                                    \
    : "r"(a0),"r"(a1),"r"(a2),"r"(a3),"r"(b0),"r"(b1))
#define LDSM_X4(r0,r1,r2,r3,addr)                                           \
  asm volatile("ldmatrix.sync.aligned.m8n8.x4.shared.b16 "                  \
    "{%0,%1,%2,%3},[%4];"                                                   \
    : "=r"(r0),"=r"(r1),"=r"(r2),"=r"(r3) : "r"(addr))
#define LDSM_X4T(r0,r1,r2,r3,addr)                                          \
  asm volatile("ldmatrix.sync.aligned.m8n8.x4.trans.shared.b16 "            \
    "{%0,%1,%2,%3},[%4];"                                                   \
    : "=r"(r0),"=r"(r1),"=r"(r2),"=r"(r3) : "r"(addr))

// ---------------- conversion kernels ----------------------------------------
__global__ __launch_bounds__(256)
void convA_kernel(const float* __restrict__ X, __half* __restrict__ Y, int K) {
  size_t i = (size_t)blockIdx.x*256 + threadIdx.x;
  float x = X[i];
  size_t row = i / K, col = i % K;
  __half hi = __float2half(x);
  float lo = x - __half2float(hi);
  Y[row*(2*(size_t)K) + col]     = hi;
  Y[row*(2*(size_t)K) + K + col] = __float2half(lo);
}

struct ConvJobs {
  const float* W[8];
  __half* Bt[8];
  int K[8], N[8];
  int bstart[9];
};
__global__ __launch_bounds__(256)
void convW_kernel(ConvJobs J) {
  __shared__ float t[32][33];
  int bx = blockIdx.x;
  int j = 0;
  while (bx >= J.bstart[j+1]) j++;
  int lb = bx - J.bstart[j];
  int nbn = J.N[j] >> 5;
  int n0 = (lb % nbn) << 5, k0 = (lb / nbn) << 5;
  const float* W = J.W[j];
  __half* Bt = J.Bt[j];
  int K = J.K[j], N = J.N[j];
  #pragma unroll
  for (int i = threadIdx.y; i < 32; i += 8)
    t[i][threadIdx.x] = W[(size_t)(k0+i)*N + n0 + threadIdx.x];
  __syncthreads();
  #pragma unroll
  for (int i = threadIdx.y; i < 32; i += 8) {
    int n = n0 + i, k = k0 + threadIdx.x;
    Bt[(size_t)n*K + k] = __float2half(t[threadIdx.x][i]);
  }
}

// ---------------- fp16 2-pass tensor-core GEMM (ldmatrix, 128x128) ----------
// C[M][N] = (Ahi+Alo) @ B16^T.  A: [row][lda] (hi/lo ptrs). B: [n][K] fp16.
// BM=128, BN=128, BK=32, 256 threads (8 warps 2x4), warp tile 64x32.
__global__ __launch_bounds__(256)
void hgemm_kernel(const __half* __restrict__ Ahi,
                  const __half* __restrict__ Alo, int lda,
                  const __half* __restrict__ Bm,
                  float* __restrict__ C, __half* __restrict__ Cb,
                  int N, int K, int outmode) {
  __shared__ __half As[2][128*40];
  __shared__ __half Bs[2][128*40];

  int tid = threadIdx.x;
  int bx = blockIdx.x, by = blockIdx.y;
  int KIT = K >> 5, NIT = 2*KIT;

  auto load_tiles = [&](int it, int buf) {
    int seg = (it >= KIT);
    int kk  = (it - seg*KIT) << 5;
    const __half* Aseg = seg ? Alo : Ahi;
    #pragma unroll
    for (int p = 0; p < 2; p++) {
      int c = tid + (p << 8);
      int row = c >> 2, kc = (c & 3) << 3;
      const __half* srcA = Aseg + (size_t)(by*128 + row)*lda + kk + kc;
      unsigned dA = (unsigned)__cvta_generic_to_shared(&As[buf][row*40 + kc]);
      asm volatile("cp.async.cg.shared.global [%0],[%1],16;" :: "r"(dA), "l"(srcA));
      const __half* srcB = Bm + (size_t)(bx*128 + row)*K + kk + kc;
      unsigned dB = (unsigned)__cvta_generic_to_shared(&Bs[buf][row*40 + kc]);
      asm volatile("cp.async.cg.shared.global [%0],[%1],16;" :: "r"(dB), "l"(srcB));
    }
    asm volatile("cp.async.commit_group;");
  };

  int wid = tid >> 5, lane = tid & 31;
  int wm = wid >> 2, wn = wid & 3;        // 2 x 4 warp grid
  int g = lane >> 2, tig = lane & 3;
  int lr = lane & 15, lc = (lane >> 4) << 3;   // ldmatrix row/col-half select

  float acc[4][4][4];
  #pragma unroll
  for (int mt=0; mt<4; mt++)
    #pragma unroll
    for (int nt=0; nt<4; nt++)
      #pragma unroll
      for (int r=0; r<4; r++) acc[mt][nt][r] = 0.f;

  load_tiles(0, 0);

  for (int it = 0; it < NIT; ++it) {
    if (it + 1 < NIT) {
      load_tiles(it + 1, (it + 1) & 1);
      asm volatile("cp.async.wait_group 1;");
    } else {
      asm volatile("cp.async.wait_group 0;");
    }
    __syncthreads();
    const __half* Ab = As[it & 1];
    const __half* Bb = Bs[it & 1];
    #pragma unroll
    for (int ks = 0; ks < 2; ks++) {
      unsigned a[4][4], b[4][2];
      #pragma unroll
      for (int mt = 0; mt < 4; mt++) {
        unsigned ad = (unsigned)__cvta_generic_to_shared(
            Ab + (wm*64 + mt*16 + lr)*40 + ks*16 + lc);
        LDSM_X4(a[mt][0], a[mt][1], a[mt][2], a[mt][3], ad);
      }
      #pragma unroll
      for (int bt = 0; bt < 2; bt++) {
        unsigned q0,q1,q2,q3;
        unsigned bd = (unsigned)__cvta_generic_to_shared(
            Bb + (wn*32 + bt*16 + lr)*40 + ks*16 + lc);
        LDSM_X4(q0,q1,q2,q3, bd);
        b[2*bt  ][0] = q0; b[2*bt  ][1] = q2;
        b[2*bt+1][0] = q1; b[2*bt+1][1] = q3;
      }
      #pragma unroll
      for (int mt = 0; mt < 4; mt++)
        #pragma unroll
        for (int nt = 0; nt < 4; nt++)
          MMAF16(acc[mt][nt][0],acc[mt][nt][1],acc[mt][nt][2],acc[mt][nt][3],
                 a[mt][0],a[mt][1],a[mt][2],a[mt][3],
                 b[nt][0],b[nt][1]);
    }
    __syncthreads();
  }

  #pragma unroll
  for (int mt = 0; mt < 4; mt++) {
    #pragma unroll
    for (int nt = 0; nt < 4; nt++) {
      int row = by*128 + wm*64 + mt*16 + g;
      int col = bx*128 + wn*32 + nt*8 + 2*tig;
      if (outmode == 0) {
        float2 v0 = make_float2(acc[mt][nt][0], acc[mt][nt][1]);
        float2 v1 = make_float2(acc[mt][nt][2], acc[mt][nt][3]);
        *(float2*)&C[(size_t)row    *N + col] = v0;
        *(float2*)&C[(size_t)(row+8)*N + col] = v1;
      } else {
        size_t ldc = 2*(size_t)N;
        #pragma unroll
        for (int rr = 0; rr < 2; rr++) {
          float c0 = acc[mt][nt][2*rr], c1 = acc[mt][nt][2*rr+1];
          __half h0 = __float2half(c0), h1 = __float2half(c1);
          float l0 = c0 - __half2float(h0), l1 = c1 - __half2float(h1);
          size_t base = (size_t)(row + rr*8)*ldc + col;
          *(__half2*)&Cb[base]     = __halves2half2(h0, h1);
          *(__half2*)&Cb[base + N] = __floats2half2_rn(l0, l1);
        }
      }
    }
  }
}

// ---------------- assemble: RoPE + layout + scale ---------------------------
__global__ __launch_bounds__(128)
void assemble_kernel(const float* __restrict__ qcqr, const float* __restrict__ kcvf,
                     const float* __restrict__ krb, const float* __restrict__ rot,
                     __half* __restrict__ Qh, __half* __restrict__ Kh,
                     __half* __restrict__ Vh) {
  int h = blockIdx.x, s = blockIdx.y, b = blockIdx.z;
  int d = threadIdx.x;
  int token = b*Sn + s;
  size_t bhs = (size_t)(b*Hn + h)*Sn + s;
  const float SCALE = 0.08838834764831845f;

  Vh[bhs*128 + d] = __float2half(kcvf[(size_t)token*2304 + 768 + h*HDn + d]);

  float qv, kv;
  if (d < 64) {
    qv = qcqr[(size_t)token*1536 + h*64 + d];
    kv = kcvf[(size_t)token*2304 + h*64 + d];
  } else {
    int i = d - 64;
    const float* rrow = rot + (size_t)s*64;
    const float* qrow = qcqr + (size_t)token*1536 + 768 + h*64;
    const float* krow = krb + (size_t)token*768 + h*64;
    if (i < 32) {
      float sn = rrow[i], cs = rrow[32+i];
      qv = qrow[i]*cs - qrow[i+32]*sn;
      kv = krow[i]*cs - krow[i+32]*sn;
    } else {
      int ii = i - 32;
      float sn = rrow[ii], cs = rrow[32+ii];
      qv = qrow[ii]*sn + qrow[ii+32]*cs;
      kv = krow[ii]*sn + krow[ii+32]*cs;
    }
  }
  qv *= SCALE;
  __half qhi = __float2half(qv);
  Qh[bhs*256 + d]       = qhi;
  Qh[bhs*256 + 128 + d] = __float2half(qv - __half2float(qhi));
  Kh[bhs*128 + d] = __float2half(kv);
}

// ---------------- fp16 2-pass causal flash attention (ldmatrix) -------------
#define FLASH_SMEM 139264   // (2*128*136 + 2*64*136 + 2*64*136) halves * 2B

__global__ __launch_bounds__(256)
void flash_kernel(const __half* __restrict__ Qg,
                  const __half* __restrict__ Kg,
                  const __half* __restrict__ Vg,
                  __half* __restrict__ At) {
  extern __shared__ __half fsm[];
  __half* Qs = fsm;              // [2 plane][128][136]
  __half* Ks = fsm + 34816;      // [2 buf][64][136]
  __half* Vs = fsm + 52224;      // [2 buf][64][136]

  int qi = 15 - (int)blockIdx.x;
  int h = blockIdx.y, b = blockIdx.z;
  int bh = b*Hn + h;
  int qbase = qi*128;
  const __half* Qb = Qg + ((size_t)bh*Sn + qbase)*256;
  const __half* Kb = Kg + (size_t)bh*Sn*128;
  const __half* Vb = Vg + (size_t)bh*Sn*128;

  int tid = threadIdx.x;
  int wid = tid>>5, lane = tid&31, g = lane>>2, tig = lane&3;
  int lr = lane & 15, lc = (lane >> 4) << 3;
  int jmax = 2*qi + 2;
  int r0 = wid*16;

  // Q load (split: plane = c>>4)
  #pragma unroll
  for (int p=0;p<16;p++){
    int lin = tid + p*256;
    int row = lin>>5, c = lin&31;
    const __half* src = Qb + (size_t)row*256 + c*8;
    unsigned d = (unsigned)__cvta_generic_to_shared(Qs + (c>>4)*17408 + row*136 + (c&15)*8);
    asm volatile("cp.async.cg.shared.global [%0],[%1],16;" :: "r"(d), "l"(src));
  }
  auto load_kv = [&](int jt, int buf){
    #pragma unroll
    for (int p=0;p<4;p++){
      int lin = tid + p*256;
      int row = lin>>4, c = lin&15;
      size_t s_off = (size_t)(jt*64 + row)*128 + c*8;
      int doff = buf*8704 + row*136 + c*8;
      unsigned dk = (unsigned)__cvta_generic_to_shared(Ks + doff);
      asm volatile("cp.async.cg.shared.global [%0],[%1],16;" :: "r"(dk), "l"(Kb + s_off));
      unsigned dv = (unsigned)__cvta_generic_to_shared(Vs + doff);
      asm volatile("cp.async.cg.shared.global [%0],[%1],16;" :: "r"(dv), "l"(Vb + s_off));
    }
    asm volatile("cp.async.commit_group;");
  };
  load_kv(0, 0);

  float o[16][4];
  #pragma unroll
  for (int nt=0;nt<16;nt++)
    #pragma unroll
    for (int r=0;r<4;r++) o[nt][r] = 0.f;
  float m0=-1e30f, m1=-1e30f, l0=0.f, l1=0.f;

  for (int jt = 0; jt < jmax; jt++) {
    int buf = jt & 1;
    if (jt + 1 < jmax) {
      load_kv(jt+1, buf^1);
      asm volatile("cp.async.wait_group 1;");
    } else {
      asm volatile("cp.async.wait_group 0;");
    }
    __syncthreads();

    // ---- S = Q @ K^T (2-pass via ldmatrix fragments) ----
    const __half* Kbuf = Ks + buf*8704;
    float acc[8][4];
    #pragma unroll
    for (int t=0;t<8;t++)
      #pragma unroll
      for (int r=0;r<4;r++) acc[t][r] = 0.f;

    #pragma unroll
    for (int ks=0; ks<8; ks++){
      unsigned ah[4], al[4];
      {
        unsigned qd = (unsigned)__cvta_generic_to_shared(
            Qs + (r0 + lr)*136 + ks*16 + lc);
        LDSM_X4(ah[0],ah[1],ah[2],ah[3], qd);
        LDSM_X4(al[0],al[1],al[2],al[3], qd + 34816);  // +plane (17408 halves)
      }
      unsigned bk[8][2];
      #pragma unroll
      for (int t16=0; t16<4; t16++){
        unsigned q0,q1,q2,q3;
        unsigned kd = (unsigned)__cvta_generic_to_shared(
            Kbuf + (t16*16 + lr)*136 + ks*16 + lc);
        LDSM_X4(q0,q1,q2,q3, kd);
        bk[2*t16  ][0] = q0; bk[2*t16  ][1] = q2;
        bk[2*t16+1][0] = q1; bk[2*t16+1][1] = q3;
      }
      #pragma unroll
      for (int t=0;t<8;t++){
        MMAF16(acc[t][0],acc[t][1],acc[t][2],acc[t][3],
               ah[0],ah[1],ah[2],ah[3], bk[t][0],bk[t][1]);
        MMAF16(acc[t][0],acc[t][1],acc[t][2],acc[t][3],
               al[0],al[1],al[2],al[3], bk[t][0],bk[t][1]);
      }
    }

    // ---- causal mask (near-diagonal tiles only) ----
    if (jt >= jmax-2) {
      int rg0 = qbase + r0 + g, rg1 = rg0 + 8;
      #pragma unroll
      for (int t=0;t<8;t++){
        int c0 = jt*64 + t*8 + 2*tig;
        if (c0   > rg0) acc[t][0] = -1e30f;
        if (c0+1 > rg0) acc[t][1] = -1e30f;
        if (c0   > rg1) acc[t][2] = -1e30f;
        if (c0+1 > rg1) acc[t][3] = -1e30f;
      }
    }

    // ---- online softmax (warp-local quad shuffles) ----
    float mx0=-1e30f, mx1=-1e30f;
    #pragma unroll
    for (int t=0;t<8;t++){
      mx0 = fmaxf(mx0, fmaxf(acc[t][0],acc[t][1]));
      mx1 = fmaxf(mx1, fmaxf(acc[t][2],acc[t][3]));
    }
    mx0 = fmaxf(mx0, __shfl_xor_sync(0xffffffffu, mx0, 1));
    mx0 = fmaxf(mx0, __shfl_xor_sync(0xffffffffu, mx0, 2));
    mx1 = fmaxf(mx1, __shfl_xor_sync(0xffffffffu, mx1, 1));
    mx1 = fmaxf(mx1, __shfl_xor_sync(0xffffffffu, mx1, 2));
    float nm0 = fmaxf(m0, mx0), nm1 = fmaxf(m1, mx1);
    float cf0 = __expf(m0 - nm0), cf1 = __expf(m1 - nm1);
    m0 = nm0; m1 = nm1;
    float s0 = 0.f, s1 = 0.f;
    #pragma unroll
    for (int t=0;t<8;t++){
      acc[t][0] = __expf(acc[t][0]-nm0);
      acc[t][1] = __expf(acc[t][1]-nm0);
      acc[t][2] = __expf(acc[t][2]-nm1);
      acc[t][3] = __expf(acc[t][3]-nm1);
      s0 += acc[t][0]+acc[t][1];
      s1 += acc[t][2]+acc[t][3];
    }
    s0 += __shfl_xor_sync(0xffffffffu, s0, 1);
    s0 += __shfl_xor_sync(0xffffffffu, s0, 2);
    s1 += __shfl_xor_sync(0xffffffffu, s1, 1);
    s1 += __shfl_xor_sync(0xffffffffu, s1, 2);
    l0 = l0*cf0 + s0;
    l1 = l1*cf1 + s1;
    #pragma unroll
    for (int nt=0;nt<16;nt++){
      o[nt][0] *= cf0; o[nt][1] *= cf0;
      o[nt][2] *= cf1; o[nt][3] *= cf1;
    }

    // ---- O += P @ V (2-pass: Phi.V + Plo.V) ----
    const __half* Vbuf = Vs + buf*8704;
    int vrow = ((lane>>3)&1)*8 + (lane&7);
    int vcol = (lane>>4)*8;
    #pragma unroll
    for (int u=0;u<4;u++){
      unsigned ph[4], pl[4];
      ph[0] = pack2h(acc[2*u  ][0], acc[2*u  ][1]);
      ph[1] = pack2h(acc[2*u  ][2], acc[2*u  ][3]);
      ph[2] = pack2h(acc[2*u+1][0], acc[2*u+1][1]);
      ph[3] = pack2h(acc[2*u+1][2], acc[2*u+1][3]);
      pl[0] = pack2h(hres(acc[2*u  ][0]), hres(acc[2*u  ][1]));
      pl[1] = pack2h(hres(acc[2*u  ][2]), hres(acc[2*u  ][3]));
      pl[2] = pack2h(hres(acc[2*u+1][0]), hres(acc[2*u+1][1]));
      pl[3] = pack2h(hres(acc[2*u+1][2]), hres(acc[2*u+1][3]));
      unsigned base = (unsigned)__cvta_generic_to_shared(
          Vbuf + (u*16 + vrow)*136 + vcol);
      #pragma unroll
      for (int dt=0;dt<8;dt++){
        unsigned v0,v1,v2,v3;
        LDSM_X4T(v0,v1,v2,v3, base + dt*32);
        MMAF16(o[dt*2  ][0],o[dt*2  ][1],o[dt*2  ][2],o[dt*2  ][3],
               ph[0],ph[1],ph[2],ph[3], v0,v1);
        MMAF16(o[dt*2  ][0],o[dt*2  ][1],o[dt*2  ][2],o[dt*2  ][3],
               pl[0],pl[1],pl[2],pl[3], v0,v1);
        MMAF16(o[dt*2+1][0],o[dt*2+1][1],o[dt*2+1][2],o[dt*2+1][3],
               ph[0],ph[1],ph[2],ph[3], v2,v3);
        MMAF16(o[dt*2+1][0],o[dt*2+1][1],o[dt*2+1][2],o[dt*2+1][3],
               pl[0],pl[1],pl[2],pl[3], v2,v3);
      }
    }
    __syncthreads();
  }

  // ---- epilogue: normalize, split-fp16 token-major output ----
  float i0 = 1.f/l0, i1 = 1.f/l1;
  int tok0 = b*Sn + qbase + r0 + g;
  __half* o0 = At + (size_t)tok0*3072 + h*128;
  __half* o1 = At + (size_t)(tok0+8)*3072 + h*128;
  #pragma unroll
  for (int nt=0;nt<16;nt++){
    int col = nt*8 + 2*tig;
    float a0 = o[nt][0]*i0, a1 = o[nt][1]*i0;
    float a2 = o[nt][2]*i1, a3 = o[nt][3]*i1;
    __half2 h0 = __floats2half2_rn(a0, a1);
    *(__half2*)(o0 + col) = h0;
    *(__half2*)(o0 + 1536 + col) = __floats2half2_rn(
        a0 - __half2float(__low2half(h0)), a1 - __half2float(__high2half(h0)));
    __half2 h1 = __floats2half2_rn(a2, a3);
    *(__half2*)(o1 + col) = h1;
    *(__half2*)(o1 + 1536 + col) = __floats2half2_rn(
        a2 - __half2float(__low2half(h1)), a3 - __half2float(__high2half(h1)));
  }
}

// ---------------- launch -----------------------------------------------------
extern "C" void kernel_launch(void* const* d_in, const int* in_sizes, int n_in,
                              void* d_out, int out_size) {
  (void)in_sizes; (void)n_in; (void)out_size;
  const float* hs   = (const float*)d_in[0];
  const float* rot  = (const float*)d_in[1];
  const float* Wkvd = (const float*)d_in[2];
  const float* Wqd  = (const float*)d_in[3];
  const float* Wku  = (const float*)d_in[4];
  const float* Wqu  = (const float*)d_in[5];
  const float* Wvu  = (const float*)d_in[6];
  const float* Wrk  = (const float*)d_in[7];
  const float* Wrq  = (const float*)d_in[8];
  const float* Wo   = (const float*)d_in[9];
  float* out = (float*)d_out;

  __half *hsA2,*wqkv,*wkv,*wq,*wrk,*wob,*dA2,*atA2,*qb,*kb,*vb;
  float *kcvf,*qcqr,*krb;
  cudaGetSymbolAddress((void**)&hsA2, g_hsA2);
  cudaGetSymbolAddress((void**)&wqkv, g_Wqkv);
  cudaGetSymbolAddress((void**)&wkv , g_Wkv);
  cudaGetSymbolAddress((void**)&wq  , g_Wq);
  cudaGetSymbolAddress((void**)&wrk , g_Wrk);
  cudaGetSymbolAddress((void**)&wob , g_Wob);
  cudaGetSymbolAddress((void**)&dA2 , g_dA2);
  cudaGetSymbolAddress((void**)&kcvf, g_kcvf);
  cudaGetSymbolAddress((void**)&qcqr, g_qcqr);
  cudaGetSymbolAddress((void**)&krb , g_krb);
  cudaGetSymbolAddress((void**)&qb  , g_qb);
  cudaGetSymbolAddress((void**)&kb  , g_kb);
  cudaGetSymbolAddress((void**)&vb  , g_vb);
  cudaGetSymbolAddress((void**)&atA2, g_atA2);

  // --- input conversions ---
  convA_kernel<<<(TOKn*1536)/256, 256>>>(hs, hsA2, 1536);
  {
    ConvJobs J;
    const float* Ws[8] = {Wkvd, Wqd, Wku, Wvu, Wqu, Wrq, Wrk, Wo};
    __half* Bs[8] = {wqkv, wqkv + (size_t)192*1536, wkv,
                     wkv + (size_t)768*192, wq, wq + (size_t)768*192,
                     wrk, wob};
    int Ks[8]  = {1536,1536,192,192,192,192,1536,1536};
    int Nsz[8] = {192,192,768,1536,768,768,768,1536};
    int acc = 0;
    for (int j = 0; j < 8; j++) {
      J.W[j] = Ws[j]; J.Bt[j] = Bs[j];
      J.K[j] = Ks[j]; J.N[j] = Nsz[j];
      J.bstart[j] = acc;
      acc += (Nsz[j]/32)*(Ks[j]/32);
    }
    J.bstart[8] = acc;
    convW_kernel<<<acc, dim3(32,8)>>>(J);
  }

  // --- projections (fp16 2-pass tensor cores) ---
  hgemm_kernel<<<dim3( 3,32),256>>>(hsA2, hsA2+1536, 3072, wqkv,
                                    nullptr, dA2, 384, 1536, 1);
  hgemm_kernel<<<dim3(18,32),256>>>(dA2, dA2+384, 768, wkv,
                                    kcvf, nullptr, 2304, 192, 0);
  hgemm_kernel<<<dim3(12,32),256>>>(dA2+192, dA2+576, 768, wq,
                                    qcqr, nullptr, 1536, 192, 0);
  hgemm_kernel<<<dim3( 6,32),256>>>(hsA2, hsA2+1536, 3072, wrk,
                                    krb, nullptr, 768, 1536, 0);

  // rope + layout
  assemble_kernel<<<dim3(Hn, Sn, Bn),128>>>(qcqr, kcvf, krb, rot, qb, kb, vb);

  // flash attention
  cudaFuncSetAttribute(flash_kernel, cudaFuncAttributeMaxDynamicSharedMemorySize,
                       FLASH_SMEM);
  flash_kernel<<<dim3(16, Hn, Bn), 256, FLASH_SMEM>>>(qb, kb, vb, atA2);

  // output projection
  hgemm_kernel<<<dim3(12,32),256>>>(atA2, atA2+1536, 3072, wob,
                                    out, nullptr, 1536, 1536, 0);
}

// round 8
// speedup vs baseline: 4.6807x; 1.1663x over previous
#include <cuda_runtime.h>
#include <cuda_fp16.h>
#include <cstdint>
#include <stdint.h>
#include <math.h>

#define Bn   2
#define Sn   2048
#define HIDn 1536
#define Hn   12
#define HDn  128
#define TOKn (Bn*Sn)   // 4096

// ---------------- scratch (device globals; no allocations allowed) ----------
__device__ __half g_hsA2[(size_t)TOKn*3072];     // hidden split fp16 [row][hi1536|lo1536]
__device__ __half g_Wqkv[(size_t)384*1536];      // [n][k] single fp16
__device__ __half g_Wkv [(size_t)2304*192];
__device__ __half g_Wq  [(size_t)1536*192];
__device__ __half g_Wrk [(size_t)768*1536];
__device__ __half g_Wob [(size_t)1536*1536];
__device__ __half g_dA2 [(size_t)TOKn*768];      // [tok][hi:kvd|qd, lo at +384]
__device__ float g_kcvf[(size_t)TOKn*2304];
__device__ float g_qcqr[(size_t)TOKn*1536];
__device__ float g_krb [(size_t)TOKn*768];
__device__ __half g_qb[(size_t)Bn*Hn*Sn*256];    // Q split [s][hi128|lo128]
__device__ __half g_kb[(size_t)Bn*Hn*Sn*128];    // K single
__device__ __half g_vb[(size_t)Bn*Hn*Sn*128];    // V single
__device__ __half g_atA2[(size_t)TOKn*3072];     // attn out split fp16

// ---------------- helpers ----------------------------------------------------
__device__ __forceinline__ unsigned pack2h(float a, float b) {
  __half2 t = __floats2half2_rn(a, b);
  return *(unsigned*)&t;
}
__device__ __forceinline__ float hres(float x) {
  return x - __half2float(__float2half(x));
}

#define MMAF16(d0,d1,d2,d3,a0,a1,a2,a3,b0,b1)                              \
  asm volatile("mma.sync.aligned.m16n8k16.row.col.f32.f16.f16.f32 "         \
    "{%0,%1,%2,%3},{%4,%5,%6,%7},{%8,%9},{%0,%1,%2,%3};"                    \
    : "+f"(d0),"+f"(d1),"+f"(d2),"+f"(d3)                                    \
    : "r"(a0),"r"(a1),"r"(a2),"r"(a3),"r"(b0),"r"(b1))
#define LDSM_X4(r0,r1,r2,r3,addr)                                           \
  asm volatile("ldmatrix.sync.aligned.m8n8.x4.shared.b16 "                  \
    "{%0,%1,%2,%3},[%4];"                                                   \
    : "=r"(r0),"=r"(r1),"=r"(r2),"=r"(r3) : "r"(addr))
#define LDSM_X4T(r0,r1,r2,r3,addr)                                          \
  asm volatile("ldmatrix.sync.aligned.m8n8.x4.trans.shared.b16 "            \
    "{%0,%1,%2,%3},[%4];"                                                   \
    : "=r"(r0),"=r"(r1),"=r"(r2),"=r"(r3) : "r"(addr))
#define CPASYNC16(dst, src)                                                 \
  asm volatile("cp.async.cg.shared.global [%0],[%1],16;" :: "r"(dst), "l"(src))

// ---------------- conversion kernels ----------------------------------------
__global__ __launch_bounds__(256)
void convA_kernel(const float* __restrict__ X, __half* __restrict__ Y, int K) {
  size_t i = (size_t)blockIdx.x*256 + threadIdx.x;
  float x = X[i];
  size_t row = i / K, col = i % K;
  __half hi = __float2half(x);
  float lo = x - __half2float(hi);
  Y[row*(2*(size_t)K) + col]     = hi;
  Y[row*(2*(size_t)K) + K + col] = __float2half(lo);
}

struct ConvJobs {
  const float* W[8];
  __half* Bt[8];
  int K[8], N[8];
  int bstart[9];
};
__global__ __launch_bounds__(256)
void convW_kernel(ConvJobs J) {
  __shared__ float t[32][33];
  int bx = blockIdx.x;
  int j = 0;
  while (bx >= J.bstart[j+1]) j++;
  int lb = bx - J.bstart[j];
  int nbn = J.N[j] >> 5;
  int n0 = (lb % nbn) << 5, k0 = (lb / nbn) << 5;
  const float* W = J.W[j];
  __half* Bt = J.Bt[j];
  int K = J.K[j], N = J.N[j];
  #pragma unroll
  for (int i = threadIdx.y; i < 32; i += 8)
    t[i][threadIdx.x] = W[(size_t)(k0+i)*N + n0 + threadIdx.x];
  __syncthreads();
  #pragma unroll
  for (int i = threadIdx.y; i < 32; i += 8) {
    int n = n0 + i, k = k0 + threadIdx.x;
    Bt[(size_t)n*K + k] = __float2half(t[threadIdx.x][i]);
  }
}

// ---------------- fp16 2-pass fused tensor-core GEMM -------------------------
// C[M][N] = (Ahi+Alo) @ B16^T, hi/lo passes fused per K-chunk (B loaded once).
// BM=128, BN=128, BK=64, 256 threads (8 warps 2x4), warp tile 64x32.
// Stage layout (halves): [Ahi 128x72][Alo 128x72][B 128x72], 2 stages.
#define HG_STAGE  27648                 // halves per stage
#define HG_SMEM   (2*HG_STAGE*2)        // bytes = 110592
__global__ __launch_bounds__(256)
void hgemm_kernel(const __half* __restrict__ Ahi,
                  const __half* __restrict__ Alo, int lda,
                  const __half* __restrict__ Bm,
                  float* __restrict__ C, __half* __restrict__ Cb,
                  int N, int K, int outmode) {
  extern __shared__ __half hsm[];
  int tid = threadIdx.x;
  int bx = blockIdx.x, by = blockIdx.y;
  int KIT = K >> 6;

  auto load_st = [&](int it, int slot) {
    int kk = it << 6;
    __half* dst = hsm + slot*HG_STAGE;
    #pragma unroll
    for (int p = 0; p < 4; p++) {
      int u = tid + (p << 8);
      int row = u >> 3, c = u & 7;
      int soff = row*72 + c*8;
      size_t ga = (size_t)(by*128 + row)*lda + kk + c*8;
      unsigned dh = (unsigned)__cvta_generic_to_shared(dst + soff);
      CPASYNC16(dh, Ahi + ga);
      unsigned dl = (unsigned)__cvta_generic_to_shared(dst + 9216 + soff);
      CPASYNC16(dl, Alo + ga);
      const __half* sB = Bm + (size_t)(bx*128 + row)*K + kk + c*8;
      unsigned db = (unsigned)__cvta_generic_to_shared(dst + 18432 + soff);
      CPASYNC16(db, sB);
    }
    asm volatile("cp.async.commit_group;");
  };

  int wid = tid >> 5, lane = tid & 31;
  int wm = wid >> 2, wn = wid & 3;        // 2 x 4 warp grid
  int g = lane >> 2, tig = lane & 3;
  int lr = lane & 15, lc = (lane >> 4) << 3;

  float acc[4][4][4];
  #pragma unroll
  for (int mt=0; mt<4; mt++)
    #pragma unroll
    for (int nt=0; nt<4; nt++)
      #pragma unroll
      for (int r=0; r<4; r++) acc[mt][nt][r] = 0.f;

  load_st(0, 0);

  for (int it = 0; it < KIT; ++it) {
    asm volatile("cp.async.wait_group 0;");
    __syncthreads();
    if (it + 1 < KIT) load_st(it + 1, (it + 1) & 1);
    const __half* St = hsm + (it & 1)*HG_STAGE;

    #pragma unroll
    for (int ks = 0; ks < 4; ks++) {
      unsigned b[4][2];
      #pragma unroll
      for (int bt = 0; bt < 2; bt++) {
        unsigned q0,q1,q2,q3;
        unsigned bd = (unsigned)__cvta_generic_to_shared(
            St + 18432 + (wn*32 + bt*16 + lr)*72 + ks*16 + lc);
        LDSM_X4(q0,q1,q2,q3, bd);
        b[2*bt  ][0] = q0; b[2*bt  ][1] = q2;
        b[2*bt+1][0] = q1; b[2*bt+1][1] = q3;
      }
      unsigned a[4][4];
      #pragma unroll
      for (int mt = 0; mt < 4; mt++) {
        unsigned ad = (unsigned)__cvta_generic_to_shared(
            St + (wm*64 + mt*16 + lr)*72 + ks*16 + lc);
        LDSM_X4(a[mt][0], a[mt][1], a[mt][2], a[mt][3], ad);
      }
      #pragma unroll
      for (int mt = 0; mt < 4; mt++)
        #pragma unroll
        for (int nt = 0; nt < 4; nt++)
          MMAF16(acc[mt][nt][0],acc[mt][nt][1],acc[mt][nt][2],acc[mt][nt][3],
                 a[mt][0],a[mt][1],a[mt][2],a[mt][3],
                 b[nt][0],b[nt][1]);
      // lo pass reuses B fragments
      #pragma unroll
      for (int mt = 0; mt < 4; mt++) {
        unsigned ad = (unsigned)__cvta_generic_to_shared(
            St + 9216 + (wm*64 + mt*16 + lr)*72 + ks*16 + lc);
        LDSM_X4(a[mt][0], a[mt][1], a[mt][2], a[mt][3], ad);
      }
      #pragma unroll
      for (int mt = 0; mt < 4; mt++)
        #pragma unroll
        for (int nt = 0; nt < 4; nt++)
          MMAF16(acc[mt][nt][0],acc[mt][nt][1],acc[mt][nt][2],acc[mt][nt][3],
                 a[mt][0],a[mt][1],a[mt][2],a[mt][3],
                 b[nt][0],b[nt][1]);
    }
  }

  #pragma unroll
  for (int mt = 0; mt < 4; mt++) {
    #pragma unroll
    for (int nt = 0; nt < 4; nt++) {
      int row = by*128 + wm*64 + mt*16 + g;
      int col = bx*128 + wn*32 + nt*8 + 2*tig;
      if (outmode == 0) {
        float2 v0 = make_float2(acc[mt][nt][0], acc[mt][nt][1]);
        float2 v1 = make_float2(acc[mt][nt][2], acc[mt][nt][3]);
        *(float2*)&C[(size_t)row    *N + col] = v0;
        *(float2*)&C[(size_t)(row+8)*N + col] = v1;
      } else {
        size_t ldc = 2*(size_t)N;
        #pragma unroll
        for (int rr = 0; rr < 2; rr++) {
          float c0 = acc[mt][nt][2*rr], c1 = acc[mt][nt][2*rr+1];
          __half h0 = __float2half(c0), h1 = __float2half(c1);
          float l0 = c0 - __half2float(h0), l1 = c1 - __half2float(h1);
          size_t base = (size_t)(row + rr*8)*ldc + col;
          *(__half2*)&Cb[base]     = __halves2half2(h0, h1);
          *(__half2*)&Cb[base + N] = __floats2half2_rn(l0, l1);
        }
      }
    }
  }
}

// ---------------- assemble: RoPE + layout + scale ---------------------------
__global__ __launch_bounds__(128)
void assemble_kernel(const float* __restrict__ qcqr, const float* __restrict__ kcvf,
                     const float* __restrict__ krb, const float* __restrict__ rot,
                     __half* __restrict__ Qh, __half* __restrict__ Kh,
                     __half* __restrict__ Vh) {
  int h = blockIdx.x, s = blockIdx.y, b = blockIdx.z;
  int d = threadIdx.x;
  int token = b*Sn + s;
  size_t bhs = (size_t)(b*Hn + h)*Sn + s;
  const float SCALE = 0.08838834764831845f;

  Vh[bhs*128 + d] = __float2half(kcvf[(size_t)token*2304 + 768 + h*HDn + d]);

  float qv, kv;
  if (d < 64) {
    qv = qcqr[(size_t)token*1536 + h*64 + d];
    kv = kcvf[(size_t)token*2304 + h*64 + d];
  } else {
    int i = d - 64;
    const float* rrow = rot + (size_t)s*64;
    const float* qrow = qcqr + (size_t)token*1536 + 768 + h*64;
    const float* krow = krb + (size_t)token*768 + h*64;
    if (i < 32) {
      float sn = rrow[i], cs = rrow[32+i];
      qv = qrow[i]*cs - qrow[i+32]*sn;
      kv = krow[i]*cs - krow[i+32]*sn;
    } else {
      int ii = i - 32;
      float sn = rrow[ii], cs = rrow[32+ii];
      qv = qrow[ii]*sn + qrow[ii+32]*cs;
      kv = krow[ii]*sn + krow[ii+32]*cs;
    }
  }
  qv *= SCALE;
  __half qhi = __float2half(qv);
  Qh[bhs*256 + d]       = qhi;
  Qh[bhs*256 + 128 + d] = __float2half(qv - __half2float(qhi));
  Kh[bhs*128 + d] = __float2half(kv);
}

// ---------------- fp16 2-pass causal flash attention (single-sync) ----------
#define FLASH_SMEM 139264   // (2*128*136 + 2*64*136 + 2*64*136) halves * 2B

__global__ __launch_bounds__(256)
void flash_kernel(const __half* __restrict__ Qg,
                  const __half* __restrict__ Kg,
                  const __half* __restrict__ Vg,
                  __half* __restrict__ At) {
  extern __shared__ __half fsm[];
  __half* Qs = fsm;              // [2 plane][128][136]
  __half* Ks = fsm + 34816;      // [2 buf][64][136]
  __half* Vs = fsm + 52224;      // [2 buf][64][136]

  int qi = 15 - (int)blockIdx.x;
  int h = blockIdx.y, b = blockIdx.z;
  int bh = b*Hn + h;
  int qbase = qi*128;
  const __half* Qb = Qg + ((size_t)bh*Sn + qbase)*256;
  const __half* Kb = Kg + (size_t)bh*Sn*128;
  const __half* Vb = Vg + (size_t)bh*Sn*128;

  int tid = threadIdx.x;
  int wid = tid>>5, lane = tid&31, g = lane>>2, tig = lane&3;
  int lr = lane & 15, lc = (lane >> 4) << 3;
  int jmax = 2*qi + 2;
  int r0 = wid*16;

  // Q load (split: plane = c>>4) — joins group 0 with first K/V tiles
  #pragma unroll
  for (int p=0;p<16;p++){
    int lin = tid + p*256;
    int row = lin>>5, c = lin&31;
    const __half* src = Qb + (size_t)row*256 + c*8;
    unsigned d = (unsigned)__cvta_generic_to_shared(Qs + (c>>4)*17408 + row*136 + (c&15)*8);
    CPASYNC16(d, src);
  }
  auto load_kv = [&](int jt, int buf){
    #pragma unroll
    for (int p=0;p<4;p++){
      int lin = tid + p*256;
      int row = lin>>4, c = lin&15;
      size_t s_off = (size_t)(jt*64 + row)*128 + c*8;
      int doff = buf*8704 + row*136 + c*8;
      unsigned dk = (unsigned)__cvta_generic_to_shared(Ks + doff);
      CPASYNC16(dk, Kb + s_off);
      unsigned dv = (unsigned)__cvta_generic_to_shared(Vs + doff);
      CPASYNC16(dv, Vb + s_off);
    }
    asm volatile("cp.async.commit_group;");
  };
  load_kv(0, 0);

  float o[16][4];
  #pragma unroll
  for (int nt=0;nt<16;nt++)
    #pragma unroll
    for (int r=0;r<4;r++) o[nt][r] = 0.f;
  float m0=-1e30f, m1=-1e30f, l0=0.f, l1=0.f;

  for (int jt = 0; jt < jmax; jt++) {
    int buf = jt & 1;
    asm volatile("cp.async.wait_group 0;");
    __syncthreads();
    if (jt + 1 < jmax) load_kv(jt+1, buf^1);

    // ---- S = Q @ K^T (2-pass via ldmatrix fragments) ----
    const __half* Kbuf = Ks + buf*8704;
    float acc[8][4];
    #pragma unroll
    for (int t=0;t<8;t++)
      #pragma unroll
      for (int r=0;r<4;r++) acc[t][r] = 0.f;

    #pragma unroll
    for (int ks=0; ks<8; ks++){
      unsigned ah[4], al[4];
      {
        unsigned qd = (unsigned)__cvta_generic_to_shared(
            Qs + (r0 + lr)*136 + ks*16 + lc);
        LDSM_X4(ah[0],ah[1],ah[2],ah[3], qd);
        LDSM_X4(al[0],al[1],al[2],al[3], qd + 34816);  // +plane (17408 halves)
      }
      unsigned bk[8][2];
      #pragma unroll
      for (int t16=0; t16<4; t16++){
        unsigned q0,q1,q2,q3;
        unsigned kd = (unsigned)__cvta_generic_to_shared(
            Kbuf + (t16*16 + lr)*136 + ks*16 + lc);
        LDSM_X4(q0,q1,q2,q3, kd);
        bk[2*t16  ][0] = q0; bk[2*t16  ][1] = q2;
        bk[2*t16+1][0] = q1; bk[2*t16+1][1] = q3;
      }
      #pragma unroll
      for (int t=0;t<8;t++){
        MMAF16(acc[t][0],acc[t][1],acc[t][2],acc[t][3],
               ah[0],ah[1],ah[2],ah[3], bk[t][0],bk[t][1]);
        MMAF16(acc[t][0],acc[t][1],acc[t][2],acc[t][3],
               al[0],al[1],al[2],al[3], bk[t][0],bk[t][1]);
      }
    }

    // ---- causal mask (near-diagonal tiles only) ----
    if (jt >= jmax-2) {
      int rg0 = qbase + r0 + g, rg1 = rg0 + 8;
      #pragma unroll
      for (int t=0;t<8;t++){
        int c0 = jt*64 + t*8 + 2*tig;
        if (c0   > rg0) acc[t][0] = -1e30f;
        if (c0+1 > rg0) acc[t][1] = -1e30f;
        if (c0   > rg1) acc[t][2] = -1e30f;
        if (c0+1 > rg1) acc[t][3] = -1e30f;
      }
    }

    // ---- online softmax (warp-local quad shuffles) ----
    float mx0=-1e30f, mx1=-1e30f;
    #pragma unroll
    for (int t=0;t<8;t++){
      mx0 = fmaxf(mx0, fmaxf(acc[t][0],acc[t][1]));
      mx1 = fmaxf(mx1, fmaxf(acc[t][2],acc[t][3]));
    }
    mx0 = fmaxf(mx0, __shfl_xor_sync(0xffffffffu, mx0, 1));
    mx0 = fmaxf(mx0, __shfl_xor_sync(0xffffffffu, mx0, 2));
    mx1 = fmaxf(mx1, __shfl_xor_sync(0xffffffffu, mx1, 1));
    mx1 = fmaxf(mx1, __shfl_xor_sync(0xffffffffu, mx1, 2));
    float nm0 = fmaxf(m0, mx0), nm1 = fmaxf(m1, mx1);
    float cf0 = __expf(m0 - nm0), cf1 = __expf(m1 - nm1);
    m0 = nm0; m1 = nm1;
    float s0 = 0.f, s1 = 0.f;
    #pragma unroll
    for (int t=0;t<8;t++){
      acc[t][0] = __expf(acc[t][0]-nm0);
      acc[t][1] = __expf(acc[t][1]-nm0);
      acc[t][2] = __expf(acc[t][2]-nm1);
      acc[t][3] = __expf(acc[t][3]-nm1);
      s0 += acc[t][0]+acc[t][1];
      s1 += acc[t][2]+acc[t][3];
    }
    s0 += __shfl_xor_sync(0xffffffffu, s0, 1);
    s0 += __shfl_xor_sync(0xffffffffu, s0, 2);
    s1 += __shfl_xor_sync(0xffffffffu, s1, 1);
    s1 += __shfl_xor_sync(0xffffffffu, s1, 2);
    l0 = l0*cf0 + s0;
    l1 = l1*cf1 + s1;
    #pragma unroll
    for (int nt=0;nt<16;nt++){
      o[nt][0] *= cf0; o[nt][1] *= cf0;
      o[nt][2] *= cf1; o[nt][3] *= cf1;
    }

    // ---- O += P @ V (2-pass: Phi.V + Plo.V) ----
    const __half* Vbuf = Vs + buf*8704;
    int vrow = ((lane>>3)&1)*8 + (lane&7);
    int vcol = (lane>>4)*8;
    #pragma unroll
    for (int u=0;u<4;u++){
      unsigned ph[4], pl[4];
      ph[0] = pack2h(acc[2*u  ][0], acc[2*u  ][1]);
      ph[1] = pack2h(acc[2*u  ][2], acc[2*u  ][3]);
      ph[2] = pack2h(acc[2*u+1][0], acc[2*u+1][1]);
      ph[3] = pack2h(acc[2*u+1][2], acc[2*u+1][3]);
      pl[0] = pack2h(hres(acc[2*u  ][0]), hres(acc[2*u  ][1]));
      pl[1] = pack2h(hres(acc[2*u  ][2]), hres(acc[2*u  ][3]));
      pl[2] = pack2h(hres(acc[2*u+1][0]), hres(acc[2*u+1][1]));
      pl[3] = pack2h(hres(acc[2*u+1][2]), hres(acc[2*u+1][3]));
      unsigned base = (unsigned)__cvta_generic_to_shared(
          Vbuf + (u*16 + vrow)*136 + vcol);
      #pragma unroll
      for (int dt=0;dt<8;dt++){
        unsigned v0,v1,v2,v3;
        LDSM_X4T(v0,v1,v2,v3, base + dt*32);
        MMAF16(o[dt*2  ][0],o[dt*2  ][1],o[dt*2  ][2],o[dt*2  ][3],
               ph[0],ph[1],ph[2],ph[3], v0,v1);
        MMAF16(o[dt*2  ][0],o[dt*2  ][1],o[dt*2  ][2],o[dt*2  ][3],
               pl[0],pl[1],pl[2],pl[3], v0,v1);
        MMAF16(o[dt*2+1][0],o[dt*2+1][1],o[dt*2+1][2],o[dt*2+1][3],
               ph[0],ph[1],ph[2],ph[3], v2,v3);
        MMAF16(o[dt*2+1][0],o[dt*2+1][1],o[dt*2+1][2],o[dt*2+1][3],
               pl[0],pl[1],pl[2],pl[3], v2,v3);
      }
    }
  }

  // ---- epilogue: normalize, split-fp16 token-major output ----
  float i0 = 1.f/l0, i1 = 1.f/l1;
  int tok0 = b*Sn + qbase + r0 + g;
  __half* o0 = At + (size_t)tok0*3072 + h*128;
  __half* o1 = At + (size_t)(tok0+8)*3072 + h*128;
  #pragma unroll
  for (int nt=0;nt<16;nt++){
    int col = nt*8 + 2*tig;
    float a0 = o[nt][0]*i0, a1 = o[nt][1]*i0;
    float a2 = o[nt][2]*i1, a3 = o[nt][3]*i1;
    __half2 h0 = __floats2half2_rn(a0, a1);
    *(__half2*)(o0 + col) = h0;
    *(__half2*)(o0 + 1536 + col) = __floats2half2_rn(
        a0 - __half2float(__low2half(h0)), a1 - __half2float(__high2half(h0)));
    __half2 h1 = __floats2half2_rn(a2, a3);
    *(__half2*)(o1 + col) = h1;
    *(__half2*)(o1 + 1536 + col) = __floats2half2_rn(
        a2 - __half2float(__low2half(h1)), a3 - __half2float(__high2half(h1)));
  }
}

// ---------------- launch -----------------------------------------------------
extern "C" void kernel_launch(void* const* d_in, const int* in_sizes, int n_in,
                              void* d_out, int out_size) {
  (void)in_sizes; (void)n_in; (void)out_size;
  const float* hs   = (const float*)d_in[0];
  const float* rot  = (const float*)d_in[1];
  const float* Wkvd = (const float*)d_in[2];
  const float* Wqd  = (const float*)d_in[3];
  const float* Wku  = (const float*)d_in[4];
  const float* Wqu  = (const float*)d_in[5];
  const float* Wvu  = (const float*)d_in[6];
  const float* Wrk  = (const float*)d_in[7];
  const float* Wrq  = (const float*)d_in[8];
  const float* Wo   = (const float*)d_in[9];
  float* out = (float*)d_out;

  __half *hsA2,*wqkv,*wkv,*wq,*wrk,*wob,*dA2,*atA2,*qb,*kb,*vb;
  float *kcvf,*qcqr,*krb;
  cudaGetSymbolAddress((void**)&hsA2, g_hsA2);
  cudaGetSymbolAddress((void**)&wqkv, g_Wqkv);
  cudaGetSymbolAddress((void**)&wkv , g_Wkv);
  cudaGetSymbolAddress((void**)&wq  , g_Wq);
  cudaGetSymbolAddress((void**)&wrk , g_Wrk);
  cudaGetSymbolAddress((void**)&wob , g_Wob);
  cudaGetSymbolAddress((void**)&dA2 , g_dA2);
  cudaGetSymbolAddress((void**)&kcvf, g_kcvf);
  cudaGetSymbolAddress((void**)&qcqr, g_qcqr);
  cudaGetSymbolAddress((void**)&krb , g_krb);
  cudaGetSymbolAddress((void**)&qb  , g_qb);
  cudaGetSymbolAddress((void**)&kb  , g_kb);
  cudaGetSymbolAddress((void**)&vb  , g_vb);
  cudaGetSymbolAddress((void**)&atA2, g_atA2);

  // --- input conversions ---
  convA_kernel<<<(TOKn*1536)/256, 256>>>(hs, hsA2, 1536);
  {
    ConvJobs J;
    const float* Ws[8] = {Wkvd, Wqd, Wku, Wvu, Wqu, Wrq, Wrk, Wo};
    __half* Bs[8] = {wqkv, wqkv + (size_t)192*1536, wkv,
                     wkv + (size_t)768*192, wq, wq + (size_t)768*192,
                     wrk, wob};
    int Ks[8]  = {1536,1536,192,192,192,192,1536,1536};
    int Nsz[8] = {192,192,768,1536,768,768,768,1536};
    int acc = 0;
    for (int j = 0; j < 8; j++) {
      J.W[j] = Ws[j]; J.Bt[j] = Bs[j];
      J.K[j] = Ks[j]; J.N[j] = Nsz[j];
      J.bstart[j] = acc;
      acc += (Nsz[j]/32)*(Ks[j]/32);
    }
    J.bstart[8] = acc;
    convW_kernel<<<acc, dim3(32,8)>>>(J);
  }

  // --- projections (fp16 fused 2-pass tensor cores) ---
  cudaFuncSetAttribute(hgemm_kernel,
      cudaFuncAttributeMaxDynamicSharedMemorySize, HG_SMEM);
  hgemm_kernel<<<dim3( 3,32),256,HG_SMEM>>>(hsA2, hsA2+1536, 3072, wqkv,
                                    nullptr, dA2, 384, 1536, 1);
  hgemm_kernel<<<dim3(18,32),256,HG_SMEM>>>(dA2, dA2+384, 768, wkv,
                                    kcvf, nullptr, 2304, 192, 0);
  hgemm_kernel<<<dim3(12,32),256,HG_SMEM>>>(dA2+192, dA2+576, 768, wq,
                                    qcqr, nullptr, 1536, 192, 0);
  hgemm_kernel<<<dim3( 6,32),256,HG_SMEM>>>(hsA2, hsA2+1536, 3072, wrk,
                                    krb, nullptr, 768, 1536, 0);

  // rope + layout
  assemble_kernel<<<dim3(Hn, Sn, Bn),128>>>(qcqr, kcvf, krb, rot, qb, kb, vb);

  // flash attention
  cudaFuncSetAttribute(flash_kernel, cudaFuncAttributeMaxDynamicSharedMemorySize,
                       FLASH_SMEM);
  flash_kernel<<<dim3(16, Hn, Bn), 256, FLASH_SMEM>>>(qb, kb, vb, atA2);

  // output projection
  hgemm_kernel<<<dim3(12,32),256,HG_SMEM>>>(atA2, atA2+1536, 3072, wob,
                                    out, nullptr, 1536, 1536, 0);
}

// round 9
// speedup vs baseline: 5.2696x; 1.1258x over previous
#include <cuda_runtime.h>
#include <cuda_fp16.h>
#include <cstdint>
#include <stdint.h>
#include <math.h>

#define Bn   2
#define Sn   2048
#define HIDn 1536
#define Hn   12
#define HDn  128
#define TOKn (Bn*Sn)   // 4096

// ---------------- scratch (device globals; no allocations allowed) ----------
__device__ __half g_hsA2[(size_t)TOKn*3072];     // hidden split fp16 [row][hi1536|lo1536]
__device__ __half g_Wqkv[(size_t)384*1536];      // [n][k] single fp16
__device__ __half g_Wkv [(size_t)2304*192];
__device__ __half g_Wq  [(size_t)1536*192];
__device__ __half g_Wrk [(size_t)768*1536];
__device__ __half g_Wob [(size_t)1536*1536];
__device__ __half g_dA2 [(size_t)TOKn*768];      // [tok][hi:kvd|qd, lo at +384]
__device__ float g_kcvf[(size_t)TOKn*2304];
__device__ float g_qcqr[(size_t)TOKn*1536];
__device__ float g_krb [(size_t)TOKn*768];
__device__ __half g_qb[(size_t)Bn*Hn*Sn*256];    // Q split [s][hi128|lo128]
__device__ __half g_kb[(size_t)Bn*Hn*Sn*128];    // K single
__device__ __half g_vb[(size_t)Bn*Hn*Sn*128];    // V single
__device__ __half g_at1[(size_t)TOKn*1536];      // attn out single fp16

// ---------------- helpers ----------------------------------------------------
__device__ __forceinline__ unsigned pack2h(float a, float b) {
  __half2 t = __floats2half2_rn(a, b);
  return *(unsigned*)&t;
}
__device__ __forceinline__ float hres(float x) {
  return x - __half2float(__float2half(x));
}

#define MMAF16(d0,d1,d2,d3,a0,a1,a2,a3,b0,b1)                              \
  asm volatile("mma.sync.aligned.m16n8k16.row.col.f32.f16.f16.f32 "         \
    "{%0,%1,%2,%3},{%4,%5,%6,%7},{%8,%9},{%0,%1,%2,%3};"                    \
    : "+f"(d0),"+f"(d1),"+f"(d2),"+f"(d3)                                    \
    : "r"(a0),"r"(a1),"r"(a2),"r"(a3),"r"(b0),"r"(b1))
#define LDSM_X4(r0,r1,r2,r3,addr)                                           \
  asm volatile("ldmatrix.sync.aligned.m8n8.x4.shared.b16 "                  \
    "{%0,%1,%2,%3},[%4];"                                                   \
    : "=r"(r0),"=r"(r1),"=r"(r2),"=r"(r3) : "r"(addr))
#define LDSM_X4T(r0,r1,r2,r3,addr)                                          \
  asm volatile("ldmatrix.sync.aligned.m8n8.x4.trans.shared.b16 "            \
    "{%0,%1,%2,%3},[%4];"                                                   \
    : "=r"(r0),"=r"(r1),"=r"(r2),"=r"(r3) : "r"(addr))
#define CPASYNC16(dst, src)                                                 \
  asm volatile("cp.async.cg.shared.global [%0],[%1],16;" :: "r"(dst), "l"(src))

// ---------------- conversion kernels ----------------------------------------
__global__ __launch_bounds__(256)
void convA_kernel(const float* __restrict__ X, __half* __restrict__ Y, int K) {
  size_t i = (size_t)blockIdx.x*256 + threadIdx.x;
  float x = X[i];
  size_t row = i / K, col = i % K;
  __half hi = __float2half(x);
  float lo = x - __half2float(hi);
  Y[row*(2*(size_t)K) + col]     = hi;
  Y[row*(2*(size_t)K) + K + col] = __float2half(lo);
}

struct ConvJobs {
  const float* W[8];
  __half* Bt[8];
  int K[8], N[8];
  int bstart[9];
};
__global__ __launch_bounds__(256)
void convW_kernel(ConvJobs J) {
  __shared__ float t[32][33];
  int bx = blockIdx.x;
  int j = 0;
  while (bx >= J.bstart[j+1]) j++;
  int lb = bx - J.bstart[j];
  int nbn = J.N[j] >> 5;
  int n0 = (lb % nbn) << 5, k0 = (lb / nbn) << 5;
  const float* W = J.W[j];
  __half* Bt = J.Bt[j];
  int K = J.K[j], N = J.N[j];
  #pragma unroll
  for (int i = threadIdx.y; i < 32; i += 8)
    t[i][threadIdx.x] = W[(size_t)(k0+i)*N + n0 + threadIdx.x];
  __syncthreads();
  #pragma unroll
  for (int i = threadIdx.y; i < 32; i += 8) {
    int n = n0 + i, k = k0 + threadIdx.x;
    Bt[(size_t)n*K + k] = __float2half(t[threadIdx.x][i]);
  }
}

// ---------------- fp16 tensor-core GEMM (batched jobs, 3-stage, BK=32) ------
// C[M][N] = (Ahi [+Alo]) @ B16^T.  BM=128, BN in {64,128}, 256 threads.
// PASSES=2: fused hi/lo per K-chunk (B frags reused). PASSES=1: single.
struct GJob {
  const __half *Ahi, *Alo, *Bm;
  float* C; __half* Cb;
  int lda, N, K, outmode, nbx;
};
struct GJobs { GJob j[3]; int bstart[4]; };

template<int BN, int PASSES, int NJ>
__global__ __launch_bounds__(256)
void hgemm_kernel(GJobs JB) {
  constexpr int ASZ   = 128*40;                 // halves per A plane
  constexpr int BOFF  = ASZ*PASSES;             // B offset in stage
  constexpr int STAGE = ASZ*PASSES + BN*40;     // halves per stage
  constexpr int WN = BN/32, WM = 8/WN, MT = 128/(WM*16);

  extern __shared__ __half hsm[];
  int tid = threadIdx.x;
  int bid = blockIdx.x;
  int ji = 0;
  #pragma unroll
  for (int t = 1; t < NJ; t++) if (bid >= JB.bstart[t]) ji = t;
  GJob jb = JB.j[ji];
  int lb = bid - JB.bstart[ji];
  int bx = lb % jb.nbx, by = lb / jb.nbx;
  const __half* Ahi = jb.Ahi;
  const __half* Alo = jb.Alo;
  const __half* Bm  = jb.Bm;
  int lda = jb.lda, N = jb.N, K = jb.K;
  int KIT = K >> 5;

  auto load_st = [&](int it, int slot) {
    int kk = it << 5;
    __half* dst = hsm + slot*STAGE;
    #pragma unroll
    for (int p = 0; p < 2; p++) {
      int u = tid + (p << 8);
      int row = u >> 2, c = u & 3;
      int soff = row*40 + c*8;
      size_t ga = (size_t)(by*128 + row)*lda + kk + c*8;
      unsigned dh = (unsigned)__cvta_generic_to_shared(dst + soff);
      CPASYNC16(dh, Ahi + ga);
      if (PASSES == 2) {
        unsigned dl = (unsigned)__cvta_generic_to_shared(dst + ASZ + soff);
        CPASYNC16(dl, Alo + ga);
      }
    }
    #pragma unroll
    for (int p = 0; p < BN/64; p++) {
      int u = tid + (p << 8);
      int row = u >> 2, c = u & 3;
      const __half* sB = Bm + (size_t)(bx*BN + row)*K + kk + c*8;
      unsigned db = (unsigned)__cvta_generic_to_shared(dst + BOFF + row*40 + c*8);
      CPASYNC16(db, sB);
    }
    asm volatile("cp.async.commit_group;");
  };

  int wid = tid >> 5, lane = tid & 31;
  int wm = wid / WN, wn = wid % WN;
  int g = lane >> 2, tig = lane & 3;
  int lr = lane & 15, lc = (lane >> 4) << 3;

  float acc[MT][4][4];
  #pragma unroll
  for (int mt=0; mt<MT; mt++)
    #pragma unroll
    for (int nt=0; nt<4; nt++)
      #pragma unroll
      for (int r=0; r<4; r++) acc[mt][nt][r] = 0.f;

  load_st(0, 0);
  load_st(1, 1);

  for (int it = 0; it < KIT; ++it) {
    if (it + 1 < KIT) asm volatile("cp.async.wait_group 1;");
    else              asm volatile("cp.async.wait_group 0;");
    __syncthreads();
    if (it + 2 < KIT) load_st(it + 2, (it + 2) % 3);
    const __half* St = hsm + (it % 3)*STAGE;

    #pragma unroll
    for (int ks = 0; ks < 2; ks++) {
      unsigned b[4][2];
      #pragma unroll
      for (int bt = 0; bt < 2; bt++) {
        unsigned q0,q1,q2,q3;
        unsigned bd = (unsigned)__cvta_generic_to_shared(
            St + BOFF + (wn*32 + bt*16 + lr)*40 + ks*16 + lc);
        LDSM_X4(q0,q1,q2,q3, bd);
        b[2*bt  ][0] = q0; b[2*bt  ][1] = q2;
        b[2*bt+1][0] = q1; b[2*bt+1][1] = q3;
      }
      unsigned a[MT][4];
      #pragma unroll
      for (int mt = 0; mt < MT; mt++) {
        unsigned ad = (unsigned)__cvta_generic_to_shared(
            St + (wm*(MT*16) + mt*16 + lr)*40 + ks*16 + lc);
        LDSM_X4(a[mt][0], a[mt][1], a[mt][2], a[mt][3], ad);
      }
      #pragma unroll
      for (int mt = 0; mt < MT; mt++)
        #pragma unroll
        for (int nt = 0; nt < 4; nt++)
          MMAF16(acc[mt][nt][0],acc[mt][nt][1],acc[mt][nt][2],acc[mt][nt][3],
                 a[mt][0],a[mt][1],a[mt][2],a[mt][3],
                 b[nt][0],b[nt][1]);
      if (PASSES == 2) {
        #pragma unroll
        for (int mt = 0; mt < MT; mt++) {
          unsigned ad = (unsigned)__cvta_generic_to_shared(
              St + ASZ + (wm*(MT*16) + mt*16 + lr)*40 + ks*16 + lc);
          LDSM_X4(a[mt][0], a[mt][1], a[mt][2], a[mt][3], ad);
        }
        #pragma unroll
        for (int mt = 0; mt < MT; mt++)
          #pragma unroll
          for (int nt = 0; nt < 4; nt++)
            MMAF16(acc[mt][nt][0],acc[mt][nt][1],acc[mt][nt][2],acc[mt][nt][3],
                   a[mt][0],a[mt][1],a[mt][2],a[mt][3],
                   b[nt][0],b[nt][1]);
      }
    }
  }

  #pragma unroll
  for (int mt = 0; mt < MT; mt++) {
    #pragma unroll
    for (int nt = 0; nt < 4; nt++) {
      int row = by*128 + wm*(MT*16) + mt*16 + g;
      int col = bx*BN + wn*32 + nt*8 + 2*tig;
      if (jb.outmode == 0) {
        float2 v0 = make_float2(acc[mt][nt][0], acc[mt][nt][1]);
        float2 v1 = make_float2(acc[mt][nt][2], acc[mt][nt][3]);
        *(float2*)&jb.C[(size_t)row    *N + col] = v0;
        *(float2*)&jb.C[(size_t)(row+8)*N + col] = v1;
      } else {
        size_t ldc = 2*(size_t)N;
        #pragma unroll
        for (int rr = 0; rr < 2; rr++) {
          float c0 = acc[mt][nt][2*rr], c1 = acc[mt][nt][2*rr+1];
          __half h0 = __float2half(c0), h1 = __float2half(c1);
          float l0 = c0 - __half2float(h0), l1 = c1 - __half2float(h1);
          size_t base = (size_t)(row + rr*8)*ldc + col;
          *(__half2*)&jb.Cb[base]     = __halves2half2(h0, h1);
          *(__half2*)&jb.Cb[base + N] = __floats2half2_rn(l0, l1);
        }
      }
    }
  }
}

// ---------------- assemble: RoPE + layout + scale ---------------------------
__global__ __launch_bounds__(128)
void assemble_kernel(const float* __restrict__ qcqr, const float* __restrict__ kcvf,
                     const float* __restrict__ krb, const float* __restrict__ rot,
                     __half* __restrict__ Qh, __half* __restrict__ Kh,
                     __half* __restrict__ Vh) {
  int h = blockIdx.x, s = blockIdx.y, b = blockIdx.z;
  int d = threadIdx.x;
  int token = b*Sn + s;
  size_t bhs = (size_t)(b*Hn + h)*Sn + s;
  const float SCALE = 0.08838834764831845f;

  Vh[bhs*128 + d] = __float2half(kcvf[(size_t)token*2304 + 768 + h*HDn + d]);

  float qv, kv;
  if (d < 64) {
    qv = qcqr[(size_t)token*1536 + h*64 + d];
    kv = kcvf[(size_t)token*2304 + h*64 + d];
  } else {
    int i = d - 64;
    const float* rrow = rot + (size_t)s*64;
    const float* qrow = qcqr + (size_t)token*1536 + 768 + h*64;
    const float* krow = krb + (size_t)token*768 + h*64;
    if (i < 32) {
      float sn = rrow[i], cs = rrow[32+i];
      qv = qrow[i]*cs - qrow[i+32]*sn;
      kv = krow[i]*cs - krow[i+32]*sn;
    } else {
      int ii = i - 32;
      float sn = rrow[ii], cs = rrow[32+ii];
      qv = qrow[ii]*sn + qrow[ii+32]*cs;
      kv = krow[ii]*sn + krow[ii+32]*cs;
    }
  }
  qv *= SCALE;
  __half qhi = __float2half(qv);
  Qh[bhs*256 + d]       = qhi;
  Qh[bhs*256 + 128 + d] = __float2half(qv - __half2float(qhi));
  Kh[bhs*128 + d] = __float2half(kv);
}

// ---------------- fp16 2-pass causal flash attention (single-sync) ----------
#define FLASH_SMEM 139264   // (2*128*136 + 2*64*136 + 2*64*136) halves * 2B

__global__ __launch_bounds__(256)
void flash_kernel(const __half* __restrict__ Qg,
                  const __half* __restrict__ Kg,
                  const __half* __restrict__ Vg,
                  __half* __restrict__ At) {
  extern __shared__ __half fsm[];
  __half* Qs = fsm;              // [2 plane][128][136]
  __half* Ks = fsm + 34816;      // [2 buf][64][136]
  __half* Vs = fsm + 52224;      // [2 buf][64][136]

  int qi = 15 - (int)blockIdx.x;
  int h = blockIdx.y, b = blockIdx.z;
  int bh = b*Hn + h;
  int qbase = qi*128;
  const __half* Qb = Qg + ((size_t)bh*Sn + qbase)*256;
  const __half* Kb = Kg + (size_t)bh*Sn*128;
  const __half* Vb = Vg + (size_t)bh*Sn*128;

  int tid = threadIdx.x;
  int wid = tid>>5, lane = tid&31, g = lane>>2, tig = lane&3;
  int lr = lane & 15, lc = (lane >> 4) << 3;
  int jmax = 2*qi + 2;
  int r0 = wid*16;

  #pragma unroll
  for (int p=0;p<16;p++){
    int lin = tid + p*256;
    int row = lin>>5, c = lin&31;
    const __half* src = Qb + (size_t)row*256 + c*8;
    unsigned d = (unsigned)__cvta_generic_to_shared(Qs + (c>>4)*17408 + row*136 + (c&15)*8);
    CPASYNC16(d, src);
  }
  auto load_kv = [&](int jt, int buf){
    #pragma unroll
    for (int p=0;p<4;p++){
      int lin = tid + p*256;
      int row = lin>>4, c = lin&15;
      size_t s_off = (size_t)(jt*64 + row)*128 + c*8;
      int doff = buf*8704 + row*136 + c*8;
      unsigned dk = (unsigned)__cvta_generic_to_shared(Ks + doff);
      CPASYNC16(dk, Kb + s_off);
      unsigned dv = (unsigned)__cvta_generic_to_shared(Vs + doff);
      CPASYNC16(dv, Vb + s_off);
    }
    asm volatile("cp.async.commit_group;");
  };
  load_kv(0, 0);

  float o[16][4];
  #pragma unroll
  for (int nt=0;nt<16;nt++)
    #pragma unroll
    for (int r=0;r<4;r++) o[nt][r] = 0.f;
  float m0=-1e30f, m1=-1e30f, l0=0.f, l1=0.f;

  for (int jt = 0; jt < jmax; jt++) {
    int buf = jt & 1;
    asm volatile("cp.async.wait_group 0;");
    __syncthreads();
    if (jt + 1 < jmax) load_kv(jt+1, buf^1);

    const __half* Kbuf = Ks + buf*8704;
    float acc[8][4];
    #pragma unroll
    for (int t=0;t<8;t++)
      #pragma unroll
      for (int r=0;r<4;r++) acc[t][r] = 0.f;

    #pragma unroll
    for (int ks=0; ks<8; ks++){
      unsigned ah[4], al[4];
      {
        unsigned qd = (unsigned)__cvta_generic_to_shared(
            Qs + (r0 + lr)*136 + ks*16 + lc);
        LDSM_X4(ah[0],ah[1],ah[2],ah[3], qd);
        LDSM_X4(al[0],al[1],al[2],al[3], qd + 34816);
      }
      unsigned bk[8][2];
      #pragma unroll
      for (int t16=0; t16<4; t16++){
        unsigned q0,q1,q2,q3;
        unsigned kd = (unsigned)__cvta_generic_to_shared(
            Kbuf + (t16*16 + lr)*136 + ks*16 + lc);
        LDSM_X4(q0,q1,q2,q3, kd);
        bk[2*t16  ][0] = q0; bk[2*t16  ][1] = q2;
        bk[2*t16+1][0] = q1; bk[2*t16+1][1] = q3;
      }
      #pragma unroll
      for (int t=0;t<8;t++){
        MMAF16(acc[t][0],acc[t][1],acc[t][2],acc[t][3],
               ah[0],ah[1],ah[2],ah[3], bk[t][0],bk[t][1]);
        MMAF16(acc[t][0],acc[t][1],acc[t][2],acc[t][3],
               al[0],al[1],al[2],al[3], bk[t][0],bk[t][1]);
      }
    }

    if (jt >= jmax-2) {
      int rg0 = qbase + r0 + g, rg1 = rg0 + 8;
      #pragma unroll
      for (int t=0;t<8;t++){
        int c0 = jt*64 + t*8 + 2*tig;
        if (c0   > rg0) acc[t][0] = -1e30f;
        if (c0+1 > rg0) acc[t][1] = -1e30f;
        if (c0   > rg1) acc[t][2] = -1e30f;
        if (c0+1 > rg1) acc[t][3] = -1e30f;
      }
    }

    float mx0=-1e30f, mx1=-1e30f;
    #pragma unroll
    for (int t=0;t<8;t++){
      mx0 = fmaxf(mx0, fmaxf(acc[t][0],acc[t][1]));
      mx1 = fmaxf(mx1, fmaxf(acc[t][2],acc[t][3]));
    }
    mx0 = fmaxf(mx0, __shfl_xor_sync(0xffffffffu, mx0, 1));
    mx0 = fmaxf(mx0, __shfl_xor_sync(0xffffffffu, mx0, 2));
    mx1 = fmaxf(mx1, __shfl_xor_sync(0xffffffffu, mx1, 1));
    mx1 = fmaxf(mx1, __shfl_xor_sync(0xffffffffu, mx1, 2));
    float nm0 = fmaxf(m0, mx0), nm1 = fmaxf(m1, mx1);
    float cf0 = __expf(m0 - nm0), cf1 = __expf(m1 - nm1);
    m0 = nm0; m1 = nm1;
    float s0 = 0.f, s1 = 0.f;
    #pragma unroll
    for (int t=0;t<8;t++){
      acc[t][0] = __expf(acc[t][0]-nm0);
      acc[t][1] = __expf(acc[t][1]-nm0);
      acc[t][2] = __expf(acc[t][2]-nm1);
      acc[t][3] = __expf(acc[t][3]-nm1);
      s0 += acc[t][0]+acc[t][1];
      s1 += acc[t][2]+acc[t][3];
    }
    s0 += __shfl_xor_sync(0xffffffffu, s0, 1);
    s0 += __shfl_xor_sync(0xffffffffu, s0, 2);
    s1 += __shfl_xor_sync(0xffffffffu, s1, 1);
    s1 += __shfl_xor_sync(0xffffffffu, s1, 2);
    l0 = l0*cf0 + s0;
    l1 = l1*cf1 + s1;
    #pragma unroll
    for (int nt=0;nt<16;nt++){
      o[nt][0] *= cf0; o[nt][1] *= cf0;
      o[nt][2] *= cf1; o[nt][3] *= cf1;
    }

    const __half* Vbuf = Vs + buf*8704;
    int vrow = ((lane>>3)&1)*8 + (lane&7);
    int vcol = (lane>>4)*8;
    #pragma unroll
    for (int u=0;u<4;u++){
      unsigned ph[4], pl[4];
      ph[0] = pack2h(acc[2*u  ][0], acc[2*u  ][1]);
      ph[1] = pack2h(acc[2*u  ][2], acc[2*u  ][3]);
      ph[2] = pack2h(acc[2*u+1][0], acc[2*u+1][1]);
      ph[3] = pack2h(acc[2*u+1][2], acc[2*u+1][3]);
      pl[0] = pack2h(hres(acc[2*u  ][0]), hres(acc[2*u  ][1]));
      pl[1] = pack2h(hres(acc[2*u  ][2]), hres(acc[2*u  ][3]));
      pl[2] = pack2h(hres(acc[2*u+1][0]), hres(acc[2*u+1][1]));
      pl[3] = pack2h(hres(acc[2*u+1][2]), hres(acc[2*u+1][3]));
      unsigned base = (unsigned)__cvta_generic_to_shared(
          Vbuf + (u*16 + vrow)*136 + vcol);
      #pragma unroll
      for (int dt=0;dt<8;dt++){
        unsigned v0,v1,v2,v3;
        LDSM_X4T(v0,v1,v2,v3, base + dt*32);
        MMAF16(o[dt*2  ][0],o[dt*2  ][1],o[dt*2  ][2],o[dt*2  ][3],
               ph[0],ph[1],ph[2],ph[3], v0,v1);
        MMAF16(o[dt*2  ][0],o[dt*2  ][1],o[dt*2  ][2],o[dt*2  ][3],
               pl[0],pl[1],pl[2],pl[3], v0,v1);
        MMAF16(o[dt*2+1][0],o[dt*2+1][1],o[dt*2+1][2],o[dt*2+1][3],
               ph[0],ph[1],ph[2],ph[3], v2,v3);
        MMAF16(o[dt*2+1][0],o[dt*2+1][1],o[dt*2+1][2],o[dt*2+1][3],
               pl[0],pl[1],pl[2],pl[3], v2,v3);
      }
    }
  }

  // ---- epilogue: normalize, single fp16 token-major output ----
  float i0 = 1.f/l0, i1 = 1.f/l1;
  int tok0 = b*Sn + qbase + r0 + g;
  __half* o0 = At + (size_t)tok0*1536 + h*128;
  __half* o1 = At + (size_t)(tok0+8)*1536 + h*128;
  #pragma unroll
  for (int nt=0;nt<16;nt++){
    int col = nt*8 + 2*tig;
    *(__half2*)(o0 + col) = __floats2half2_rn(o[nt][0]*i0, o[nt][1]*i0);
    *(__half2*)(o1 + col) = __floats2half2_rn(o[nt][2]*i1, o[nt][3]*i1);
  }
}

// ---------------- launch -----------------------------------------------------
extern "C" void kernel_launch(void* const* d_in, const int* in_sizes, int n_in,
                              void* d_out, int out_size) {
  (void)in_sizes; (void)n_in; (void)out_size;
  const float* hs   = (const float*)d_in[0];
  const float* rot  = (const float*)d_in[1];
  const float* Wkvd = (const float*)d_in[2];
  const float* Wqd  = (const float*)d_in[3];
  const float* Wku  = (const float*)d_in[4];
  const float* Wqu  = (const float*)d_in[5];
  const float* Wvu  = (const float*)d_in[6];
  const float* Wrk  = (const float*)d_in[7];
  const float* Wrq  = (const float*)d_in[8];
  const float* Wo   = (const float*)d_in[9];
  float* out = (float*)d_out;

  __half *hsA2,*wqkv,*wkv,*wq,*wrk,*wob,*dA2,*at1,*qb,*kb,*vb;
  float *kcvf,*qcqr,*krb;
  cudaGetSymbolAddress((void**)&hsA2, g_hsA2);
  cudaGetSymbolAddress((void**)&wqkv, g_Wqkv);
  cudaGetSymbolAddress((void**)&wkv , g_Wkv);
  cudaGetSymbolAddress((void**)&wq  , g_Wq);
  cudaGetSymbolAddress((void**)&wrk , g_Wrk);
  cudaGetSymbolAddress((void**)&wob , g_Wob);
  cudaGetSymbolAddress((void**)&dA2 , g_dA2);
  cudaGetSymbolAddress((void**)&kcvf, g_kcvf);
  cudaGetSymbolAddress((void**)&qcqr, g_qcqr);
  cudaGetSymbolAddress((void**)&krb , g_krb);
  cudaGetSymbolAddress((void**)&qb  , g_qb);
  cudaGetSymbolAddress((void**)&kb  , g_kb);
  cudaGetSymbolAddress((void**)&vb  , g_vb);
  cudaGetSymbolAddress((void**)&at1 , g_at1);

  // --- input conversions ---
  convA_kernel<<<(TOKn*1536)/256, 256>>>(hs, hsA2, 1536);
  {
    ConvJobs J;
    const float* Ws[8] = {Wkvd, Wqd, Wku, Wvu, Wqu, Wrq, Wrk, Wo};
    __half* Bs[8] = {wqkv, wqkv + (size_t)192*1536, wkv,
                     wkv + (size_t)768*192, wq, wq + (size_t)768*192,
                     wrk, wob};
    int Ks[8]  = {1536,1536,192,192,192,192,1536,1536};
    int Nsz[8] = {192,192,768,1536,768,768,768,1536};
    int acc = 0;
    for (int j = 0; j < 8; j++) {
      J.W[j] = Ws[j]; J.Bt[j] = Bs[j];
      J.K[j] = Ks[j]; J.N[j] = Nsz[j];
      J.bstart[j] = acc;
      acc += (Nsz[j]/32)*(Ks[j]/32);
    }
    J.bstart[8] = acc;
    convW_kernel<<<acc, dim3(32,8)>>>(J);
  }

  // --- GEMM smem sizes per instantiation ---
  const int SM_64_2  = (128*40*2 +  64*40)*3*2;  // 76800
  const int SM_128_2 = (128*40*2 + 128*40)*3*2;  // 92160
  const int SM_128_1 = (128*40   + 128*40)*3*2;  // 61440
  cudaFuncSetAttribute(hgemm_kernel<64,2,1>,
      cudaFuncAttributeMaxDynamicSharedMemorySize, SM_64_2);
  cudaFuncSetAttribute(hgemm_kernel<128,2,3>,
      cudaFuncAttributeMaxDynamicSharedMemorySize, SM_128_2);
  cudaFuncSetAttribute(hgemm_kernel<128,1,1>,
      cudaFuncAttributeMaxDynamicSharedMemorySize, SM_128_1);

  // --- qkvd: dA2 = hs @ [Wkvd|Wqd]  (BN=64 -> 192 blocks) ---
  {
    GJobs J{};
    J.j[0] = {hsA2, hsA2+1536, wqkv, nullptr, dA2, 3072, 384, 1536, 1, 6};
    J.bstart[0] = 0; J.bstart[1] = 192;
    hgemm_kernel<64,2,1><<<192, 256, SM_64_2>>>(J);
  }
  // --- batched: krb | kcvf | qcqr ---
  {
    GJobs J{};
    J.j[0] = {hsA2,   hsA2+1536, wrk, krb,  nullptr, 3072,  768, 1536, 0,  6};
    J.j[1] = {dA2,    dA2+384,   wkv, kcvf, nullptr,  768, 2304,  192, 0, 18};
    J.j[2] = {dA2+192,dA2+576,   wq,  qcqr, nullptr,  768, 1536,  192, 0, 12};
    J.bstart[0] = 0; J.bstart[1] = 192; J.bstart[2] = 768; J.bstart[3] = 1152;
    hgemm_kernel<128,2,3><<<1152, 256, SM_128_2>>>(J);
  }

  // rope + layout
  assemble_kernel<<<dim3(Hn, Sn, Bn),128>>>(qcqr, kcvf, krb, rot, qb, kb, vb);

  // flash attention
  cudaFuncSetAttribute(flash_kernel, cudaFuncAttributeMaxDynamicSharedMemorySize,
                       FLASH_SMEM);
  flash_kernel<<<dim3(16, Hn, Bn), 256, FLASH_SMEM>>>(qb, kb, vb, at1);

  // --- output projection: single-pass A (error adds at output only) ---
  {
    GJobs J{};
    J.j[0] = {at1, nullptr, wob, out, nullptr, 1536, 1536, 1536, 0, 12};
    J.bstart[0] = 0; J.bstart[1] = 384;
    hgemm_kernel<128,1,1><<<384, 256, SM_128_1>>>(J);
  }
}

// round 10
// speedup vs baseline: 6.2724x; 1.1903x over previous
#include <cuda_runtime.h>
#include <cuda_fp16.h>
#include <cstdint>
#include <stdint.h>
#include <math.h>

#define Bn   2
#define Sn   2048
#define HIDn 1536
#define Hn   12
#define HDn  128
#define TOKn (Bn*Sn)   // 4096

// ---------------- scratch (device globals; no allocations allowed) ----------
__device__ __half g_hsA2[(size_t)TOKn*3072];     // hidden split fp16 [row][hi1536|lo1536]
__device__ __half g_Wqkv[(size_t)384*1536];      // [n][k] single fp16
__device__ __half g_Wkv [(size_t)2304*192];
__device__ __half g_Wq  [(size_t)1536*192];
__device__ __half g_Wrk [(size_t)768*1536];
__device__ __half g_Wob [(size_t)1536*1536];
__device__ __half g_dA1 [(size_t)TOKn*384];      // [tok][kvd192|qd192] single fp16
__device__ float g_kcvf[(size_t)TOKn*2304];
__device__ float g_qcqr[(size_t)TOKn*1536];
__device__ float g_krb [(size_t)TOKn*768];
__device__ __half g_qb[(size_t)Bn*Hn*Sn*256];    // Q split [s][hi128|lo128]
__device__ __half g_kb[(size_t)Bn*Hn*Sn*128];    // K single
__device__ __half g_vb[(size_t)Bn*Hn*Sn*128];    // V single
__device__ __half g_at1[(size_t)TOKn*1536];      // attn out single fp16

// ---------------- helpers ----------------------------------------------------
__device__ __forceinline__ unsigned pack2h(float a, float b) {
  __half2 t = __floats2half2_rn(a, b);
  return *(unsigned*)&t;
}

#define MMAF16(d0,d1,d2,d3,a0,a1,a2,a3,b0,b1)                              \
  asm volatile("mma.sync.aligned.m16n8k16.row.col.f32.f16.f16.f32 "         \
    "{%0,%1,%2,%3},{%4,%5,%6,%7},{%8,%9},{%0,%1,%2,%3};"                    \
    : "+f"(d0),"+f"(d1),"+f"(d2),"+f"(d3)                                    \
    : "r"(a0),"r"(a1),"r"(a2),"r"(a3),"r"(b0),"r"(b1))
#define LDSM_X4(r0,r1,r2,r3,addr)                                           \
  asm volatile("ldmatrix.sync.aligned.m8n8.x4.shared.b16 "                  \
    "{%0,%1,%2,%3},[%4];"                                                   \
    : "=r"(r0),"=r"(r1),"=r"(r2),"=r"(r3) : "r"(addr))
#define LDSM_X4T(r0,r1,r2,r3,addr)                                          \
  asm volatile("ldmatrix.sync.aligned.m8n8.x4.trans.shared.b16 "            \
    "{%0,%1,%2,%3},[%4];"                                                   \
    : "=r"(r0),"=r"(r1),"=r"(r2),"=r"(r3) : "r"(addr))
#define CPASYNC16(dst, src)                                                 \
  asm volatile("cp.async.cg.shared.global [%0],[%1],16;" :: "r"(dst), "l"(src))

// ---------------- conversion kernels ----------------------------------------
__global__ __launch_bounds__(256)
void convA_kernel(const float* __restrict__ X, __half* __restrict__ Y, int K) {
  size_t i = (size_t)blockIdx.x*256 + threadIdx.x;
  float x = X[i];
  size_t row = i / K, col = i % K;
  __half hi = __float2half(x);
  float lo = x - __half2float(hi);
  Y[row*(2*(size_t)K) + col]     = hi;
  Y[row*(2*(size_t)K) + K + col] = __float2half(lo);
}

struct ConvJobs {
  const float* W[8];
  __half* Bt[8];
  int K[8], N[8];
  int bstart[9];
};
__global__ __launch_bounds__(256)
void convW_kernel(ConvJobs J) {
  __shared__ float t[32][33];
  int bx = blockIdx.x;
  int j = 0;
  while (bx >= J.bstart[j+1]) j++;
  int lb = bx - J.bstart[j];
  int nbn = J.N[j] >> 5;
  int n0 = (lb % nbn) << 5, k0 = (lb / nbn) << 5;
  const float* W = J.W[j];
  __half* Bt = J.Bt[j];
  int K = J.K[j], N = J.N[j];
  #pragma unroll
  for (int i = threadIdx.y; i < 32; i += 8)
    t[i][threadIdx.x] = W[(size_t)(k0+i)*N + n0 + threadIdx.x];
  __syncthreads();
  #pragma unroll
  for (int i = threadIdx.y; i < 32; i += 8) {
    int n = n0 + i, k = k0 + threadIdx.x;
    Bt[(size_t)n*K + k] = __float2half(t[threadIdx.x][i]);
  }
}

// ---------------- fp16 tensor-core GEMM (batched jobs, 3-stage, BK=32) ------
// C[M][N] = (Ahi [+Alo]) @ B16^T.  BM=128, BN in {64,128}, 256 threads.
// PASSES=2: fused hi/lo per K-chunk (B frags reused). PASSES=1: single.
// outmode 0: fp32 C.  outmode 1: single fp16 Cb [row][N].
struct GJob {
  const __half *Ahi, *Alo, *Bm;
  float* C; __half* Cb;
  int lda, N, K, outmode, nbx;
};
struct GJobs { GJob j[3]; int bstart[4]; };

template<int BN, int PASSES, int NJ>
__global__ __launch_bounds__(256)
void hgemm_kernel(GJobs JB) {
  constexpr int ASZ   = 128*40;                 // halves per A plane
  constexpr int BOFF  = ASZ*PASSES;             // B offset in stage
  constexpr int STAGE = ASZ*PASSES + BN*40;     // halves per stage
  constexpr int WN = BN/32, WM = 8/WN, MT = 128/(WM*16);

  extern __shared__ __half hsm[];
  int tid = threadIdx.x;
  int bid = blockIdx.x;
  int ji = 0;
  #pragma unroll
  for (int t = 1; t < NJ; t++) if (bid >= JB.bstart[t]) ji = t;
  GJob jb = JB.j[ji];
  int lb = bid - JB.bstart[ji];
  int bx = lb % jb.nbx, by = lb / jb.nbx;
  const __half* Ahi = jb.Ahi;
  const __half* Alo = jb.Alo;
  const __half* Bm  = jb.Bm;
  int lda = jb.lda, N = jb.N, K = jb.K;
  int KIT = K >> 5;

  auto load_st = [&](int it, int slot) {
    int kk = it << 5;
    __half* dst = hsm + slot*STAGE;
    #pragma unroll
    for (int p = 0; p < 2; p++) {
      int u = tid + (p << 8);
      int row = u >> 2, c = u & 3;
      int soff = row*40 + c*8;
      size_t ga = (size_t)(by*128 + row)*lda + kk + c*8;
      unsigned dh = (unsigned)__cvta_generic_to_shared(dst + soff);
      CPASYNC16(dh, Ahi + ga);
      if (PASSES == 2) {
        unsigned dl = (unsigned)__cvta_generic_to_shared(dst + ASZ + soff);
        CPASYNC16(dl, Alo + ga);
      }
    }
    #pragma unroll
    for (int p = 0; p < BN/64; p++) {
      int u = tid + (p << 8);
      int row = u >> 2, c = u & 3;
      const __half* sB = Bm + (size_t)(bx*BN + row)*K + kk + c*8;
      unsigned db = (unsigned)__cvta_generic_to_shared(dst + BOFF + row*40 + c*8);
      CPASYNC16(db, sB);
    }
    asm volatile("cp.async.commit_group;");
  };

  int wid = tid >> 5, lane = tid & 31;
  int wm = wid / WN, wn = wid % WN;
  int g = lane >> 2, tig = lane & 3;
  int lr = lane & 15, lc = (lane >> 4) << 3;

  float acc[MT][4][4];
  #pragma unroll
  for (int mt=0; mt<MT; mt++)
    #pragma unroll
    for (int nt=0; nt<4; nt++)
      #pragma unroll
      for (int r=0; r<4; r++) acc[mt][nt][r] = 0.f;

  load_st(0, 0);
  load_st(1, 1);

  for (int it = 0; it < KIT; ++it) {
    if (it + 1 < KIT) asm volatile("cp.async.wait_group 1;");
    else              asm volatile("cp.async.wait_group 0;");
    __syncthreads();
    if (it + 2 < KIT) load_st(it + 2, (it + 2) % 3);
    const __half* St = hsm + (it % 3)*STAGE;

    #pragma unroll
    for (int ks = 0; ks < 2; ks++) {
      unsigned b[4][2];
      #pragma unroll
      for (int bt = 0; bt < 2; bt++) {
        unsigned q0,q1,q2,q3;
        unsigned bd = (unsigned)__cvta_generic_to_shared(
            St + BOFF + (wn*32 + bt*16 + lr)*40 + ks*16 + lc);
        LDSM_X4(q0,q1,q2,q3, bd);
        b[2*bt  ][0] = q0; b[2*bt  ][1] = q2;
        b[2*bt+1][0] = q1; b[2*bt+1][1] = q3;
      }
      unsigned a[MT][4];
      #pragma unroll
      for (int mt = 0; mt < MT; mt++) {
        unsigned ad = (unsigned)__cvta_generic_to_shared(
            St + (wm*(MT*16) + mt*16 + lr)*40 + ks*16 + lc);
        LDSM_X4(a[mt][0], a[mt][1], a[mt][2], a[mt][3], ad);
      }
      #pragma unroll
      for (int mt = 0; mt < MT; mt++)
        #pragma unroll
        for (int nt = 0; nt < 4; nt++)
          MMAF16(acc[mt][nt][0],acc[mt][nt][1],acc[mt][nt][2],acc[mt][nt][3],
                 a[mt][0],a[mt][1],a[mt][2],a[mt][3],
                 b[nt][0],b[nt][1]);
      if (PASSES == 2) {
        #pragma unroll
        for (int mt = 0; mt < MT; mt++) {
          unsigned ad = (unsigned)__cvta_generic_to_shared(
              St + ASZ + (wm*(MT*16) + mt*16 + lr)*40 + ks*16 + lc);
          LDSM_X4(a[mt][0], a[mt][1], a[mt][2], a[mt][3], ad);
        }
        #pragma unroll
        for (int mt = 0; mt < MT; mt++)
          #pragma unroll
          for (int nt = 0; nt < 4; nt++)
            MMAF16(acc[mt][nt][0],acc[mt][nt][1],acc[mt][nt][2],acc[mt][nt][3],
                   a[mt][0],a[mt][1],a[mt][2],a[mt][3],
                   b[nt][0],b[nt][1]);
      }
    }
  }

  #pragma unroll
  for (int mt = 0; mt < MT; mt++) {
    #pragma unroll
    for (int nt = 0; nt < 4; nt++) {
      int row = by*128 + wm*(MT*16) + mt*16 + g;
      int col = bx*BN + wn*32 + nt*8 + 2*tig;
      if (jb.outmode == 0) {
        float2 v0 = make_float2(acc[mt][nt][0], acc[mt][nt][1]);
        float2 v1 = make_float2(acc[mt][nt][2], acc[mt][nt][3]);
        *(float2*)&jb.C[(size_t)row    *N + col] = v0;
        *(float2*)&jb.C[(size_t)(row+8)*N + col] = v1;
      } else {
        *(__half2*)&jb.Cb[(size_t)row    *N + col] =
            __floats2half2_rn(acc[mt][nt][0], acc[mt][nt][1]);
        *(__half2*)&jb.Cb[(size_t)(row+8)*N + col] =
            __floats2half2_rn(acc[mt][nt][2], acc[mt][nt][3]);
      }
    }
  }
}

// ---------------- assemble: RoPE + layout + scale ---------------------------
__global__ __launch_bounds__(128)
void assemble_kernel(const float* __restrict__ qcqr, const float* __restrict__ kcvf,
                     const float* __restrict__ krb, const float* __restrict__ rot,
                     __half* __restrict__ Qh, __half* __restrict__ Kh,
                     __half* __restrict__ Vh) {
  int h = blockIdx.x, s = blockIdx.y, b = blockIdx.z;
  int d = threadIdx.x;
  int token = b*Sn + s;
  size_t bhs = (size_t)(b*Hn + h)*Sn + s;
  const float SCALE = 0.08838834764831845f;

  Vh[bhs*128 + d] = __float2half(kcvf[(size_t)token*2304 + 768 + h*HDn + d]);

  float qv, kv;
  if (d < 64) {
    qv = qcqr[(size_t)token*1536 + h*64 + d];
    kv = kcvf[(size_t)token*2304 + h*64 + d];
  } else {
    int i = d - 64;
    const float* rrow = rot + (size_t)s*64;
    const float* qrow = qcqr + (size_t)token*1536 + 768 + h*64;
    const float* krow = krb + (size_t)token*768 + h*64;
    if (i < 32) {
      float sn = rrow[i], cs = rrow[32+i];
      qv = qrow[i]*cs - qrow[i+32]*sn;
      kv = krow[i]*cs - krow[i+32]*sn;
    } else {
      int ii = i - 32;
      float sn = rrow[ii], cs = rrow[32+ii];
      qv = qrow[ii]*sn + qrow[ii+32]*cs;
      kv = krow[ii]*sn + krow[ii+32]*cs;
    }
  }
  qv *= SCALE;
  __half qhi = __float2half(qv);
  Qh[bhs*256 + d]       = qhi;
  Qh[bhs*256 + 128 + d] = __float2half(qv - __half2float(qhi));
  Kh[bhs*128 + d] = __float2half(kv);
}

// ---------------- causal flash attention (QK 2-pass, PV 1-pass) -------------
#define FLASH_SMEM 139264   // (2*128*136 + 2*64*136 + 2*64*136) halves * 2B

__global__ __launch_bounds__(256)
void flash_kernel(const __half* __restrict__ Qg,
                  const __half* __restrict__ Kg,
                  const __half* __restrict__ Vg,
                  __half* __restrict__ At) {
  extern __shared__ __half fsm[];
  __half* Qs = fsm;              // [2 plane][128][136]
  __half* Ks = fsm + 34816;      // [2 buf][64][136]
  __half* Vs = fsm + 52224;      // [2 buf][64][136]

  int qi = 15 - (int)blockIdx.x;
  int h = blockIdx.y, b = blockIdx.z;
  int bh = b*Hn + h;
  int qbase = qi*128;
  const __half* Qb = Qg + ((size_t)bh*Sn + qbase)*256;
  const __half* Kb = Kg + (size_t)bh*Sn*128;
  const __half* Vb = Vg + (size_t)bh*Sn*128;

  int tid = threadIdx.x;
  int wid = tid>>5, lane = tid&31, g = lane>>2, tig = lane&3;
  int lr = lane & 15, lc = (lane >> 4) << 3;
  int jmax = 2*qi + 2;
  int r0 = wid*16;

  #pragma unroll
  for (int p=0;p<16;p++){
    int lin = tid + p*256;
    int row = lin>>5, c = lin&31;
    const __half* src = Qb + (size_t)row*256 + c*8;
    unsigned d = (unsigned)__cvta_generic_to_shared(Qs + (c>>4)*17408 + row*136 + (c&15)*8);
    CPASYNC16(d, src);
  }
  auto load_kv = [&](int jt, int buf){
    #pragma unroll
    for (int p=0;p<4;p++){
      int lin = tid + p*256;
      int row = lin>>4, c = lin&15;
      size_t s_off = (size_t)(jt*64 + row)*128 + c*8;
      int doff = buf*8704 + row*136 + c*8;
      unsigned dk = (unsigned)__cvta_generic_to_shared(Ks + doff);
      CPASYNC16(dk, Kb + s_off);
      unsigned dv = (unsigned)__cvta_generic_to_shared(Vs + doff);
      CPASYNC16(dv, Vb + s_off);
    }
    asm volatile("cp.async.commit_group;");
  };
  load_kv(0, 0);

  float o[16][4];
  #pragma unroll
  for (int nt=0;nt<16;nt++)
    #pragma unroll
    for (int r=0;r<4;r++) o[nt][r] = 0.f;
  float m0=-1e30f, m1=-1e30f, l0=0.f, l1=0.f;

  for (int jt = 0; jt < jmax; jt++) {
    int buf = jt & 1;
    asm volatile("cp.async.wait_group 0;");
    __syncthreads();
    if (jt + 1 < jmax) load_kv(jt+1, buf^1);

    const __half* Kbuf = Ks + buf*8704;
    float acc[8][4];
    #pragma unroll
    for (int t=0;t<8;t++)
      #pragma unroll
      for (int r=0;r<4;r++) acc[t][r] = 0.f;

    #pragma unroll
    for (int ks=0; ks<8; ks++){
      unsigned ah[4], al[4];
      {
        unsigned qd = (unsigned)__cvta_generic_to_shared(
            Qs + (r0 + lr)*136 + ks*16 + lc);
        LDSM_X4(ah[0],ah[1],ah[2],ah[3], qd);
        LDSM_X4(al[0],al[1],al[2],al[3], qd + 34816);
      }
      unsigned bk[8][2];
      #pragma unroll
      for (int t16=0; t16<4; t16++){
        unsigned q0,q1,q2,q3;
        unsigned kd = (unsigned)__cvta_generic_to_shared(
            Kbuf + (t16*16 + lr)*136 + ks*16 + lc);
        LDSM_X4(q0,q1,q2,q3, kd);
        bk[2*t16  ][0] = q0; bk[2*t16  ][1] = q2;
        bk[2*t16+1][0] = q1; bk[2*t16+1][1] = q3;
      }
      #pragma unroll
      for (int t=0;t<8;t++){
        MMAF16(acc[t][0],acc[t][1],acc[t][2],acc[t][3],
               ah[0],ah[1],ah[2],ah[3], bk[t][0],bk[t][1]);
        MMAF16(acc[t][0],acc[t][1],acc[t][2],acc[t][3],
               al[0],al[1],al[2],al[3], bk[t][0],bk[t][1]);
      }
    }

    if (jt >= jmax-2) {
      int rg0 = qbase + r0 + g, rg1 = rg0 + 8;
      #pragma unroll
      for (int t=0;t<8;t++){
        int c0 = jt*64 + t*8 + 2*tig;
        if (c0   > rg0) acc[t][0] = -1e30f;
        if (c0+1 > rg0) acc[t][1] = -1e30f;
        if (c0   > rg1) acc[t][2] = -1e30f;
        if (c0+1 > rg1) acc[t][3] = -1e30f;
      }
    }

    float mx0=-1e30f, mx1=-1e30f;
    #pragma unroll
    for (int t=0;t<8;t++){
      mx0 = fmaxf(mx0, fmaxf(acc[t][0],acc[t][1]));
      mx1 = fmaxf(mx1, fmaxf(acc[t][2],acc[t][3]));
    }
    mx0 = fmaxf(mx0, __shfl_xor_sync(0xffffffffu, mx0, 1));
    mx0 = fmaxf(mx0, __shfl_xor_sync(0xffffffffu, mx0, 2));
    mx1 = fmaxf(mx1, __shfl_xor_sync(0xffffffffu, mx1, 1));
    mx1 = fmaxf(mx1, __shfl_xor_sync(0xffffffffu, mx1, 2));
    float nm0 = fmaxf(m0, mx0), nm1 = fmaxf(m1, mx1);
    float cf0 = __expf(m0 - nm0), cf1 = __expf(m1 - nm1);
    m0 = nm0; m1 = nm1;
    float s0 = 0.f, s1 = 0.f;
    #pragma unroll
    for (int t=0;t<8;t++){
      acc[t][0] = __expf(acc[t][0]-nm0);
      acc[t][1] = __expf(acc[t][1]-nm0);
      acc[t][2] = __expf(acc[t][2]-nm1);
      acc[t][3] = __expf(acc[t][3]-nm1);
      s0 += acc[t][0]+acc[t][1];
      s1 += acc[t][2]+acc[t][3];
    }
    s0 += __shfl_xor_sync(0xffffffffu, s0, 1);
    s0 += __shfl_xor_sync(0xffffffffu, s0, 2);
    s1 += __shfl_xor_sync(0xffffffffu, s1, 1);
    s1 += __shfl_xor_sync(0xffffffffu, s1, 2);
    l0 = l0*cf0 + s0;
    l1 = l1*cf1 + s1;
    #pragma unroll
    for (int nt=0;nt<16;nt++){
      o[nt][0] *= cf0; o[nt][1] *= cf0;
      o[nt][2] *= cf1; o[nt][3] *= cf1;
    }

    // ---- O += P @ V (single pass) ----
    const __half* Vbuf = Vs + buf*8704;
    int vrow = ((lane>>3)&1)*8 + (lane&7);
    int vcol = (lane>>4)*8;
    #pragma unroll
    for (int u=0;u<4;u++){
      unsigned ph[4];
      ph[0] = pack2h(acc[2*u  ][0], acc[2*u  ][1]);
      ph[1] = pack2h(acc[2*u  ][2], acc[2*u  ][3]);
      ph[2] = pack2h(acc[2*u+1][0], acc[2*u+1][1]);
      ph[3] = pack2h(acc[2*u+1][2], acc[2*u+1][3]);
      unsigned base = (unsigned)__cvta_generic_to_shared(
          Vbuf + (u*16 + vrow)*136 + vcol);
      #pragma unroll
      for (int dt=0;dt<8;dt++){
        unsigned v0,v1,v2,v3;
        LDSM_X4T(v0,v1,v2,v3, base + dt*32);
        MMAF16(o[dt*2  ][0],o[dt*2  ][1],o[dt*2  ][2],o[dt*2  ][3],
               ph[0],ph[1],ph[2],ph[3], v0,v1);
        MMAF16(o[dt*2+1][0],o[dt*2+1][1],o[dt*2+1][2],o[dt*2+1][3],
               ph[0],ph[1],ph[2],ph[3], v2,v3);
      }
    }
  }

  // ---- epilogue: normalize, single fp16 token-major output ----
  float i0 = 1.f/l0, i1 = 1.f/l1;
  int tok0 = b*Sn + qbase + r0 + g;
  __half* o0 = At + (size_t)tok0*1536 + h*128;
  __half* o1 = At + (size_t)(tok0+8)*1536 + h*128;
  #pragma unroll
  for (int nt=0;nt<16;nt++){
    int col = nt*8 + 2*tig;
    *(__half2*)(o0 + col) = __floats2half2_rn(o[nt][0]*i0, o[nt][1]*i0);
    *(__half2*)(o1 + col) = __floats2half2_rn(o[nt][2]*i1, o[nt][3]*i1);
  }
}

// ---------------- launch -----------------------------------------------------
extern "C" void kernel_launch(void* const* d_in, const int* in_sizes, int n_in,
                              void* d_out, int out_size) {
  (void)in_sizes; (void)n_in; (void)out_size;
  const float* hs   = (const float*)d_in[0];
  const float* rot  = (const float*)d_in[1];
  const float* Wkvd = (const float*)d_in[2];
  const float* Wqd  = (const float*)d_in[3];
  const float* Wku  = (const float*)d_in[4];
  const float* Wqu  = (const float*)d_in[5];
  const float* Wvu  = (const float*)d_in[6];
  const float* Wrk  = (const float*)d_in[7];
  const float* Wrq  = (const float*)d_in[8];
  const float* Wo   = (const float*)d_in[9];
  float* out = (float*)d_out;

  __half *hsA2,*wqkv,*wkv,*wq,*wrk,*wob,*dA1,*at1,*qb,*kb,*vb;
  float *kcvf,*qcqr,*krb;
  cudaGetSymbolAddress((void**)&hsA2, g_hsA2);
  cudaGetSymbolAddress((void**)&wqkv, g_Wqkv);
  cudaGetSymbolAddress((void**)&wkv , g_Wkv);
  cudaGetSymbolAddress((void**)&wq  , g_Wq);
  cudaGetSymbolAddress((void**)&wrk , g_Wrk);
  cudaGetSymbolAddress((void**)&wob , g_Wob);
  cudaGetSymbolAddress((void**)&dA1 , g_dA1);
  cudaGetSymbolAddress((void**)&kcvf, g_kcvf);
  cudaGetSymbolAddress((void**)&qcqr, g_qcqr);
  cudaGetSymbolAddress((void**)&krb , g_krb);
  cudaGetSymbolAddress((void**)&qb  , g_qb);
  cudaGetSymbolAddress((void**)&kb  , g_kb);
  cudaGetSymbolAddress((void**)&vb  , g_vb);
  cudaGetSymbolAddress((void**)&at1 , g_at1);

  // --- input conversions ---
  convA_kernel<<<(TOKn*1536)/256, 256>>>(hs, hsA2, 1536);
  {
    ConvJobs J;
    const float* Ws[8] = {Wkvd, Wqd, Wku, Wvu, Wqu, Wrq, Wrk, Wo};
    __half* Bs[8] = {wqkv, wqkv + (size_t)192*1536, wkv,
                     wkv + (size_t)768*192, wq, wq + (size_t)768*192,
                     wrk, wob};
    int Ks[8]  = {1536,1536,192,192,192,192,1536,1536};
    int Nsz[8] = {192,192,768,1536,768,768,768,1536};
    int acc = 0;
    for (int j = 0; j < 8; j++) {
      J.W[j] = Ws[j]; J.Bt[j] = Bs[j];
      J.K[j] = Ks[j]; J.N[j] = Nsz[j];
      J.bstart[j] = acc;
      acc += (Nsz[j]/32)*(Ks[j]/32);
    }
    J.bstart[8] = acc;
    convW_kernel<<<acc, dim3(32,8)>>>(J);
  }

  // --- GEMM smem sizes per instantiation ---
  const int SM_64_2  = (128*40*2 +  64*40)*3*2;  // 76800
  const int SM_128_1 = (128*40   + 128*40)*3*2;  // 61440
  cudaFuncSetAttribute(hgemm_kernel<64,2,1>,
      cudaFuncAttributeMaxDynamicSharedMemorySize, SM_64_2);
  cudaFuncSetAttribute(hgemm_kernel<128,1,3>,
      cudaFuncAttributeMaxDynamicSharedMemorySize, SM_128_1);
  cudaFuncSetAttribute(hgemm_kernel<128,1,1>,
      cudaFuncAttributeMaxDynamicSharedMemorySize, SM_128_1);

  // --- qkvd: dA1 = hs @ [Wkvd|Wqd]  (2-pass A, single fp16 out) ---
  {
    GJobs J{};
    J.j[0] = {hsA2, hsA2+1536, wqkv, nullptr, dA1, 3072, 384, 1536, 1, 6};
    J.bstart[0] = 0; J.bstart[1] = 192;
    hgemm_kernel<64,2,1><<<192, 256, SM_64_2>>>(J);
  }
  // --- batched single-pass: krb | kcvf | qcqr ---
  {
    GJobs J{};
    J.j[0] = {hsA2,    nullptr, wrk, krb,  nullptr, 3072,  768, 1536, 0,  6};
    J.j[1] = {dA1,     nullptr, wkv, kcvf, nullptr,  384, 2304,  192, 0, 18};
    J.j[2] = {dA1+192, nullptr, wq,  qcqr, nullptr,  384, 1536,  192, 0, 12};
    J.bstart[0] = 0; J.bstart[1] = 192; J.bstart[2] = 768; J.bstart[3] = 1152;
    hgemm_kernel<128,1,3><<<1152, 256, SM_128_1>>>(J);
  }

  // rope + layout
  assemble_kernel<<<dim3(Hn, Sn, Bn),128>>>(qcqr, kcvf, krb, rot, qb, kb, vb);

  // flash attention
  cudaFuncSetAttribute(flash_kernel, cudaFuncAttributeMaxDynamicSharedMemorySize,
                       FLASH_SMEM);
  flash_kernel<<<dim3(16, Hn, Bn), 256, FLASH_SMEM>>>(qb, kb, vb, at1);

  // --- output projection: single-pass A ---
  {
    GJobs J{};
    J.j[0] = {at1, nullptr, wob, out, nullptr, 1536, 1536, 1536, 0, 12};
    J.bstart[0] = 0; J.bstart[1] = 384;
    hgemm_kernel<128,1,1><<<384, 256, SM_128_1>>>(J);
  }
}

// round 11
// speedup vs baseline: 6.4720x; 1.0318x over previous
#include <cuda_runtime.h>
#include <cuda_fp16.h>
#include <cstdint>
#include <stdint.h>
#include <math.h>

#define Bn   2
#define Sn   2048
#define HIDn 1536
#define Hn   12
#define HDn  128
#define TOKn (Bn*Sn)   // 4096

// ---------------- scratch (device globals; no allocations allowed) ----------
__device__ __half g_hsA2[(size_t)TOKn*3072];     // hidden split fp16 [row][hi1536|lo1536]
__device__ __half g_Wqkv[(size_t)384*1536];      // [n][k] single fp16
__device__ __half g_Wkv [(size_t)2304*192];
__device__ __half g_Wq  [(size_t)1536*192];
__device__ __half g_Wrk [(size_t)768*1536];
__device__ __half g_Wob [(size_t)1536*1536];
__device__ __half g_dA1 [(size_t)TOKn*384];      // [tok][kvd192|qd192] single fp16
__device__ __half g_kcvf[(size_t)TOKn*2304];     // fp16 (K/V rounded anyway)
__device__ float g_qcqr[(size_t)TOKn*1536];      // fp32 (feeds Q hi/lo split)
__device__ __half g_krb [(size_t)TOKn*768];      // fp16
__device__ __half g_qb[(size_t)Bn*Hn*Sn*256];    // Q split [s][hi128|lo128]
__device__ __half g_kb[(size_t)Bn*Hn*Sn*128];    // K single
__device__ __half g_vb[(size_t)Bn*Hn*Sn*128];    // V single
__device__ __half g_at1[(size_t)TOKn*1536];      // attn out single fp16

// ---------------- helpers ----------------------------------------------------
__device__ __forceinline__ unsigned pack2h(float a, float b) {
  __half2 t = __floats2half2_rn(a, b);
  return *(unsigned*)&t;
}

#define MMAF16(d0,d1,d2,d3,a0,a1,a2,a3,b0,b1)                              \
  asm volatile("mma.sync.aligned.m16n8k16.row.col.f32.f16.f16.f32 "         \
    "{%0,%1,%2,%3},{%4,%5,%6,%7},{%8,%9},{%0,%1,%2,%3};"                    \
    : "+f"(d0),"+f"(d1),"+f"(d2),"+f"(d3)                                    \
    : "r"(a0),"r"(a1),"r"(a2),"r"(a3),"r"(b0),"r"(b1))
#define LDSM_X4(r0,r1,r2,r3,addr)                                           \
  asm volatile("ldmatrix.sync.aligned.m8n8.x4.shared.b16 "                  \
    "{%0,%1,%2,%3},[%4];"                                                   \
    : "=r"(r0),"=r"(r1),"=r"(r2),"=r"(r3) : "r"(addr))
#define LDSM_X4T(r0,r1,r2,r3,addr)                                          \
  asm volatile("ldmatrix.sync.aligned.m8n8.x4.trans.shared.b16 "            \
    "{%0,%1,%2,%3},[%4];"                                                   \
    : "=r"(r0),"=r"(r1),"=r"(r2),"=r"(r3) : "r"(addr))
#define CPASYNC16(dst, src)                                                 \
  asm volatile("cp.async.cg.shared.global [%0],[%1],16;" :: "r"(dst), "l"(src))

// ---------------- conversion kernels ----------------------------------------
// vectorized: each thread converts 4 floats (K=1536 divisible by 4)
__global__ __launch_bounds__(256)
void convA_kernel(const float4* __restrict__ X, __half* __restrict__ Y) {
  size_t i = (size_t)blockIdx.x*256 + threadIdx.x;
  float4 v = X[i];
  size_t e = i*4;
  size_t row = e / 1536, col = e % 1536;
  __half2 h0 = __floats2half2_rn(v.x, v.y);
  __half2 h1 = __floats2half2_rn(v.z, v.w);
  __half* hi = Y + row*3072 + col;
  *(__half2*)(hi)     = h0;
  *(__half2*)(hi + 2) = h1;
  float l0 = v.x - __half2float(__low2half(h0));
  float l1 = v.y - __half2float(__high2half(h0));
  float l2 = v.z - __half2float(__low2half(h1));
  float l3 = v.w - __half2float(__high2half(h1));
  __half* lo = hi + 1536;
  *(__half2*)(lo)     = __floats2half2_rn(l0, l1);
  *(__half2*)(lo + 2) = __floats2half2_rn(l2, l3);
}

struct ConvJobs {
  const float* W[8];
  __half* Bt[8];
  int K[8], N[8];
  int bstart[9];
};
__global__ __launch_bounds__(256)
void convW_kernel(ConvJobs J) {
  __shared__ float t[32][33];
  int bx = blockIdx.x;
  int j = 0;
  while (bx >= J.bstart[j+1]) j++;
  int lb = bx - J.bstart[j];
  int nbn = J.N[j] >> 5;
  int n0 = (lb % nbn) << 5, k0 = (lb / nbn) << 5;
  const float* W = J.W[j];
  __half* Bt = J.Bt[j];
  int K = J.K[j], N = J.N[j];
  #pragma unroll
  for (int i = threadIdx.y; i < 32; i += 8)
    t[i][threadIdx.x] = W[(size_t)(k0+i)*N + n0 + threadIdx.x];
  __syncthreads();
  #pragma unroll
  for (int i = threadIdx.y; i < 32; i += 8) {
    int n = n0 + i, k = k0 + threadIdx.x;
    Bt[(size_t)n*K + k] = __float2half(t[threadIdx.x][i]);
  }
}

// ---------------- fp16 tensor-core GEMM (batched jobs, 3-stage, BK=32) ------
// C[M][N] = (Ahi [+Alo]) @ B16^T.  BM=128, BN in {64,128}, 256 threads.
// PASSES=2: fused hi/lo per K-chunk (B frags reused). PASSES=1: single.
// outmode 0: fp32 C.  outmode 1: single fp16 Cb [row][N].
struct GJob {
  const __half *Ahi, *Alo, *Bm;
  float* C; __half* Cb;
  int lda, N, K, outmode, nbx;
};
struct GJobs { GJob j[3]; int bstart[4]; };

template<int BN, int PASSES, int NJ>
__global__ __launch_bounds__(256)
void hgemm_kernel(GJobs JB) {
  constexpr int ASZ   = 128*40;                 // halves per A plane
  constexpr int BOFF  = ASZ*PASSES;             // B offset in stage
  constexpr int STAGE = ASZ*PASSES + BN*40;     // halves per stage
  constexpr int WN = BN/32, WM = 8/WN, MT = 128/(WM*16);

  extern __shared__ __half hsm[];
  int tid = threadIdx.x;
  int bid = blockIdx.x;
  int ji = 0;
  #pragma unroll
  for (int t = 1; t < NJ; t++) if (bid >= JB.bstart[t]) ji = t;
  GJob jb = JB.j[ji];
  int lb = bid - JB.bstart[ji];
  int bx = lb % jb.nbx, by = lb / jb.nbx;
  const __half* Ahi = jb.Ahi;
  const __half* Alo = jb.Alo;
  const __half* Bm  = jb.Bm;
  int lda = jb.lda, N = jb.N, K = jb.K;
  int KIT = K >> 5;

  auto load_st = [&](int it, int slot) {
    int kk = it << 5;
    __half* dst = hsm + slot*STAGE;
    #pragma unroll
    for (int p = 0; p < 2; p++) {
      int u = tid + (p << 8);
      int row = u >> 2, c = u & 3;
      int soff = row*40 + c*8;
      size_t ga = (size_t)(by*128 + row)*lda + kk + c*8;
      unsigned dh = (unsigned)__cvta_generic_to_shared(dst + soff);
      CPASYNC16(dh, Ahi + ga);
      if (PASSES == 2) {
        unsigned dl = (unsigned)__cvta_generic_to_shared(dst + ASZ + soff);
        CPASYNC16(dl, Alo + ga);
      }
    }
    #pragma unroll
    for (int p = 0; p < BN/64; p++) {
      int u = tid + (p << 8);
      int row = u >> 2, c = u & 3;
      const __half* sB = Bm + (size_t)(bx*BN + row)*K + kk + c*8;
      unsigned db = (unsigned)__cvta_generic_to_shared(dst + BOFF + row*40 + c*8);
      CPASYNC16(db, sB);
    }
    asm volatile("cp.async.commit_group;");
  };

  int wid = tid >> 5, lane = tid & 31;
  int wm = wid / WN, wn = wid % WN;
  int g = lane >> 2, tig = lane & 3;
  int lr = lane & 15, lc = (lane >> 4) << 3;

  float acc[MT][4][4];
  #pragma unroll
  for (int mt=0; mt<MT; mt++)
    #pragma unroll
    for (int nt=0; nt<4; nt++)
      #pragma unroll
      for (int r=0; r<4; r++) acc[mt][nt][r] = 0.f;

  load_st(0, 0);
  load_st(1, 1);

  for (int it = 0; it < KIT; ++it) {
    if (it + 1 < KIT) asm volatile("cp.async.wait_group 1;");
    else              asm volatile("cp.async.wait_group 0;");
    __syncthreads();
    if (it + 2 < KIT) load_st(it + 2, (it + 2) % 3);
    const __half* St = hsm + (it % 3)*STAGE;

    #pragma unroll
    for (int ks = 0; ks < 2; ks++) {
      unsigned b[4][2];
      #pragma unroll
      for (int bt = 0; bt < 2; bt++) {
        unsigned q0,q1,q2,q3;
        unsigned bd = (unsigned)__cvta_generic_to_shared(
            St + BOFF + (wn*32 + bt*16 + lr)*40 + ks*16 + lc);
        LDSM_X4(q0,q1,q2,q3, bd);
        b[2*bt  ][0] = q0; b[2*bt  ][1] = q2;
        b[2*bt+1][0] = q1; b[2*bt+1][1] = q3;
      }
      unsigned a[MT][4];
      #pragma unroll
      for (int mt = 0; mt < MT; mt++) {
        unsigned ad = (unsigned)__cvta_generic_to_shared(
            St + (wm*(MT*16) + mt*16 + lr)*40 + ks*16 + lc);
        LDSM_X4(a[mt][0], a[mt][1], a[mt][2], a[mt][3], ad);
      }
      #pragma unroll
      for (int mt = 0; mt < MT; mt++)
        #pragma unroll
        for (int nt = 0; nt < 4; nt++)
          MMAF16(acc[mt][nt][0],acc[mt][nt][1],acc[mt][nt][2],acc[mt][nt][3],
                 a[mt][0],a[mt][1],a[mt][2],a[mt][3],
                 b[nt][0],b[nt][1]);
      if (PASSES == 2) {
        #pragma unroll
        for (int mt = 0; mt < MT; mt++) {
          unsigned ad = (unsigned)__cvta_generic_to_shared(
              St + ASZ + (wm*(MT*16) + mt*16 + lr)*40 + ks*16 + lc);
          LDSM_X4(a[mt][0], a[mt][1], a[mt][2], a[mt][3], ad);
        }
        #pragma unroll
        for (int mt = 0; mt < MT; mt++)
          #pragma unroll
          for (int nt = 0; nt < 4; nt++)
            MMAF16(acc[mt][nt][0],acc[mt][nt][1],acc[mt][nt][2],acc[mt][nt][3],
                   a[mt][0],a[mt][1],a[mt][2],a[mt][3],
                   b[nt][0],b[nt][1]);
      }
    }
  }

  #pragma unroll
  for (int mt = 0; mt < MT; mt++) {
    #pragma unroll
    for (int nt = 0; nt < 4; nt++) {
      int row = by*128 + wm*(MT*16) + mt*16 + g;
      int col = bx*BN + wn*32 + nt*8 + 2*tig;
      if (jb.outmode == 0) {
        float2 v0 = make_float2(acc[mt][nt][0], acc[mt][nt][1]);
        float2 v1 = make_float2(acc[mt][nt][2], acc[mt][nt][3]);
        *(float2*)&jb.C[(size_t)row    *N + col] = v0;
        *(float2*)&jb.C[(size_t)(row+8)*N + col] = v1;
      } else {
        *(__half2*)&jb.Cb[(size_t)row    *N + col] =
            __floats2half2_rn(acc[mt][nt][0], acc[mt][nt][1]);
        *(__half2*)&jb.Cb[(size_t)(row+8)*N + col] =
            __floats2half2_rn(acc[mt][nt][2], acc[mt][nt][3]);
      }
    }
  }
}

// ---------------- assemble: RoPE + layout + scale (coalesced) ---------------
// grid (Sn, Bn), 256 threads; Q scale folds 1/sqrt(128) * log2(e) for exp2.
__global__ __launch_bounds__(256)
void assemble_kernel(const float* __restrict__ qcqr, const __half* __restrict__ kcvf,
                     const __half* __restrict__ krb, const float* __restrict__ rot,
                     __half* __restrict__ Qh, __half* __restrict__ Kh,
                     __half* __restrict__ Vh) {
  int s = blockIdx.x, b = blockIdx.y;
  int tid = threadIdx.x;
  int token = b*Sn + s;
  const float* rrow = rot + (size_t)s*64;
  const float SCALE = 0.08838834764831845f * 1.4426950408889634f;

  #pragma unroll
  for (int it = 0; it < 6; it++) {
    int lin = it*256 + tid;          // 0..1535
    int h = lin >> 7, d = lin & 127;
    size_t bhs = (size_t)(b*Hn + h)*Sn + s;

    Vh[bhs*128 + d] = kcvf[(size_t)token*2304 + 768 + h*HDn + d];

    float qv, kv;
    if (d < 64) {
      qv = qcqr[(size_t)token*1536 + h*64 + d];
      kv = __half2float(kcvf[(size_t)token*2304 + h*64 + d]);
    } else {
      int i = d - 64;
      const float* qrow = qcqr + (size_t)token*1536 + 768 + h*64;
      const __half* krow = krb + (size_t)token*768 + h*64;
      if (i < 32) {
        float sn = rrow[i], cs = rrow[32+i];
        qv = qrow[i]*cs - qrow[i+32]*sn;
        kv = __half2float(krow[i])*cs - __half2float(krow[i+32])*sn;
      } else {
        int ii = i - 32;
        float sn = rrow[ii], cs = rrow[32+ii];
        qv = qrow[ii]*sn + qrow[ii+32]*cs;
        kv = __half2float(krow[ii])*sn + __half2float(krow[ii+32])*cs;
      }
    }
    qv *= SCALE;
    __half qhi = __float2half(qv);
    Qh[bhs*256 + d]       = qhi;
    Qh[bhs*256 + 128 + d] = __float2half(qv - __half2float(qhi));
    Kh[bhs*128 + d] = __float2half(kv);
  }
}

// ---------------- causal flash attention (QK 2-pass, PV 1-pass, exp2) -------
#define FLASH_SMEM 139264   // (2*128*136 + 2*64*136 + 2*64*136) halves * 2B

__global__ __launch_bounds__(256)
void flash_kernel(const __half* __restrict__ Qg,
                  const __half* __restrict__ Kg,
                  const __half* __restrict__ Vg,
                  __half* __restrict__ At) {
  extern __shared__ __half fsm[];
  __half* Qs = fsm;              // [2 plane][128][136]
  __half* Ks = fsm + 34816;      // [2 buf][64][136]
  __half* Vs = fsm + 52224;      // [2 buf][64][136]

  int qi = 15 - (int)blockIdx.x;
  int h = blockIdx.y, b = blockIdx.z;
  int bh = b*Hn + h;
  int qbase = qi*128;
  const __half* Qb = Qg + ((size_t)bh*Sn + qbase)*256;
  const __half* Kb = Kg + (size_t)bh*Sn*128;
  const __half* Vb = Vg + (size_t)bh*Sn*128;

  int tid = threadIdx.x;
  int wid = tid>>5, lane = tid&31, g = lane>>2, tig = lane&3;
  int lr = lane & 15, lc = (lane >> 4) << 3;
  int jmax = 2*qi + 2;
  int r0 = wid*16;

  #pragma unroll
  for (int p=0;p<16;p++){
    int lin = tid + p*256;
    int row = lin>>5, c = lin&31;
    const __half* src = Qb + (size_t)row*256 + c*8;
    unsigned d = (unsigned)__cvta_generic_to_shared(Qs + (c>>4)*17408 + row*136 + (c&15)*8);
    CPASYNC16(d, src);
  }
  auto load_kv = [&](int jt, int buf){
    #pragma unroll
    for (int p=0;p<4;p++){
      int lin = tid + p*256;
      int row = lin>>4, c = lin&15;
      size_t s_off = (size_t)(jt*64 + row)*128 + c*8;
      int doff = buf*8704 + row*136 + c*8;
      unsigned dk = (unsigned)__cvta_generic_to_shared(Ks + doff);
      CPASYNC16(dk, Kb + s_off);
      unsigned dv = (unsigned)__cvta_generic_to_shared(Vs + doff);
      CPASYNC16(dv, Vb + s_off);
    }
    asm volatile("cp.async.commit_group;");
  };
  load_kv(0, 0);

  float o[16][4];
  #pragma unroll
  for (int nt=0;nt<16;nt++)
    #pragma unroll
    for (int r=0;r<4;r++) o[nt][r] = 0.f;
  float m0=-1e30f, m1=-1e30f, l0=0.f, l1=0.f;

  for (int jt = 0; jt < jmax; jt++) {
    int buf = jt & 1;
    asm volatile("cp.async.wait_group 0;");
    __syncthreads();
    if (jt + 1 < jmax) load_kv(jt+1, buf^1);

    const __half* Kbuf = Ks + buf*8704;
    float acc[8][4];
    #pragma unroll
    for (int t=0;t<8;t++)
      #pragma unroll
      for (int r=0;r<4;r++) acc[t][r] = 0.f;

    #pragma unroll
    for (int ks=0; ks<8; ks++){
      unsigned ah[4], al[4];
      {
        unsigned qd = (unsigned)__cvta_generic_to_shared(
            Qs + (r0 + lr)*136 + ks*16 + lc);
        LDSM_X4(ah[0],ah[1],ah[2],ah[3], qd);
        LDSM_X4(al[0],al[1],al[2],al[3], qd + 34816);
      }
      unsigned bk[8][2];
      #pragma unroll
      for (int t16=0; t16<4; t16++){
        unsigned q0,q1,q2,q3;
        unsigned kd = (unsigned)__cvta_generic_to_shared(
            Kbuf + (t16*16 + lr)*136 + ks*16 + lc);
        LDSM_X4(q0,q1,q2,q3, kd);
        bk[2*t16  ][0] = q0; bk[2*t16  ][1] = q2;
        bk[2*t16+1][0] = q1; bk[2*t16+1][1] = q3;
      }
      #pragma unroll
      for (int t=0;t<8;t++){
        MMAF16(acc[t][0],acc[t][1],acc[t][2],acc[t][3],
               ah[0],ah[1],ah[2],ah[3], bk[t][0],bk[t][1]);
        MMAF16(acc[t][0],acc[t][1],acc[t][2],acc[t][3],
               al[0],al[1],al[2],al[3], bk[t][0],bk[t][1]);
      }
    }

    if (jt >= jmax-2) {
      int rg0 = qbase + r0 + g, rg1 = rg0 + 8;
      #pragma unroll
      for (int t=0;t<8;t++){
        int c0 = jt*64 + t*8 + 2*tig;
        if (c0   > rg0) acc[t][0] = -1e30f;
        if (c0+1 > rg0) acc[t][1] = -1e30f;
        if (c0   > rg1) acc[t][2] = -1e30f;
        if (c0+1 > rg1) acc[t][3] = -1e30f;
      }
    }

    float mx0=-1e30f, mx1=-1e30f;
    #pragma unroll
    for (int t=0;t<8;t++){
      mx0 = fmaxf(mx0, fmaxf(acc[t][0],acc[t][1]));
      mx1 = fmaxf(mx1, fmaxf(acc[t][2],acc[t][3]));
    }
    mx0 = fmaxf(mx0, __shfl_xor_sync(0xffffffffu, mx0, 1));
    mx0 = fmaxf(mx0, __shfl_xor_sync(0xffffffffu, mx0, 2));
    mx1 = fmaxf(mx1, __shfl_xor_sync(0xffffffffu, mx1, 1));
    mx1 = fmaxf(mx1, __shfl_xor_sync(0xffffffffu, mx1, 2));
    float nm0 = fmaxf(m0, mx0), nm1 = fmaxf(m1, mx1);
    float cf0 = exp2f(m0 - nm0), cf1 = exp2f(m1 - nm1);
    m0 = nm0; m1 = nm1;
    float s0 = 0.f, s1 = 0.f;
    #pragma unroll
    for (int t=0;t<8;t++){
      acc[t][0] = exp2f(acc[t][0]-nm0);
      acc[t][1] = exp2f(acc[t][1]-nm0);
      acc[t][2] = exp2f(acc[t][2]-nm1);
      acc[t][3] = exp2f(acc[t][3]-nm1);
      s0 += acc[t][0]+acc[t][1];
      s1 += acc[t][2]+acc[t][3];
    }
    s0 += __shfl_xor_sync(0xffffffffu, s0, 1);
    s0 += __shfl_xor_sync(0xffffffffu, s0, 2);
    s1 += __shfl_xor_sync(0xffffffffu, s1, 1);
    s1 += __shfl_xor_sync(0xffffffffu, s1, 2);
    l0 = l0*cf0 + s0;
    l1 = l1*cf1 + s1;
    #pragma unroll
    for (int nt=0;nt<16;nt++){
      o[nt][0] *= cf0; o[nt][1] *= cf0;
      o[nt][2] *= cf1; o[nt][3] *= cf1;
    }

    // ---- O += P @ V (single pass) ----
    const __half* Vbuf = Vs + buf*8704;
    int vrow = ((lane>>3)&1)*8 + (lane&7);
    int vcol = (lane>>4)*8;
    #pragma unroll
    for (int u=0;u<4;u++){
      unsigned ph[4];
      ph[0] = pack2h(acc[2*u  ][0], acc[2*u  ][1]);
      ph[1] = pack2h(acc[2*u  ][2], acc[2*u  ][3]);
      ph[2] = pack2h(acc[2*u+1][0], acc[2*u+1][1]);
      ph[3] = pack2h(acc[2*u+1][2], acc[2*u+1][3]);
      unsigned base = (unsigned)__cvta_generic_to_shared(
          Vbuf + (u*16 + vrow)*136 + vcol);
      #pragma unroll
      for (int dt=0;dt<8;dt++){
        unsigned v0,v1,v2,v3;
        LDSM_X4T(v0,v1,v2,v3, base + dt*32);
        MMAF16(o[dt*2  ][0],o[dt*2  ][1],o[dt*2  ][2],o[dt*2  ][3],
               ph[0],ph[1],ph[2],ph[3], v0,v1);
        MMAF16(o[dt*2+1][0],o[dt*2+1][1],o[dt*2+1][2],o[dt*2+1][3],
               ph[0],ph[1],ph[2],ph[3], v2,v3);
      }
    }
  }

  // ---- epilogue: normalize, single fp16 token-major output ----
  float i0 = 1.f/l0, i1 = 1.f/l1;
  int tok0 = b*Sn + qbase + r0 + g;
  __half* o0 = At + (size_t)tok0*1536 + h*128;
  __half* o1 = At + (size_t)(tok0+8)*1536 + h*128;
  #pragma unroll
  for (int nt=0;nt<16;nt++){
    int col = nt*8 + 2*tig;
    *(__half2*)(o0 + col) = __floats2half2_rn(o[nt][0]*i0, o[nt][1]*i0);
    *(__half2*)(o1 + col) = __floats2half2_rn(o[nt][2]*i1, o[nt][3]*i1);
  }
}

// ---------------- launch -----------------------------------------------------
extern "C" void kernel_launch(void* const* d_in, const int* in_sizes, int n_in,
                              void* d_out, int out_size) {
  (void)in_sizes; (void)n_in; (void)out_size;
  const float* hs   = (const float*)d_in[0];
  const float* rot  = (const float*)d_in[1];
  const float* Wkvd = (const float*)d_in[2];
  const float* Wqd  = (const float*)d_in[3];
  const float* Wku  = (const float*)d_in[4];
  const float* Wqu  = (const float*)d_in[5];
  const float* Wvu  = (const float*)d_in[6];
  const float* Wrk  = (const float*)d_in[7];
  const float* Wrq  = (const float*)d_in[8];
  const float* Wo   = (const float*)d_in[9];
  float* out = (float*)d_out;

  __half *hsA2,*wqkv,*wkv,*wq,*wrk,*wob,*dA1,*at1,*qb,*kb,*vb,*kcvf,*krb;
  float *qcqr;
  cudaGetSymbolAddress((void**)&hsA2, g_hsA2);
  cudaGetSymbolAddress((void**)&wqkv, g_Wqkv);
  cudaGetSymbolAddress((void**)&wkv , g_Wkv);
  cudaGetSymbolAddress((void**)&wq  , g_Wq);
  cudaGetSymbolAddress((void**)&wrk , g_Wrk);
  cudaGetSymbolAddress((void**)&wob , g_Wob);
  cudaGetSymbolAddress((void**)&dA1 , g_dA1);
  cudaGetSymbolAddress((void**)&kcvf, g_kcvf);
  cudaGetSymbolAddress((void**)&qcqr, g_qcqr);
  cudaGetSymbolAddress((void**)&krb , g_krb);
  cudaGetSymbolAddress((void**)&qb  , g_qb);
  cudaGetSymbolAddress((void**)&kb  , g_kb);
  cudaGetSymbolAddress((void**)&vb  , g_vb);
  cudaGetSymbolAddress((void**)&at1 , g_at1);

  // --- input conversions ---
  convA_kernel<<<(TOKn*1536/4)/256, 256>>>((const float4*)hs, hsA2);
  {
    ConvJobs J;
    const float* Ws[8] = {Wkvd, Wqd, Wku, Wvu, Wqu, Wrq, Wrk, Wo};
    __half* Bs[8] = {wqkv, wqkv + (size_t)192*1536, wkv,
                     wkv + (size_t)768*192, wq, wq + (size_t)768*192,
                     wrk, wob};
    int Ks[8]  = {1536,1536,192,192,192,192,1536,1536};
    int Nsz[8] = {192,192,768,1536,768,768,768,1536};
    int acc = 0;
    for (int j = 0; j < 8; j++) {
      J.W[j] = Ws[j]; J.Bt[j] = Bs[j];
      J.K[j] = Ks[j]; J.N[j] = Nsz[j];
      J.bstart[j] = acc;
      acc += (Nsz[j]/32)*(Ks[j]/32);
    }
    J.bstart[8] = acc;
    convW_kernel<<<acc, dim3(32,8)>>>(J);
  }

  // --- GEMM smem sizes per instantiation ---
  const int SM_64_2  = (128*40*2 +  64*40)*3*2;  // 76800
  const int SM_128_1 = (128*40   + 128*40)*3*2;  // 61440
  cudaFuncSetAttribute(hgemm_kernel<64,2,1>,
      cudaFuncAttributeMaxDynamicSharedMemorySize, SM_64_2);
  cudaFuncSetAttribute(hgemm_kernel<128,1,3>,
      cudaFuncAttributeMaxDynamicSharedMemorySize, SM_128_1);
  cudaFuncSetAttribute(hgemm_kernel<128,1,1>,
      cudaFuncAttributeMaxDynamicSharedMemorySize, SM_128_1);

  // --- qkvd: dA1 = hs @ [Wkvd|Wqd]  (2-pass A, single fp16 out) ---
  {
    GJobs J{};
    J.j[0] = {hsA2, hsA2+1536, wqkv, nullptr, dA1, 3072, 384, 1536, 1, 6};
    J.bstart[0] = 0; J.bstart[1] = 192;
    hgemm_kernel<64,2,1><<<192, 256, SM_64_2>>>(J);
  }
  // --- batched single-pass: krb | kcvf | qcqr (kcvf/krb -> fp16) ---
  {
    GJobs J{};
    J.j[0] = {hsA2,    nullptr, wrk, nullptr, krb,  3072,  768, 1536, 1,  6};
    J.j[1] = {dA1,     nullptr, wkv, nullptr, kcvf,  384, 2304,  192, 1, 18};
    J.j[2] = {dA1+192, nullptr, wq,  qcqr, nullptr,  384, 1536,  192, 0, 12};
    J.bstart[0] = 0; J.bstart[1] = 192; J.bstart[2] = 768; J.bstart[3] = 1152;
    hgemm_kernel<128,1,3><<<1152, 256, SM_128_1>>>(J);
  }

  // rope + layout (coalesced)
  assemble_kernel<<<dim3(Sn, Bn), 256>>>(qcqr, kcvf, krb, rot, qb, kb, vb);

  // flash attention (exp2 domain)
  cudaFuncSetAttribute(flash_kernel, cudaFuncAttributeMaxDynamicSharedMemorySize,
                       FLASH_SMEM);
  flash_kernel<<<dim3(16, Hn, Bn), 256, FLASH_SMEM>>>(qb, kb, vb, at1);

  // --- output projection: single-pass A ---
  {
    GJobs J{};
    J.j[0] = {at1, nullptr, wob, out, nullptr, 1536, 1536, 1536, 0, 12};
    J.bstart[0] = 0; J.bstart[1] = 384;
    hgemm_kernel<128,1,1><<<384, 256, SM_128_1>>>(J);
  }
}

// round 12
// speedup vs baseline: 7.3522x; 1.1360x over previous
#include <cuda_runtime.h>
#include <cuda_fp16.h>
#include <cstdint>
#include <stdint.h>
#include <math.h>

#define Bn   2
#define Sn   2048
#define HIDn 1536
#define Hn   12
#define HDn  128
#define TOKn (Bn*Sn)   // 4096

// ---------------- scratch (device globals; no allocations allowed) ----------
__device__ __half g_hsA2[(size_t)TOKn*3072];     // hidden split fp16 [row][hi1536|lo1536]
__device__ __half g_Wqkv[(size_t)384*1536];      // [n][k] single fp16
__device__ __half g_Wkv [(size_t)2304*192];
__device__ __half g_Wq  [(size_t)1536*192];
__device__ __half g_Wrk [(size_t)768*1536];
__device__ __half g_Wob [(size_t)1536*1536];
__device__ __half g_dA1 [(size_t)TOKn*384];      // [tok][kvd192|qd192] single fp16
__device__ __half g_kcvf[(size_t)TOKn*2304];     // fp16
__device__ __half g_qcqr[(size_t)TOKn*1536];     // fp16
__device__ __half g_krb [(size_t)TOKn*768];      // fp16
__device__ __half g_qb[(size_t)Bn*Hn*Sn*128];    // Q single fp16
__device__ __half g_kb[(size_t)Bn*Hn*Sn*128];    // K single
__device__ __half g_vb[(size_t)Bn*Hn*Sn*128];    // V single
__device__ __half g_at1[(size_t)TOKn*1536];      // attn out single fp16

// ---------------- helpers ----------------------------------------------------
__device__ __forceinline__ unsigned pack2h(float a, float b) {
  __half2 t = __floats2half2_rn(a, b);
  return *(unsigned*)&t;
}

#define MMAF16(d0,d1,d2,d3,a0,a1,a2,a3,b0,b1)                              \
  asm volatile("mma.sync.aligned.m16n8k16.row.col.f32.f16.f16.f32 "         \
    "{%0,%1,%2,%3},{%4,%5,%6,%7},{%8,%9},{%0,%1,%2,%3};"                    \
    : "+f"(d0),"+f"(d1),"+f"(d2),"+f"(d3)                                    \
    : "r"(a0),"r"(a1),"r"(a2),"r"(a3),"r"(b0),"r"(b1))
#define LDSM_X4(r0,r1,r2,r3,addr)                                           \
  asm volatile("ldmatrix.sync.aligned.m8n8.x4.shared.b16 "                  \
    "{%0,%1,%2,%3},[%4];"                                                   \
    : "=r"(r0),"=r"(r1),"=r"(r2),"=r"(r3) : "r"(addr))
#define LDSM_X4T(r0,r1,r2,r3,addr)                                          \
  asm volatile("ldmatrix.sync.aligned.m8n8.x4.trans.shared.b16 "            \
    "{%0,%1,%2,%3},[%4];"                                                   \
    : "=r"(r0),"=r"(r1),"=r"(r2),"=r"(r3) : "r"(addr))
#define CPASYNC16(dst, src)                                                 \
  asm volatile("cp.async.cg.shared.global [%0],[%1],16;" :: "r"(dst), "l"(src))

// ---------------- conversion kernels ----------------------------------------
__global__ __launch_bounds__(256)
void convA_kernel(const float4* __restrict__ X, __half* __restrict__ Y) {
  size_t i = (size_t)blockIdx.x*256 + threadIdx.x;
  float4 v = X[i];
  size_t e = i*4;
  size_t row = e / 1536, col = e % 1536;
  __half2 h0 = __floats2half2_rn(v.x, v.y);
  __half2 h1 = __floats2half2_rn(v.z, v.w);
  __half* hi = Y + row*3072 + col;
  *(__half2*)(hi)     = h0;
  *(__half2*)(hi + 2) = h1;
  float l0 = v.x - __half2float(__low2half(h0));
  float l1 = v.y - __half2float(__high2half(h0));
  float l2 = v.z - __half2float(__low2half(h1));
  float l3 = v.w - __half2float(__high2half(h1));
  __half* lo = hi + 1536;
  *(__half2*)(lo)     = __floats2half2_rn(l0, l1);
  *(__half2*)(lo + 2) = __floats2half2_rn(l2, l3);
}

struct ConvJobs {
  const float* W[8];
  __half* Bt[8];
  int K[8], N[8];
  int bstart[9];
};
__global__ __launch_bounds__(256)
void convW_kernel(ConvJobs J) {
  __shared__ float t[32][33];
  int bx = blockIdx.x;
  int j = 0;
  while (bx >= J.bstart[j+1]) j++;
  int lb = bx - J.bstart[j];
  int nbn = J.N[j] >> 5;
  int n0 = (lb % nbn) << 5, k0 = (lb / nbn) << 5;
  const float* W = J.W[j];
  __half* Bt = J.Bt[j];
  int K = J.K[j], N = J.N[j];
  #pragma unroll
  for (int i = threadIdx.y; i < 32; i += 8)
    t[i][threadIdx.x] = W[(size_t)(k0+i)*N + n0 + threadIdx.x];
  __syncthreads();
  #pragma unroll
  for (int i = threadIdx.y; i < 32; i += 8) {
    int n = n0 + i, k = k0 + threadIdx.x;
    Bt[(size_t)n*K + k] = __float2half(t[threadIdx.x][i]);
  }
}

// ---------------- fp16 tensor-core GEMM (batched jobs, 3-stage, BK=32) ------
struct GJob {
  const __half *Ahi, *Alo, *Bm;
  float* C; __half* Cb;
  int lda, N, K, outmode, nbx;
};
struct GJobs { GJob j[3]; int bstart[4]; };

template<int BN, int PASSES, int NJ>
__global__ __launch_bounds__(256)
void hgemm_kernel(GJobs JB) {
  constexpr int ASZ   = 128*40;
  constexpr int BOFF  = ASZ*PASSES;
  constexpr int STAGE = ASZ*PASSES + BN*40;
  constexpr int WN = BN/32, WM = 8/WN, MT = 128/(WM*16);

  extern __shared__ __half hsm[];
  int tid = threadIdx.x;
  int bid = blockIdx.x;
  int ji = 0;
  #pragma unroll
  for (int t = 1; t < NJ; t++) if (bid >= JB.bstart[t]) ji = t;
  GJob jb = JB.j[ji];
  int lb = bid - JB.bstart[ji];
  int bx = lb % jb.nbx, by = lb / jb.nbx;
  const __half* Ahi = jb.Ahi;
  const __half* Alo = jb.Alo;
  const __half* Bm  = jb.Bm;
  int lda = jb.lda, N = jb.N, K = jb.K;
  int KIT = K >> 5;

  auto load_st = [&](int it, int slot) {
    int kk = it << 5;
    __half* dst = hsm + slot*STAGE;
    #pragma unroll
    for (int p = 0; p < 2; p++) {
      int u = tid + (p << 8);
      int row = u >> 2, c = u & 3;
      int soff = row*40 + c*8;
      size_t ga = (size_t)(by*128 + row)*lda + kk + c*8;
      unsigned dh = (unsigned)__cvta_generic_to_shared(dst + soff);
      CPASYNC16(dh, Ahi + ga);
      if (PASSES == 2) {
        unsigned dl = (unsigned)__cvta_generic_to_shared(dst + ASZ + soff);
        CPASYNC16(dl, Alo + ga);
      }
    }
    #pragma unroll
    for (int p = 0; p < BN/64; p++) {
      int u = tid + (p << 8);
      int row = u >> 2, c = u & 3;
      const __half* sB = Bm + (size_t)(bx*BN + row)*K + kk + c*8;
      unsigned db = (unsigned)__cvta_generic_to_shared(dst + BOFF + row*40 + c*8);
      CPASYNC16(db, sB);
    }
    asm volatile("cp.async.commit_group;");
  };

  int wid = tid >> 5, lane = tid & 31;
  int wm = wid / WN, wn = wid % WN;
  int g = lane >> 2, tig = lane & 3;
  int lr = lane & 15, lc = (lane >> 4) << 3;

  float acc[MT][4][4];
  #pragma unroll
  for (int mt=0; mt<MT; mt++)
    #pragma unroll
    for (int nt=0; nt<4; nt++)
      #pragma unroll
      for (int r=0; r<4; r++) acc[mt][nt][r] = 0.f;

  load_st(0, 0);
  load_st(1, 1);

  for (int it = 0; it < KIT; ++it) {
    if (it + 1 < KIT) asm volatile("cp.async.wait_group 1;");
    else              asm volatile("cp.async.wait_group 0;");
    __syncthreads();
    if (it + 2 < KIT) load_st(it + 2, (it + 2) % 3);
    const __half* St = hsm + (it % 3)*STAGE;

    #pragma unroll
    for (int ks = 0; ks < 2; ks++) {
      unsigned b[4][2];
      #pragma unroll
      for (int bt = 0; bt < 2; bt++) {
        unsigned q0,q1,q2,q3;
        unsigned bd = (unsigned)__cvta_generic_to_shared(
            St + BOFF + (wn*32 + bt*16 + lr)*40 + ks*16 + lc);
        LDSM_X4(q0,q1,q2,q3, bd);
        b[2*bt  ][0] = q0; b[2*bt  ][1] = q2;
        b[2*bt+1][0] = q1; b[2*bt+1][1] = q3;
      }
      unsigned a[MT][4];
      #pragma unroll
      for (int mt = 0; mt < MT; mt++) {
        unsigned ad = (unsigned)__cvta_generic_to_shared(
            St + (wm*(MT*16) + mt*16 + lr)*40 + ks*16 + lc);
        LDSM_X4(a[mt][0], a[mt][1], a[mt][2], a[mt][3], ad);
      }
      #pragma unroll
      for (int mt = 0; mt < MT; mt++)
        #pragma unroll
        for (int nt = 0; nt < 4; nt++)
          MMAF16(acc[mt][nt][0],acc[mt][nt][1],acc[mt][nt][2],acc[mt][nt][3],
                 a[mt][0],a[mt][1],a[mt][2],a[mt][3],
                 b[nt][0],b[nt][1]);
      if (PASSES == 2) {
        #pragma unroll
        for (int mt = 0; mt < MT; mt++) {
          unsigned ad = (unsigned)__cvta_generic_to_shared(
              St + ASZ + (wm*(MT*16) + mt*16 + lr)*40 + ks*16 + lc);
          LDSM_X4(a[mt][0], a[mt][1], a[mt][2], a[mt][3], ad);
        }
        #pragma unroll
        for (int mt = 0; mt < MT; mt++)
          #pragma unroll
          for (int nt = 0; nt < 4; nt++)
            MMAF16(acc[mt][nt][0],acc[mt][nt][1],acc[mt][nt][2],acc[mt][nt][3],
                   a[mt][0],a[mt][1],a[mt][2],a[mt][3],
                   b[nt][0],b[nt][1]);
      }
    }
  }

  #pragma unroll
  for (int mt = 0; mt < MT; mt++) {
    #pragma unroll
    for (int nt = 0; nt < 4; nt++) {
      int row = by*128 + wm*(MT*16) + mt*16 + g;
      int col = bx*BN + wn*32 + nt*8 + 2*tig;
      if (jb.outmode == 0) {
        float2 v0 = make_float2(acc[mt][nt][0], acc[mt][nt][1]);
        float2 v1 = make_float2(acc[mt][nt][2], acc[mt][nt][3]);
        *(float2*)&jb.C[(size_t)row    *N + col] = v0;
        *(float2*)&jb.C[(size_t)(row+8)*N + col] = v1;
      } else {
        *(__half2*)&jb.Cb[(size_t)row    *N + col] =
            __floats2half2_rn(acc[mt][nt][0], acc[mt][nt][1]);
        *(__half2*)&jb.Cb[(size_t)(row+8)*N + col] =
            __floats2half2_rn(acc[mt][nt][2], acc[mt][nt][3]);
      }
    }
  }
}

// ---------------- assemble: RoPE + layout + scale (coalesced) ---------------
// grid (Sn, Bn), 256 threads; Q scale folds 1/sqrt(128) * log2(e) for exp2.
__global__ __launch_bounds__(256)
void assemble_kernel(const __half* __restrict__ qcqr, const __half* __restrict__ kcvf,
                     const __half* __restrict__ krb, const float* __restrict__ rot,
                     __half* __restrict__ Qh, __half* __restrict__ Kh,
                     __half* __restrict__ Vh) {
  int s = blockIdx.x, b = blockIdx.y;
  int tid = threadIdx.x;
  int token = b*Sn + s;
  const float* rrow = rot + (size_t)s*64;
  const float SCALE = 0.08838834764831845f * 1.4426950408889634f;

  #pragma unroll
  for (int it = 0; it < 6; it++) {
    int lin = it*256 + tid;          // 0..1535
    int h = lin >> 7, d = lin & 127;
    size_t bhs = (size_t)(b*Hn + h)*Sn + s;

    Vh[bhs*128 + d] = kcvf[(size_t)token*2304 + 768 + h*HDn + d];

    float qv, kv;
    if (d < 64) {
      qv = __half2float(qcqr[(size_t)token*1536 + h*64 + d]);
      kv = __half2float(kcvf[(size_t)token*2304 + h*64 + d]);
    } else {
      int i = d - 64;
      const __half* qrow = qcqr + (size_t)token*1536 + 768 + h*64;
      const __half* krow = krb + (size_t)token*768 + h*64;
      if (i < 32) {
        float sn = rrow[i], cs = rrow[32+i];
        qv = __half2float(qrow[i])*cs - __half2float(qrow[i+32])*sn;
        kv = __half2float(krow[i])*cs - __half2float(krow[i+32])*sn;
      } else {
        int ii = i - 32;
        float sn = rrow[ii], cs = rrow[32+ii];
        qv = __half2float(qrow[ii])*sn + __half2float(qrow[ii+32])*cs;
        kv = __half2float(krow[ii])*sn + __half2float(krow[ii+32])*cs;
      }
    }
    Qh[bhs*128 + d] = __float2half(qv * SCALE);
    Kh[bhs*128 + d] = __float2half(kv);
  }
}

// ---------------- causal flash attention (QK 1-pass, PV 1-pass, exp2) -------
// smem: Q[128][136] + K[2][64][136] + V[2][64][136] = 104448 B -> 2 CTAs/SM
#define FLASH_SMEM 104448

__global__ __launch_bounds__(256, 2)
void flash_kernel(const __half* __restrict__ Qg,
                  const __half* __restrict__ Kg,
                  const __half* __restrict__ Vg,
                  __half* __restrict__ At) {
  extern __shared__ __half fsm[];
  __half* Qs = fsm;              // [128][136]
  __half* Ks = fsm + 17408;      // [2 buf][64][136]
  __half* Vs = fsm + 34816;      // [2 buf][64][136]

  int qi = 15 - (int)blockIdx.x;
  int h = blockIdx.y, b = blockIdx.z;
  int bh = b*Hn + h;
  int qbase = qi*128;
  const __half* Qb = Qg + ((size_t)bh*Sn + qbase)*128;
  const __half* Kb = Kg + (size_t)bh*Sn*128;
  const __half* Vb = Vg + (size_t)bh*Sn*128;

  int tid = threadIdx.x;
  int wid = tid>>5, lane = tid&31, g = lane>>2, tig = lane&3;
  int lr = lane & 15, lc = (lane >> 4) << 3;
  int jmax = 2*qi + 2;
  int r0 = wid*16;

  // Q load (joins first commit group)
  #pragma unroll
  for (int p=0;p<8;p++){
    int lin = tid + p*256;
    int row = lin>>4, c = lin&15;
    const __half* src = Qb + (size_t)row*128 + c*8;
    unsigned d = (unsigned)__cvta_generic_to_shared(Qs + row*136 + c*8);
    CPASYNC16(d, src);
  }
  auto load_kv = [&](int jt, int buf){
    #pragma unroll
    for (int p=0;p<4;p++){
      int lin = tid + p*256;
      int row = lin>>4, c = lin&15;
      size_t s_off = (size_t)(jt*64 + row)*128 + c*8;
      int doff = buf*8704 + row*136 + c*8;
      unsigned dk = (unsigned)__cvta_generic_to_shared(Ks + doff);
      CPASYNC16(dk, Kb + s_off);
      unsigned dv = (unsigned)__cvta_generic_to_shared(Vs + doff);
      CPASYNC16(dv, Vb + s_off);
    }
    asm volatile("cp.async.commit_group;");
  };
  load_kv(0, 0);

  float o[16][4];
  #pragma unroll
  for (int nt=0;nt<16;nt++)
    #pragma unroll
    for (int r=0;r<4;r++) o[nt][r] = 0.f;
  float m0=-1e30f, m1=-1e30f, l0=0.f, l1=0.f;

  for (int jt = 0; jt < jmax; jt++) {
    int buf = jt & 1;
    asm volatile("cp.async.wait_group 0;");
    __syncthreads();
    if (jt + 1 < jmax) load_kv(jt+1, buf^1);

    // ---- S = Q @ K^T (single pass) ----
    const __half* Kbuf = Ks + buf*8704;
    float acc[8][4];
    #pragma unroll
    for (int t=0;t<8;t++)
      #pragma unroll
      for (int r=0;r<4;r++) acc[t][r] = 0.f;

    #pragma unroll
    for (int ks=0; ks<8; ks++){
      unsigned ah[4];
      {
        unsigned qd = (unsigned)__cvta_generic_to_shared(
            Qs + (r0 + lr)*136 + ks*16 + lc);
        LDSM_X4(ah[0],ah[1],ah[2],ah[3], qd);
      }
      unsigned bk[8][2];
      #pragma unroll
      for (int t16=0; t16<4; t16++){
        unsigned q0,q1,q2,q3;
        unsigned kd = (unsigned)__cvta_generic_to_shared(
            Kbuf + (t16*16 + lr)*136 + ks*16 + lc);
        LDSM_X4(q0,q1,q2,q3, kd);
        bk[2*t16  ][0] = q0; bk[2*t16  ][1] = q2;
        bk[2*t16+1][0] = q1; bk[2*t16+1][1] = q3;
      }
      #pragma unroll
      for (int t=0;t<8;t++)
        MMAF16(acc[t][0],acc[t][1],acc[t][2],acc[t][3],
               ah[0],ah[1],ah[2],ah[3], bk[t][0],bk[t][1]);
    }

    if (jt >= jmax-2) {
      int rg0 = qbase + r0 + g, rg1 = rg0 + 8;
      #pragma unroll
      for (int t=0;t<8;t++){
        int c0 = jt*64 + t*8 + 2*tig;
        if (c0   > rg0) acc[t][0] = -1e30f;
        if (c0+1 > rg0) acc[t][1] = -1e30f;
        if (c0   > rg1) acc[t][2] = -1e30f;
        if (c0+1 > rg1) acc[t][3] = -1e30f;
      }
    }

    float mx0=-1e30f, mx1=-1e30f;
    #pragma unroll
    for (int t=0;t<8;t++){
      mx0 = fmaxf(mx0, fmaxf(acc[t][0],acc[t][1]));
      mx1 = fmaxf(mx1, fmaxf(acc[t][2],acc[t][3]));
    }
    mx0 = fmaxf(mx0, __shfl_xor_sync(0xffffffffu, mx0, 1));
    mx0 = fmaxf(mx0, __shfl_xor_sync(0xffffffffu, mx0, 2));
    mx1 = fmaxf(mx1, __shfl_xor_sync(0xffffffffu, mx1, 1));
    mx1 = fmaxf(mx1, __shfl_xor_sync(0xffffffffu, mx1, 2));
    float nm0 = fmaxf(m0, mx0), nm1 = fmaxf(m1, mx1);
    float cf0 = exp2f(m0 - nm0), cf1 = exp2f(m1 - nm1);
    m0 = nm0; m1 = nm1;
    float s0 = 0.f, s1 = 0.f;
    #pragma unroll
    for (int t=0;t<8;t++){
      acc[t][0] = exp2f(acc[t][0]-nm0);
      acc[t][1] = exp2f(acc[t][1]-nm0);
      acc[t][2] = exp2f(acc[t][2]-nm1);
      acc[t][3] = exp2f(acc[t][3]-nm1);
      s0 += acc[t][0]+acc[t][1];
      s1 += acc[t][2]+acc[t][3];
    }
    s0 += __shfl_xor_sync(0xffffffffu, s0, 1);
    s0 += __shfl_xor_sync(0xffffffffu, s0, 2);
    s1 += __shfl_xor_sync(0xffffffffu, s1, 1);
    s1 += __shfl_xor_sync(0xffffffffu, s1, 2);
    l0 = l0*cf0 + s0;
    l1 = l1*cf1 + s1;
    #pragma unroll
    for (int nt=0;nt<16;nt++){
      o[nt][0] *= cf0; o[nt][1] *= cf0;
      o[nt][2] *= cf1; o[nt][3] *= cf1;
    }

    // ---- O += P @ V (single pass) ----
    const __half* Vbuf = Vs + buf*8704;
    int vrow = ((lane>>3)&1)*8 + (lane&7);
    int vcol = (lane>>4)*8;
    #pragma unroll
    for (int u=0;u<4;u++){
      unsigned ph[4];
      ph[0] = pack2h(acc[2*u  ][0], acc[2*u  ][1]);
      ph[1] = pack2h(acc[2*u  ][2], acc[2*u  ][3]);
      ph[2] = pack2h(acc[2*u+1][0], acc[2*u+1][1]);
      ph[3] = pack2h(acc[2*u+1][2], acc[2*u+1][3]);
      unsigned base = (unsigned)__cvta_generic_to_shared(
          Vbuf + (u*16 + vrow)*136 + vcol);
      #pragma unroll
      for (int dt=0;dt<8;dt++){
        unsigned v0,v1,v2,v3;
        LDSM_X4T(v0,v1,v2,v3, base + dt*32);
        MMAF16(o[dt*2  ][0],o[dt*2  ][1],o[dt*2  ][2],o[dt*2  ][3],
               ph[0],ph[1],ph[2],ph[3], v0,v1);
        MMAF16(o[dt*2+1][0],o[dt*2+1][1],o[dt*2+1][2],o[dt*2+1][3],
               ph[0],ph[1],ph[2],ph[3], v2,v3);
      }
    }
  }

  // ---- epilogue: normalize, single fp16 token-major output ----
  float i0 = 1.f/l0, i1 = 1.f/l1;
  int tok0 = b*Sn + qbase + r0 + g;
  __half* o0 = At + (size_t)tok0*1536 + h*128;
  __half* o1 = At + (size_t)(tok0+8)*1536 + h*128;
  #pragma unroll
  for (int nt=0;nt<16;nt++){
    int col = nt*8 + 2*tig;
    *(__half2*)(o0 + col) = __floats2half2_rn(o[nt][0]*i0, o[nt][1]*i0);
    *(__half2*)(o1 + col) = __floats2half2_rn(o[nt][2]*i1, o[nt][3]*i1);
  }
}

// ---------------- launch -----------------------------------------------------
extern "C" void kernel_launch(void* const* d_in, const int* in_sizes, int n_in,
                              void* d_out, int out_size) {
  (void)in_sizes; (void)n_in; (void)out_size;
  const float* hs   = (const float*)d_in[0];
  const float* rot  = (const float*)d_in[1];
  const float* Wkvd = (const float*)d_in[2];
  const float* Wqd  = (const float*)d_in[3];
  const float* Wku  = (const float*)d_in[4];
  const float* Wqu  = (const float*)d_in[5];
  const float* Wvu  = (const float*)d_in[6];
  const float* Wrk  = (const float*)d_in[7];
  const float* Wrq  = (const float*)d_in[8];
  const float* Wo   = (const float*)d_in[9];
  float* out = (float*)d_out;

  __half *hsA2,*wqkv,*wkv,*wq,*wrk,*wob,*dA1,*at1,*qb,*kb,*vb,*kcvf,*krb,*qcqr;
  cudaGetSymbolAddress((void**)&hsA2, g_hsA2);
  cudaGetSymbolAddress((void**)&wqkv, g_Wqkv);
  cudaGetSymbolAddress((void**)&wkv , g_Wkv);
  cudaGetSymbolAddress((void**)&wq  , g_Wq);
  cudaGetSymbolAddress((void**)&wrk , g_Wrk);
  cudaGetSymbolAddress((void**)&wob , g_Wob);
  cudaGetSymbolAddress((void**)&dA1 , g_dA1);
  cudaGetSymbolAddress((void**)&kcvf, g_kcvf);
  cudaGetSymbolAddress((void**)&qcqr, g_qcqr);
  cudaGetSymbolAddress((void**)&krb , g_krb);
  cudaGetSymbolAddress((void**)&qb  , g_qb);
  cudaGetSymbolAddress((void**)&kb  , g_kb);
  cudaGetSymbolAddress((void**)&vb  , g_vb);
  cudaGetSymbolAddress((void**)&at1 , g_at1);

  // --- input conversions ---
  convA_kernel<<<(TOKn*1536/4)/256, 256>>>((const float4*)hs, hsA2);
  {
    ConvJobs J;
    const float* Ws[8] = {Wkvd, Wqd, Wku, Wvu, Wqu, Wrq, Wrk, Wo};
    __half* Bs[8] = {wqkv, wqkv + (size_t)192*1536, wkv,
                     wkv + (size_t)768*192, wq, wq + (size_t)768*192,
                     wrk, wob};
    int Ks[8]  = {1536,1536,192,192,192,192,1536,1536};
    int Nsz[8] = {192,192,768,1536,768,768,768,1536};
    int acc = 0;
    for (int j = 0; j < 8; j++) {
      J.W[j] = Ws[j]; J.Bt[j] = Bs[j];
      J.K[j] = Ks[j]; J.N[j] = Nsz[j];
      J.bstart[j] = acc;
      acc += (Nsz[j]/32)*(Ks[j]/32);
    }
    J.bstart[8] = acc;
    convW_kernel<<<acc, dim3(32,8)>>>(J);
  }

  // --- GEMM smem sizes per instantiation ---
  const int SM_64_2  = (128*40*2 +  64*40)*3*2;  // 76800
  const int SM_128_1 = (128*40   + 128*40)*3*2;  // 61440
  cudaFuncSetAttribute(hgemm_kernel<64,2,1>,
      cudaFuncAttributeMaxDynamicSharedMemorySize, SM_64_2);
  cudaFuncSetAttribute(hgemm_kernel<128,1,3>,
      cudaFuncAttributeMaxDynamicSharedMemorySize, SM_128_1);
  cudaFuncSetAttribute(hgemm_kernel<128,1,1>,
      cudaFuncAttributeMaxDynamicSharedMemorySize, SM_128_1);

  // --- qkvd: dA1 = hs @ [Wkvd|Wqd]  (2-pass A, single fp16 out) ---
  {
    GJobs J{};
    J.j[0] = {hsA2, hsA2+1536, wqkv, nullptr, dA1, 3072, 384, 1536, 1, 6};
    J.bstart[0] = 0; J.bstart[1] = 192;
    hgemm_kernel<64,2,1><<<192, 256, SM_64_2>>>(J);
  }
  // --- batched single-pass: krb | kcvf | qcqr (all fp16 out) ---
  {
    GJobs J{};
    J.j[0] = {hsA2,    nullptr, wrk, nullptr, krb,  3072,  768, 1536, 1,  6};
    J.j[1] = {dA1,     nullptr, wkv, nullptr, kcvf,  384, 2304,  192, 1, 18};
    J.j[2] = {dA1+192, nullptr, wq,  nullptr, qcqr,  384, 1536,  192, 1, 12};
    J.bstart[0] = 0; J.bstart[1] = 192; J.bstart[2] = 768; J.bstart[3] = 1152;
    hgemm_kernel<128,1,3><<<1152, 256, SM_128_1>>>(J);
  }

  // rope + layout (coalesced)
  assemble_kernel<<<dim3(Sn, Bn), 256>>>(qcqr, kcvf, krb, rot, qb, kb, vb);

  // flash attention (single-pass QK/PV, 2 CTAs/SM)
  cudaFuncSetAttribute(flash_kernel, cudaFuncAttributeMaxDynamicSharedMemorySize,
                       FLASH_SMEM);
  flash_kernel<<<dim3(16, Hn, Bn), 256, FLASH_SMEM>>>(qb, kb, vb, at1);

  // --- output projection: single-pass A ---
  {
    GJobs J{};
    J.j[0] = {at1, nullptr, wob, out, nullptr, 1536, 1536, 1536, 0, 12};
    J.bstart[0] = 0; J.bstart[1] = 384;
    hgemm_kernel<128,1,1><<<384, 256, SM_128_1>>>(J);
  }
}

// round 13
// speedup vs baseline: 8.3102x; 1.1303x over previous
#include <cuda_runtime.h>
#include <cuda_fp16.h>
#include <cstdint>
#include <stdint.h>
#include <math.h>

#define Bn   2
#define Sn   2048
#define HIDn 1536
#define Hn   12
#define HDn  128
#define TOKn (Bn*Sn)   // 4096

// ---------------- scratch (device globals; no allocations allowed) ----------
__device__ __half g_hs16[(size_t)TOKn*1536];     // hidden single fp16
__device__ __half g_Wqkv[(size_t)384*1536];      // [n][k] single fp16
__device__ __half g_Wkv [(size_t)2304*192];
__device__ __half g_Wq  [(size_t)1536*192];
__device__ __half g_Wrk [(size_t)768*1536];
__device__ __half g_Wob [(size_t)1536*1536];
__device__ __half g_dA1 [(size_t)TOKn*384];      // [tok][kvd192|qd192] single fp16
__device__ __half g_kcvf[(size_t)TOKn*2304];     // fp16
__device__ __half g_qcqr[(size_t)TOKn*1536];     // fp16
__device__ __half g_krb [(size_t)TOKn*768];      // fp16
__device__ __half g_qb[(size_t)Bn*Hn*Sn*128];    // Q single fp16 (scaled)
__device__ __half g_kb[(size_t)Bn*Hn*Sn*128];    // K single
__device__ __half g_vb[(size_t)Bn*Hn*Sn*128];    // V single
__device__ __half g_at1[(size_t)TOKn*1536];      // attn out single fp16

// ---------------- helpers ----------------------------------------------------
__device__ __forceinline__ unsigned pack2h(float a, float b) {
  __half2 t = __floats2half2_rn(a, b);
  return *(unsigned*)&t;
}

#define MMAF16(d0,d1,d2,d3,a0,a1,a2,a3,b0,b1)                              \
  asm volatile("mma.sync.aligned.m16n8k16.row.col.f32.f16.f16.f32 "         \
    "{%0,%1,%2,%3},{%4,%5,%6,%7},{%8,%9},{%0,%1,%2,%3};"                    \
    : "+f"(d0),"+f"(d1),"+f"(d2),"+f"(d3)                                    \
    : "r"(a0),"r"(a1),"r"(a2),"r"(a3),"r"(b0),"r"(b1))
#define LDSM_X4(r0,r1,r2,r3,addr)                                           \
  asm volatile("ldmatrix.sync.aligned.m8n8.x4.shared.b16 "                  \
    "{%0,%1,%2,%3},[%4];"                                                   \
    : "=r"(r0),"=r"(r1),"=r"(r2),"=r"(r3) : "r"(addr))
#define LDSM_X4T(r0,r1,r2,r3,addr)                                          \
  asm volatile("ldmatrix.sync.aligned.m8n8.x4.trans.shared.b16 "            \
    "{%0,%1,%2,%3},[%4];"                                                   \
    : "=r"(r0),"=r"(r1),"=r"(r2),"=r"(r3) : "r"(addr))
#define CPASYNC16(dst, src)                                                 \
  asm volatile("cp.async.cg.shared.global [%0],[%1],16;" :: "r"(dst), "l"(src))

// ---------------- conversion kernels ----------------------------------------
__global__ __launch_bounds__(256)
void convA_kernel(const float4* __restrict__ X, __half* __restrict__ Y) {
  size_t i = (size_t)blockIdx.x*256 + threadIdx.x;
  float4 v = X[i];
  __half2 h0 = __floats2half2_rn(v.x, v.y);
  __half2 h1 = __floats2half2_rn(v.z, v.w);
  *(__half2*)(Y + i*4)     = h0;
  *(__half2*)(Y + i*4 + 2) = h1;
}

struct ConvJobs {
  const float* W[8];
  __half* Bt[8];
  int K[8], N[8];
  int bstart[9];
};
__global__ __launch_bounds__(256)
void convW_kernel(ConvJobs J) {
  __shared__ float t[32][33];
  int bx = blockIdx.x;
  int j = 0;
  while (bx >= J.bstart[j+1]) j++;
  int lb = bx - J.bstart[j];
  int nbn = J.N[j] >> 5;
  int n0 = (lb % nbn) << 5, k0 = (lb / nbn) << 5;
  const float* W = J.W[j];
  __half* Bt = J.Bt[j];
  int K = J.K[j], N = J.N[j];
  #pragma unroll
  for (int i = threadIdx.y; i < 32; i += 8)
    t[i][threadIdx.x] = W[(size_t)(k0+i)*N + n0 + threadIdx.x];
  __syncthreads();
  #pragma unroll
  for (int i = threadIdx.y; i < 32; i += 8) {
    int n = n0 + i, k = k0 + threadIdx.x;
    Bt[(size_t)n*K + k] = __float2half(t[threadIdx.x][i]);
  }
}

// ---------------- fp16 tensor-core GEMM (batched, 3-stage, BK=64) -----------
// C[M][N] = A16 @ B16^T.  BM=128, BN in {64,128}, 256 threads (8 warps).
// outmode 0: fp32 C.  outmode 1: fp16 Cb [row][N].
struct GJob {
  const __half *Am, *Bm;
  float* C; __half* Cb;
  int lda, N, K, outmode, nbx;
};
struct GJobs { GJob j[3]; int bstart[4]; };

template<int BN, int NJ>
__global__ __launch_bounds__(256)
void hgemm_kernel(GJobs JB) {
  constexpr int BOFF  = 128*72;           // B offset in stage (halves)
  constexpr int STAGE = (128 + BN)*72;    // halves per stage
  constexpr int WN = BN/32, WM = 8/WN, MT = 128/(WM*16);

  extern __shared__ __half hsm[];
  int tid = threadIdx.x;
  int bid = blockIdx.x;
  int ji = 0;
  #pragma unroll
  for (int t = 1; t < NJ; t++) if (bid >= JB.bstart[t]) ji = t;
  GJob jb = JB.j[ji];
  int lb = bid - JB.bstart[ji];
  int bx = lb % jb.nbx, by = lb / jb.nbx;
  const __half* Am = jb.Am;
  const __half* Bm = jb.Bm;
  int lda = jb.lda, N = jb.N, K = jb.K;
  int KIT = K >> 6;

  auto load_st = [&](int it, int slot) {
    int kk = it << 6;
    __half* dst = hsm + slot*STAGE;
    #pragma unroll
    for (int p = 0; p < 4; p++) {
      int u = tid + (p << 8);
      int row = u >> 3, c = u & 7;
      size_t ga = (size_t)(by*128 + row)*lda + kk + c*8;
      unsigned dh = (unsigned)__cvta_generic_to_shared(dst + row*72 + c*8);
      CPASYNC16(dh, Am + ga);
    }
    #pragma unroll
    for (int p = 0; p < BN/32; p++) {
      int u = tid + (p << 8);
      int row = u >> 3, c = u & 7;
      const __half* sB = Bm + (size_t)(bx*BN + row)*K + kk + c*8;
      unsigned db = (unsigned)__cvta_generic_to_shared(dst + BOFF + row*72 + c*8);
      CPASYNC16(db, sB);
    }
    asm volatile("cp.async.commit_group;");
  };

  int wid = tid >> 5, lane = tid & 31;
  int wm = wid / WN, wn = wid % WN;
  int g = lane >> 2, tig = lane & 3;
  int lr = lane & 15, lc = (lane >> 4) << 3;

  float acc[MT][4][4];
  #pragma unroll
  for (int mt=0; mt<MT; mt++)
    #pragma unroll
    for (int nt=0; nt<4; nt++)
      #pragma unroll
      for (int r=0; r<4; r++) acc[mt][nt][r] = 0.f;

  load_st(0, 0);
  load_st(1, 1);

  for (int it = 0; it < KIT; ++it) {
    if (it + 1 < KIT) asm volatile("cp.async.wait_group 1;");
    else              asm volatile("cp.async.wait_group 0;");
    __syncthreads();
    if (it + 2 < KIT) load_st(it + 2, (it + 2) % 3);
    const __half* St = hsm + (it % 3)*STAGE;

    #pragma unroll
    for (int ks = 0; ks < 4; ks++) {
      unsigned b[4][2];
      #pragma unroll
      for (int bt = 0; bt < 2; bt++) {
        unsigned q0,q1,q2,q3;
        unsigned bd = (unsigned)__cvta_generic_to_shared(
            St + BOFF + (wn*32 + bt*16 + lr)*72 + ks*16 + lc);
        LDSM_X4(q0,q1,q2,q3, bd);
        b[2*bt  ][0] = q0; b[2*bt  ][1] = q2;
        b[2*bt+1][0] = q1; b[2*bt+1][1] = q3;
      }
      unsigned a[MT][4];
      #pragma unroll
      for (int mt = 0; mt < MT; mt++) {
        unsigned ad = (unsigned)__cvta_generic_to_shared(
            St + (wm*(MT*16) + mt*16 + lr)*72 + ks*16 + lc);
        LDSM_X4(a[mt][0], a[mt][1], a[mt][2], a[mt][3], ad);
      }
      #pragma unroll
      for (int mt = 0; mt < MT; mt++)
        #pragma unroll
        for (int nt = 0; nt < 4; nt++)
          MMAF16(acc[mt][nt][0],acc[mt][nt][1],acc[mt][nt][2],acc[mt][nt][3],
                 a[mt][0],a[mt][1],a[mt][2],a[mt][3],
                 b[nt][0],b[nt][1]);
    }
  }

  #pragma unroll
  for (int mt = 0; mt < MT; mt++) {
    #pragma unroll
    for (int nt = 0; nt < 4; nt++) {
      int row = by*128 + wm*(MT*16) + mt*16 + g;
      int col = bx*BN + wn*32 + nt*8 + 2*tig;
      if (jb.outmode == 0) {
        float2 v0 = make_float2(acc[mt][nt][0], acc[mt][nt][1]);
        float2 v1 = make_float2(acc[mt][nt][2], acc[mt][nt][3]);
        *(float2*)&jb.C[(size_t)row    *N + col] = v0;
        *(float2*)&jb.C[(size_t)(row+8)*N + col] = v1;
      } else {
        *(__half2*)&jb.Cb[(size_t)row    *N + col] =
            __floats2half2_rn(acc[mt][nt][0], acc[mt][nt][1]);
        *(__half2*)&jb.Cb[(size_t)(row+8)*N + col] =
            __floats2half2_rn(acc[mt][nt][2], acc[mt][nt][3]);
      }
    }
  }
}

// ---------------- assemble: RoPE + layout + scale (coalesced) ---------------
__global__ __launch_bounds__(256)
void assemble_kernel(const __half* __restrict__ qcqr, const __half* __restrict__ kcvf,
                     const __half* __restrict__ krb, const float* __restrict__ rot,
                     __half* __restrict__ Qh, __half* __restrict__ Kh,
                     __half* __restrict__ Vh) {
  int s = blockIdx.x, b = blockIdx.y;
  int tid = threadIdx.x;
  int token = b*Sn + s;
  const float* rrow = rot + (size_t)s*64;
  const float SCALE = 0.08838834764831845f * 1.4426950408889634f;

  #pragma unroll
  for (int it = 0; it < 6; it++) {
    int lin = it*256 + tid;          // 0..1535
    int h = lin >> 7, d = lin & 127;
    size_t bhs = (size_t)(b*Hn + h)*Sn + s;

    Vh[bhs*128 + d] = kcvf[(size_t)token*2304 + 768 + h*HDn + d];

    float qv, kv;
    if (d < 64) {
      qv = __half2float(qcqr[(size_t)token*1536 + h*64 + d]);
      kv = __half2float(kcvf[(size_t)token*2304 + h*64 + d]);
    } else {
      int i = d - 64;
      const __half* qrow = qcqr + (size_t)token*1536 + 768 + h*64;
      const __half* krow = krb + (size_t)token*768 + h*64;
      if (i < 32) {
        float sn = rrow[i], cs = rrow[32+i];
        qv = __half2float(qrow[i])*cs - __half2float(qrow[i+32])*sn;
        kv = __half2float(krow[i])*cs - __half2float(krow[i+32])*sn;
      } else {
        int ii = i - 32;
        float sn = rrow[ii], cs = rrow[32+ii];
        qv = __half2float(qrow[ii])*sn + __half2float(qrow[ii+32])*cs;
        kv = __half2float(krow[ii])*sn + __half2float(krow[ii+32])*cs;
      }
    }
    Qh[bhs*128 + d] = __float2half(qv * SCALE);
    Kh[bhs*128 + d] = __float2half(kv);
  }
}

// ---------------- causal flash attention (QK 1-pass, PV 1-pass, exp2) -------
// smem: Q[128][136] + K[2][64][136] + V[2][64][136] = 104448 B -> 2 CTAs/SM
#define FLASH_SMEM 104448

__global__ __launch_bounds__(256, 2)
void flash_kernel(const __half* __restrict__ Qg,
                  const __half* __restrict__ Kg,
                  const __half* __restrict__ Vg,
                  __half* __restrict__ At) {
  extern __shared__ __half fsm[];
  __half* Qs = fsm;              // [128][136]
  __half* Ks = fsm + 17408;      // [2 buf][64][136]
  __half* Vs = fsm + 34816;      // [2 buf][64][136]

  int qi = 15 - (int)blockIdx.x;
  int h = blockIdx.y, b = blockIdx.z;
  int bh = b*Hn + h;
  int qbase = qi*128;
  const __half* Qb = Qg + ((size_t)bh*Sn + qbase)*128;
  const __half* Kb = Kg + (size_t)bh*Sn*128;
  const __half* Vb = Vg + (size_t)bh*Sn*128;

  int tid = threadIdx.x;
  int wid = tid>>5, lane = tid&31, g = lane>>2, tig = lane&3;
  int lr = lane & 15, lc = (lane >> 4) << 3;
  int jmax = 2*qi + 2;
  int r0 = wid*16;

  #pragma unroll
  for (int p=0;p<8;p++){
    int lin = tid + p*256;
    int row = lin>>4, c = lin&15;
    const __half* src = Qb + (size_t)row*128 + c*8;
    unsigned d = (unsigned)__cvta_generic_to_shared(Qs + row*136 + c*8);
    CPASYNC16(d, src);
  }
  auto load_kv = [&](int jt, int buf){
    #pragma unroll
    for (int p=0;p<4;p++){
      int lin = tid + p*256;
      int row = lin>>4, c = lin&15;
      size_t s_off = (size_t)(jt*64 + row)*128 + c*8;
      int doff = buf*8704 + row*136 + c*8;
      unsigned dk = (unsigned)__cvta_generic_to_shared(Ks + doff);
      CPASYNC16(dk, Kb + s_off);
      unsigned dv = (unsigned)__cvta_generic_to_shared(Vs + doff);
      CPASYNC16(dv, Vb + s_off);
    }
    asm volatile("cp.async.commit_group;");
  };
  load_kv(0, 0);

  float o[16][4];
  #pragma unroll
  for (int nt=0;nt<16;nt++)
    #pragma unroll
    for (int r=0;r<4;r++) o[nt][r] = 0.f;
  float m0=-1e30f, m1=-1e30f, l0=0.f, l1=0.f;

  for (int jt = 0; jt < jmax; jt++) {
    int buf = jt & 1;
    asm volatile("cp.async.wait_group 0;");
    __syncthreads();
    if (jt + 1 < jmax) load_kv(jt+1, buf^1);

    const __half* Kbuf = Ks + buf*8704;
    float acc[8][4];
    #pragma unroll
    for (int t=0;t<8;t++)
      #pragma unroll
      for (int r=0;r<4;r++) acc[t][r] = 0.f;

    #pragma unroll
    for (int ks=0; ks<8; ks++){
      unsigned ah[4];
      {
        unsigned qd = (unsigned)__cvta_generic_to_shared(
            Qs + (r0 + lr)*136 + ks*16 + lc);
        LDSM_X4(ah[0],ah[1],ah[2],ah[3], qd);
      }
      unsigned bk[8][2];
      #pragma unroll
      for (int t16=0; t16<4; t16++){
        unsigned q0,q1,q2,q3;
        unsigned kd = (unsigned)__cvta_generic_to_shared(
            Kbuf + (t16*16 + lr)*136 + ks*16 + lc);
        LDSM_X4(q0,q1,q2,q3, kd);
        bk[2*t16  ][0] = q0; bk[2*t16  ][1] = q2;
        bk[2*t16+1][0] = q1; bk[2*t16+1][1] = q3;
      }
      #pragma unroll
      for (int t=0;t<8;t++)
        MMAF16(acc[t][0],acc[t][1],acc[t][2],acc[t][3],
               ah[0],ah[1],ah[2],ah[3], bk[t][0],bk[t][1]);
    }

    if (jt >= jmax-2) {
      int rg0 = qbase + r0 + g, rg1 = rg0 + 8;
      #pragma unroll
      for (int t=0;t<8;t++){
        int c0 = jt*64 + t*8 + 2*tig;
        if (c0   > rg0) acc[t][0] = -1e30f;
        if (c0+1 > rg0) acc[t][1] = -1e30f;
        if (c0   > rg1) acc[t][2] = -1e30f;
        if (c0+1 > rg1) acc[t][3] = -1e30f;
      }
    }

    float mx0=-1e30f, mx1=-1e30f;
    #pragma unroll
    for (int t=0;t<8;t++){
      mx0 = fmaxf(mx0, fmaxf(acc[t][0],acc[t][1]));
      mx1 = fmaxf(mx1, fmaxf(acc[t][2],acc[t][3]));
    }
    mx0 = fmaxf(mx0, __shfl_xor_sync(0xffffffffu, mx0, 1));
    mx0 = fmaxf(mx0, __shfl_xor_sync(0xffffffffu, mx0, 2));
    mx1 = fmaxf(mx1, __shfl_xor_sync(0xffffffffu, mx1, 1));
    mx1 = fmaxf(mx1, __shfl_xor_sync(0xffffffffu, mx1, 2));
    float nm0 = fmaxf(m0, mx0), nm1 = fmaxf(m1, mx1);
    float cf0 = exp2f(m0 - nm0), cf1 = exp2f(m1 - nm1);
    m0 = nm0; m1 = nm1;
    float s0 = 0.f, s1 = 0.f;
    #pragma unroll
    for (int t=0;t<8;t++){
      acc[t][0] = exp2f(acc[t][0]-nm0);
      acc[t][1] = exp2f(acc[t][1]-nm0);
      acc[t][2] = exp2f(acc[t][2]-nm1);
      acc[t][3] = exp2f(acc[t][3]-nm1);
      s0 += acc[t][0]+acc[t][1];
      s1 += acc[t][2]+acc[t][3];
    }
    s0 += __shfl_xor_sync(0xffffffffu, s0, 1);
    s0 += __shfl_xor_sync(0xffffffffu, s0, 2);
    s1 += __shfl_xor_sync(0xffffffffu, s1, 1);
    s1 += __shfl_xor_sync(0xffffffffu, s1, 2);
    l0 = l0*cf0 + s0;
    l1 = l1*cf1 + s1;
    #pragma unroll
    for (int nt=0;nt<16;nt++){
      o[nt][0] *= cf0; o[nt][1] *= cf0;
      o[nt][2] *= cf1; o[nt][3] *= cf1;
    }

    const __half* Vbuf = Vs + buf*8704;
    int vrow = ((lane>>3)&1)*8 + (lane&7);
    int vcol = (lane>>4)*8;
    #pragma unroll
    for (int u=0;u<4;u++){
      unsigned ph[4];
      ph[0] = pack2h(acc[2*u  ][0], acc[2*u  ][1]);
      ph[1] = pack2h(acc[2*u  ][2], acc[2*u  ][3]);
      ph[2] = pack2h(acc[2*u+1][0], acc[2*u+1][1]);
      ph[3] = pack2h(acc[2*u+1][2], acc[2*u+1][3]);
      unsigned base = (unsigned)__cvta_generic_to_shared(
          Vbuf + (u*16 + vrow)*136 + vcol);
      #pragma unroll
      for (int dt=0;dt<8;dt++){
        unsigned v0,v1,v2,v3;
        LDSM_X4T(v0,v1,v2,v3, base + dt*32);
        MMAF16(o[dt*2  ][0],o[dt*2  ][1],o[dt*2  ][2],o[dt*2  ][3],
               ph[0],ph[1],ph[2],ph[3], v0,v1);
        MMAF16(o[dt*2+1][0],o[dt*2+1][1],o[dt*2+1][2],o[dt*2+1][3],
               ph[0],ph[1],ph[2],ph[3], v2,v3);
      }
    }
  }

  float i0 = 1.f/l0, i1 = 1.f/l1;
  int tok0 = b*Sn + qbase + r0 + g;
  __half* o0 = At + (size_t)tok0*1536 + h*128;
  __half* o1 = At + (size_t)(tok0+8)*1536 + h*128;
  #pragma unroll
  for (int nt=0;nt<16;nt++){
    int col = nt*8 + 2*tig;
    *(__half2*)(o0 + col) = __floats2half2_rn(o[nt][0]*i0, o[nt][1]*i0);
    *(__half2*)(o1 + col) = __floats2half2_rn(o[nt][2]*i1, o[nt][3]*i1);
  }
}

// ---------------- launch -----------------------------------------------------
extern "C" void kernel_launch(void* const* d_in, const int* in_sizes, int n_in,
                              void* d_out, int out_size) {
  (void)in_sizes; (void)n_in; (void)out_size;
  const float* hs   = (const float*)d_in[0];
  const float* rot  = (const float*)d_in[1];
  const float* Wkvd = (const float*)d_in[2];
  const float* Wqd  = (const float*)d_in[3];
  const float* Wku  = (const float*)d_in[4];
  const float* Wqu  = (const float*)d_in[5];
  const float* Wvu  = (const float*)d_in[6];
  const float* Wrk  = (const float*)d_in[7];
  const float* Wrq  = (const float*)d_in[8];
  const float* Wo   = (const float*)d_in[9];
  float* out = (float*)d_out;

  __half *hs16,*wqkv,*wkv,*wq,*wrk,*wob,*dA1,*at1,*qb,*kb,*vb,*kcvf,*krb,*qcqr;
  cudaGetSymbolAddress((void**)&hs16, g_hs16);
  cudaGetSymbolAddress((void**)&wqkv, g_Wqkv);
  cudaGetSymbolAddress((void**)&wkv , g_Wkv);
  cudaGetSymbolAddress((void**)&wq  , g_Wq);
  cudaGetSymbolAddress((void**)&wrk , g_Wrk);
  cudaGetSymbolAddress((void**)&wob , g_Wob);
  cudaGetSymbolAddress((void**)&dA1 , g_dA1);
  cudaGetSymbolAddress((void**)&kcvf, g_kcvf);
  cudaGetSymbolAddress((void**)&qcqr, g_qcqr);
  cudaGetSymbolAddress((void**)&krb , g_krb);
  cudaGetSymbolAddress((void**)&qb  , g_qb);
  cudaGetSymbolAddress((void**)&kb  , g_kb);
  cudaGetSymbolAddress((void**)&vb  , g_vb);
  cudaGetSymbolAddress((void**)&at1 , g_at1);

  // --- input conversions ---
  convA_kernel<<<(TOKn*1536/4)/256, 256>>>((const float4*)hs, hs16);
  {
    ConvJobs J;
    const float* Ws[8] = {Wkvd, Wqd, Wku, Wvu, Wqu, Wrq, Wrk, Wo};
    __half* Bs[8] = {wqkv, wqkv + (size_t)192*1536, wkv,
                     wkv + (size_t)768*192, wq, wq + (size_t)768*192,
                     wrk, wob};
    int Ks[8]  = {1536,1536,192,192,192,192,1536,1536};
    int Nsz[8] = {192,192,768,1536,768,768,768,1536};
    int acc = 0;
    for (int j = 0; j < 8; j++) {
      J.W[j] = Ws[j]; J.Bt[j] = Bs[j];
      J.K[j] = Ks[j]; J.N[j] = Nsz[j];
      J.bstart[j] = acc;
      acc += (Nsz[j]/32)*(Ks[j]/32);
    }
    J.bstart[8] = acc;
    convW_kernel<<<acc, dim3(32,8)>>>(J);
  }

  // --- GEMM smem sizes ---
  const int SM_64  = (128 +  64)*72*2*3;  // 82944
  const int SM_128 = (128 + 128)*72*2*3;  // 110592
  cudaFuncSetAttribute(hgemm_kernel<64,1>,
      cudaFuncAttributeMaxDynamicSharedMemorySize, SM_64);
  cudaFuncSetAttribute(hgemm_kernel<128,3>,
      cudaFuncAttributeMaxDynamicSharedMemorySize, SM_128);
  cudaFuncSetAttribute(hgemm_kernel<128,1>,
      cudaFuncAttributeMaxDynamicSharedMemorySize, SM_128);

  // --- qkvd: dA1 = hs @ [Wkvd|Wqd]  (single-pass, fp16 out, BN=64) ---
  {
    GJobs J{};
    J.j[0] = {hs16, wqkv, nullptr, dA1, 1536, 384, 1536, 1, 6};
    J.bstart[0] = 0; J.bstart[1] = 192;
    hgemm_kernel<64,1><<<192, 256, SM_64>>>(J);
  }
  // --- batched single-pass: krb | kcvf | qcqr (all fp16 out) ---
  {
    GJobs J{};
    J.j[0] = {hs16,    wrk, nullptr, krb,  1536,  768, 1536, 1,  6};
    J.j[1] = {dA1,     wkv, nullptr, kcvf,  384, 2304,  192, 1, 18};
    J.j[2] = {dA1+192, wq,  nullptr, qcqr,  384, 1536,  192, 1, 12};
    J.bstart[0] = 0; J.bstart[1] = 192; J.bstart[2] = 768; J.bstart[3] = 1152;
    hgemm_kernel<128,3><<<1152, 256, SM_128>>>(J);
  }

  // rope + layout (coalesced)
  assemble_kernel<<<dim3(Sn, Bn), 256>>>(qcqr, kcvf, krb, rot, qb, kb, vb);

  // flash attention (single-pass QK/PV, 2 CTAs/SM)
  cudaFuncSetAttribute(flash_kernel, cudaFuncAttributeMaxDynamicSharedMemorySize,
                       FLASH_SMEM);
  flash_kernel<<<dim3(16, Hn, Bn), 256, FLASH_SMEM>>>(qb, kb, vb, at1);

  // --- output projection: fp32 out ---
  {
    GJobs J{};
    J.j[0] = {at1, wob, out, nullptr, 1536, 1536, 1536, 0, 12};
    J.bstart[0] = 0; J.bstart[1] = 384;
    hgemm_kernel<128,1><<<384, 256, SM_128>>>(J);
  }
}

// round 14
// speedup vs baseline: 8.7895x; 1.0577x over previous
#include <cuda_runtime.h>
#include <cuda_fp16.h>
#include <cstdint>
#include <stdint.h>
#include <math.h>

#define Bn   2
#define Sn   2048
#define HIDn 1536
#define Hn   12
#define HDn  128
#define TOKn (Bn*Sn)   // 4096

// ---------------- scratch (device globals; no allocations allowed) ----------
__device__ __half g_hs16[(size_t)TOKn*1536];     // hidden single fp16
__device__ __half g_Wqkv[(size_t)384*1536];      // [n][k] single fp16
__device__ __half g_Wkv [(size_t)2304*192];
__device__ __half g_Wq  [(size_t)1536*192];
__device__ __half g_Wrk [(size_t)768*1536];
__device__ __half g_Wob [(size_t)1536*1536];
__device__ __half g_dA1 [(size_t)TOKn*384];      // [tok][kvd192|qd192] single fp16
__device__ __half g_kcvf[(size_t)TOKn*2304];     // fp16
__device__ __half g_qcqr[(size_t)TOKn*1536];     // fp16
__device__ __half g_krb [(size_t)TOKn*768];      // fp16
__device__ __half g_qb[(size_t)Bn*Hn*Sn*128];    // Q single fp16 (scaled)
__device__ __half g_kb[(size_t)Bn*Hn*Sn*128];    // K single
__device__ __half g_vb[(size_t)Bn*Hn*Sn*128];    // V single
__device__ __half g_at1[(size_t)TOKn*1536];      // attn out single fp16

// ---------------- helpers ----------------------------------------------------
__device__ __forceinline__ unsigned pack2h(float a, float b) {
  __half2 t = __floats2half2_rn(a, b);
  return *(unsigned*)&t;
}

#define MMAF16(d0,d1,d2,d3,a0,a1,a2,a3,b0,b1)                              \
  asm volatile("mma.sync.aligned.m16n8k16.row.col.f32.f16.f16.f32 "         \
    "{%0,%1,%2,%3},{%4,%5,%6,%7},{%8,%9},{%0,%1,%2,%3};"                    \
    : "+f"(d0),"+f"(d1),"+f"(d2),"+f"(d3)                                    \
    : "r"(a0),"r"(a1),"r"(a2),"r"(a3),"r"(b0),"r"(b1))
#define LDSM_X4(r0,r1,r2,r3,addr)                                           \
  asm volatile("ldmatrix.sync.aligned.m8n8.x4.shared.b16 "                  \
    "{%0,%1,%2,%3},[%4];"                                                   \
    : "=r"(r0),"=r"(r1),"=r"(r2),"=r"(r3) : "r"(addr))
#define LDSM_X4T(r0,r1,r2,r3,addr)                                          \
  asm volatile("ldmatrix.sync.aligned.m8n8.x4.trans.shared.b16 "            \
    "{%0,%1,%2,%3},[%4];"                                                   \
    : "=r"(r0),"=r"(r1),"=r"(r2),"=r"(r3) : "r"(addr))
#define CPASYNC16(dst, src)                                                 \
  asm volatile("cp.async.cg.shared.global [%0],[%1],16;" :: "r"(dst), "l"(src))

// ---------------- conversion kernels ----------------------------------------
__global__ __launch_bounds__(256)
void convA_kernel(const float4* __restrict__ X, __half* __restrict__ Y) {
  size_t i = (size_t)blockIdx.x*256 + threadIdx.x;
  float4 v = X[i];
  __half2 h0 = __floats2half2_rn(v.x, v.y);
  __half2 h1 = __floats2half2_rn(v.z, v.w);
  *(__half2*)(Y + i*4)     = h0;
  *(__half2*)(Y + i*4 + 2) = h1;
}

struct ConvJobs {
  const float* W[8];
  __half* Bt[8];
  int K[8], N[8];
  int bstart[9];
};
__global__ __launch_bounds__(256)
void convW_kernel(ConvJobs J) {
  __shared__ float t[32][33];
  int bx = blockIdx.x;
  int j = 0;
  while (bx >= J.bstart[j+1]) j++;
  int lb = bx - J.bstart[j];
  int nbn = J.N[j] >> 5;
  int n0 = (lb % nbn) << 5, k0 = (lb / nbn) << 5;
  const float* W = J.W[j];
  __half* Bt = J.Bt[j];
  int K = J.K[j], N = J.N[j];
  #pragma unroll
  for (int i = threadIdx.y; i < 32; i += 8)
    t[i][threadIdx.x] = W[(size_t)(k0+i)*N + n0 + threadIdx.x];
  __syncthreads();
  #pragma unroll
  for (int i = threadIdx.y; i < 32; i += 8) {
    int n = n0 + i, k = k0 + threadIdx.x;
    Bt[(size_t)n*K + k] = __float2half(t[threadIdx.x][i]);
  }
}

// ---------------- fp16 tensor-core GEMM (batched, 3-stage, BK=64) -----------
struct GJob {
  const __half *Am, *Bm;
  float* C; __half* Cb;
  int lda, N, K, outmode, nbx;
};
struct GJobs { GJob j[3]; int bstart[4]; };

template<int BN, int NJ>
__global__ __launch_bounds__(256)
void hgemm_kernel(GJobs JB) {
  constexpr int BOFF  = 128*72;
  constexpr int STAGE = (128 + BN)*72;
  constexpr int WN = BN/32, WM = 8/WN, MT = 128/(WM*16);

  extern __shared__ __half hsm[];
  int tid = threadIdx.x;
  int bid = blockIdx.x;
  int ji = 0;
  #pragma unroll
  for (int t = 1; t < NJ; t++) if (bid >= JB.bstart[t]) ji = t;
  GJob jb = JB.j[ji];
  int lb = bid - JB.bstart[ji];
  int bx = lb % jb.nbx, by = lb / jb.nbx;
  const __half* Am = jb.Am;
  const __half* Bm = jb.Bm;
  int lda = jb.lda, N = jb.N, K = jb.K;
  int KIT = K >> 6;

  auto load_st = [&](int it, int slot) {
    int kk = it << 6;
    __half* dst = hsm + slot*STAGE;
    #pragma unroll
    for (int p = 0; p < 4; p++) {
      int u = tid + (p << 8);
      int row = u >> 3, c = u & 7;
      size_t ga = (size_t)(by*128 + row)*lda + kk + c*8;
      unsigned dh = (unsigned)__cvta_generic_to_shared(dst + row*72 + c*8);
      CPASYNC16(dh, Am + ga);
    }
    #pragma unroll
    for (int p = 0; p < BN/32; p++) {
      int u = tid + (p << 8);
      int row = u >> 3, c = u & 7;
      const __half* sB = Bm + (size_t)(bx*BN + row)*K + kk + c*8;
      unsigned db = (unsigned)__cvta_generic_to_shared(dst + BOFF + row*72 + c*8);
      CPASYNC16(db, sB);
    }
    asm volatile("cp.async.commit_group;");
  };

  int wid = tid >> 5, lane = tid & 31;
  int wm = wid / WN, wn = wid % WN;
  int g = lane >> 2, tig = lane & 3;
  int lr = lane & 15, lc = (lane >> 4) << 3;

  float acc[MT][4][4];
  #pragma unroll
  for (int mt=0; mt<MT; mt++)
    #pragma unroll
    for (int nt=0; nt<4; nt++)
      #pragma unroll
      for (int r=0; r<4; r++) acc[mt][nt][r] = 0.f;

  load_st(0, 0);
  load_st(1, 1);

  for (int it = 0; it < KIT; ++it) {
    if (it + 1 < KIT) asm volatile("cp.async.wait_group 1;");
    else              asm volatile("cp.async.wait_group 0;");
    __syncthreads();
    if (it + 2 < KIT) load_st(it + 2, (it + 2) % 3);
    const __half* St = hsm + (it % 3)*STAGE;

    #pragma unroll
    for (int ks = 0; ks < 4; ks++) {
      unsigned b[4][2];
      #pragma unroll
      for (int bt = 0; bt < 2; bt++) {
        unsigned q0,q1,q2,q3;
        unsigned bd = (unsigned)__cvta_generic_to_shared(
            St + BOFF + (wn*32 + bt*16 + lr)*72 + ks*16 + lc);
        LDSM_X4(q0,q1,q2,q3, bd);
        b[2*bt  ][0] = q0; b[2*bt  ][1] = q2;
        b[2*bt+1][0] = q1; b[2*bt+1][1] = q3;
      }
      unsigned a[MT][4];
      #pragma unroll
      for (int mt = 0; mt < MT; mt++) {
        unsigned ad = (unsigned)__cvta_generic_to_shared(
            St + (wm*(MT*16) + mt*16 + lr)*72 + ks*16 + lc);
        LDSM_X4(a[mt][0], a[mt][1], a[mt][2], a[mt][3], ad);
      }
      #pragma unroll
      for (int mt = 0; mt < MT; mt++)
        #pragma unroll
        for (int nt = 0; nt < 4; nt++)
          MMAF16(acc[mt][nt][0],acc[mt][nt][1],acc[mt][nt][2],acc[mt][nt][3],
                 a[mt][0],a[mt][1],a[mt][2],a[mt][3],
                 b[nt][0],b[nt][1]);
    }
  }

  #pragma unroll
  for (int mt = 0; mt < MT; mt++) {
    #pragma unroll
    for (int nt = 0; nt < 4; nt++) {
      int row = by*128 + wm*(MT*16) + mt*16 + g;
      int col = bx*BN + wn*32 + nt*8 + 2*tig;
      if (jb.outmode == 0) {
        float2 v0 = make_float2(acc[mt][nt][0], acc[mt][nt][1]);
        float2 v1 = make_float2(acc[mt][nt][2], acc[mt][nt][3]);
        *(float2*)&jb.C[(size_t)row    *N + col] = v0;
        *(float2*)&jb.C[(size_t)(row+8)*N + col] = v1;
      } else {
        *(__half2*)&jb.Cb[(size_t)row    *N + col] =
            __floats2half2_rn(acc[mt][nt][0], acc[mt][nt][1]);
        *(__half2*)&jb.Cb[(size_t)(row+8)*N + col] =
            __floats2half2_rn(acc[mt][nt][2], acc[mt][nt][3]);
      }
    }
  }
}

// ---------------- assemble: RoPE + layout + scale (coalesced) ---------------
__global__ __launch_bounds__(256)
void assemble_kernel(const __half* __restrict__ qcqr, const __half* __restrict__ kcvf,
                     const __half* __restrict__ krb, const float* __restrict__ rot,
                     __half* __restrict__ Qh, __half* __restrict__ Kh,
                     __half* __restrict__ Vh) {
  int s = blockIdx.x, b = blockIdx.y;
  int tid = threadIdx.x;
  int token = b*Sn + s;
  const float* rrow = rot + (size_t)s*64;
  const float SCALE = 0.08838834764831845f * 1.4426950408889634f;

  #pragma unroll
  for (int it = 0; it < 6; it++) {
    int lin = it*256 + tid;
    int h = lin >> 7, d = lin & 127;
    size_t bhs = (size_t)(b*Hn + h)*Sn + s;

    Vh[bhs*128 + d] = kcvf[(size_t)token*2304 + 768 + h*HDn + d];

    float qv, kv;
    if (d < 64) {
      qv = __half2float(qcqr[(size_t)token*1536 + h*64 + d]);
      kv = __half2float(kcvf[(size_t)token*2304 + h*64 + d]);
    } else {
      int i = d - 64;
      const __half* qrow = qcqr + (size_t)token*1536 + 768 + h*64;
      const __half* krow = krb + (size_t)token*768 + h*64;
      if (i < 32) {
        float sn = rrow[i], cs = rrow[32+i];
        qv = __half2float(qrow[i])*cs - __half2float(qrow[i+32])*sn;
        kv = __half2float(krow[i])*cs - __half2float(krow[i+32])*sn;
      } else {
        int ii = i - 32;
        float sn = rrow[ii], cs = rrow[32+ii];
        qv = __half2float(qrow[ii])*sn + __half2float(qrow[ii+32])*cs;
        kv = __half2float(krow[ii])*sn + __half2float(krow[ii+32])*cs;
      }
    }
    Qh[bhs*128 + d] = __float2half(qv * SCALE);
    Kh[bhs*128 + d] = __float2half(kv);
  }
}

// ---------------- causal flash attention (QK 1-pass, PV 1-pass, exp2) -------
// grid (24 bh, 16 qtiles): qi is the SLOW dim -> longest blocks dispatch first.
#define FLASH_SMEM 104448

__global__ __launch_bounds__(256, 2)
void flash_kernel(const __half* __restrict__ Qg,
                  const __half* __restrict__ Kg,
                  const __half* __restrict__ Vg,
                  __half* __restrict__ At) {
  extern __shared__ __half fsm[];
  __half* Qs = fsm;              // [128][136]
  __half* Ks = fsm + 17408;      // [2 buf][64][136]
  __half* Vs = fsm + 34816;      // [2 buf][64][136]

  int bh = (int)blockIdx.x;          // 0..23
  int qi = 15 - (int)blockIdx.y;     // longest (qi=15) first
  int h = bh % Hn, b = bh / Hn;
  int qbase = qi*128;
  const __half* Qb = Qg + ((size_t)bh*Sn + qbase)*128;
  const __half* Kb = Kg + (size_t)bh*Sn*128;
  const __half* Vb = Vg + (size_t)bh*Sn*128;

  int tid = threadIdx.x;
  int wid = tid>>5, lane = tid&31, g = lane>>2, tig = lane&3;
  int lr = lane & 15, lc = (lane >> 4) << 3;
  int jmax = 2*qi + 2;
  int r0 = wid*16;

  #pragma unroll
  for (int p=0;p<8;p++){
    int lin = tid + p*256;
    int row = lin>>4, c = lin&15;
    const __half* src = Qb + (size_t)row*128 + c*8;
    unsigned d = (unsigned)__cvta_generic_to_shared(Qs + row*136 + c*8);
    CPASYNC16(d, src);
  }
  auto load_kv = [&](int jt, int buf){
    #pragma unroll
    for (int p=0;p<4;p++){
      int lin = tid + p*256;
      int row = lin>>4, c = lin&15;
      size_t s_off = (size_t)(jt*64 + row)*128 + c*8;
      int doff = buf*8704 + row*136 + c*8;
      unsigned dk = (unsigned)__cvta_generic_to_shared(Ks + doff);
      CPASYNC16(dk, Kb + s_off);
      unsigned dv = (unsigned)__cvta_generic_to_shared(Vs + doff);
      CPASYNC16(dv, Vb + s_off);
    }
    asm volatile("cp.async.commit_group;");
  };
  load_kv(0, 0);

  float o[16][4];
  #pragma unroll
  for (int nt=0;nt<16;nt++)
    #pragma unroll
    for (int r=0;r<4;r++) o[nt][r] = 0.f;
  float m0=-1e30f, m1=-1e30f, l0=0.f, l1=0.f;

  for (int jt = 0; jt < jmax; jt++) {
    int buf = jt & 1;
    asm volatile("cp.async.wait_group 0;");
    __syncthreads();
    if (jt + 1 < jmax) load_kv(jt+1, buf^1);

    const __half* Kbuf = Ks + buf*8704;
    float acc[8][4];
    #pragma unroll
    for (int t=0;t<8;t++)
      #pragma unroll
      for (int r=0;r<4;r++) acc[t][r] = 0.f;

    #pragma unroll
    for (int ks=0; ks<8; ks++){
      unsigned ah[4];
      {
        unsigned qd = (unsigned)__cvta_generic_to_shared(
            Qs + (r0 + lr)*136 + ks*16 + lc);
        LDSM_X4(ah[0],ah[1],ah[2],ah[3], qd);
      }
      unsigned bk[8][2];
      #pragma unroll
      for (int t16=0; t16<4; t16++){
        unsigned q0,q1,q2,q3;
        unsigned kd = (unsigned)__cvta_generic_to_shared(
            Kbuf + (t16*16 + lr)*136 + ks*16 + lc);
        LDSM_X4(q0,q1,q2,q3, kd);
        bk[2*t16  ][0] = q0; bk[2*t16  ][1] = q2;
        bk[2*t16+1][0] = q1; bk[2*t16+1][1] = q3;
      }
      #pragma unroll
      for (int t=0;t<8;t++)
        MMAF16(acc[t][0],acc[t][1],acc[t][2],acc[t][3],
               ah[0],ah[1],ah[2],ah[3], bk[t][0],bk[t][1]);
    }

    if (jt >= jmax-2) {
      int rg0 = qbase + r0 + g, rg1 = rg0 + 8;
      #pragma unroll
      for (int t=0;t<8;t++){
        int c0 = jt*64 + t*8 + 2*tig;
        if (c0   > rg0) acc[t][0] = -1e30f;
        if (c0+1 > rg0) acc[t][1] = -1e30f;
        if (c0   > rg1) acc[t][2] = -1e30f;
        if (c0+1 > rg1) acc[t][3] = -1e30f;
      }
    }

    float mx0=-1e30f, mx1=-1e30f;
    #pragma unroll
    for (int t=0;t<8;t++){
      mx0 = fmaxf(mx0, fmaxf(acc[t][0],acc[t][1]));
      mx1 = fmaxf(mx1, fmaxf(acc[t][2],acc[t][3]));
    }
    mx0 = fmaxf(mx0, __shfl_xor_sync(0xffffffffu, mx0, 1));
    mx0 = fmaxf(mx0, __shfl_xor_sync(0xffffffffu, mx0, 2));
    mx1 = fmaxf(mx1, __shfl_xor_sync(0xffffffffu, mx1, 1));
    mx1 = fmaxf(mx1, __shfl_xor_sync(0xffffffffu, mx1, 2));
    float nm0 = fmaxf(m0, mx0), nm1 = fmaxf(m1, mx1);
    float cf0 = exp2f(m0 - nm0), cf1 = exp2f(m1 - nm1);
    m0 = nm0; m1 = nm1;
    float s0 = 0.f, s1 = 0.f;
    #pragma unroll
    for (int t=0;t<8;t++){
      acc[t][0] = exp2f(acc[t][0]-nm0);
      acc[t][1] = exp2f(acc[t][1]-nm0);
      acc[t][2] = exp2f(acc[t][2]-nm1);
      acc[t][3] = exp2f(acc[t][3]-nm1);
      s0 += acc[t][0]+acc[t][1];
      s1 += acc[t][2]+acc[t][3];
    }
    s0 += __shfl_xor_sync(0xffffffffu, s0, 1);
    s0 += __shfl_xor_sync(0xffffffffu, s0, 2);
    s1 += __shfl_xor_sync(0xffffffffu, s1, 1);
    s1 += __shfl_xor_sync(0xffffffffu, s1, 2);
    l0 = l0*cf0 + s0;
    l1 = l1*cf1 + s1;
    #pragma unroll
    for (int nt=0;nt<16;nt++){
      o[nt][0] *= cf0; o[nt][1] *= cf0;
      o[nt][2] *= cf1; o[nt][3] *= cf1;
    }

    const __half* Vbuf = Vs + buf*8704;
    int vrow = ((lane>>3)&1)*8 + (lane&7);
    int vcol = (lane>>4)*8;
    #pragma unroll
    for (int u=0;u<4;u++){
      unsigned ph[4];
      ph[0] = pack2h(acc[2*u  ][0], acc[2*u  ][1]);
      ph[1] = pack2h(acc[2*u  ][2], acc[2*u  ][3]);
      ph[2] = pack2h(acc[2*u+1][0], acc[2*u+1][1]);
      ph[3] = pack2h(acc[2*u+1][2], acc[2*u+1][3]);
      unsigned base = (unsigned)__cvta_generic_to_shared(
          Vbuf + (u*16 + vrow)*136 + vcol);
      #pragma unroll
      for (int dt=0;dt<8;dt++){
        unsigned v0,v1,v2,v3;
        LDSM_X4T(v0,v1,v2,v3, base + dt*32);
        MMAF16(o[dt*2  ][0],o[dt*2  ][1],o[dt*2  ][2],o[dt*2  ][3],
               ph[0],ph[1],ph[2],ph[3], v0,v1);
        MMAF16(o[dt*2+1][0],o[dt*2+1][1],o[dt*2+1][2],o[dt*2+1][3],
               ph[0],ph[1],ph[2],ph[3], v2,v3);
      }
    }
  }

  float i0 = 1.f/l0, i1 = 1.f/l1;
  int tok0 = b*Sn + qbase + r0 + g;
  __half* o0 = At + (size_t)tok0*1536 + h*128;
  __half* o1 = At + (size_t)(tok0+8)*1536 + h*128;
  #pragma unroll
  for (int nt=0;nt<16;nt++){
    int col = nt*8 + 2*tig;
    *(__half2*)(o0 + col) = __floats2half2_rn(o[nt][0]*i0, o[nt][1]*i0);
    *(__half2*)(o1 + col) = __floats2half2_rn(o[nt][2]*i1, o[nt][3]*i1);
  }
}

// ---------------- launch -----------------------------------------------------
extern "C" void kernel_launch(void* const* d_in, const int* in_sizes, int n_in,
                              void* d_out, int out_size) {
  (void)in_sizes; (void)n_in; (void)out_size;
  const float* hs   = (const float*)d_in[0];
  const float* rot  = (const float*)d_in[1];
  const float* Wkvd = (const float*)d_in[2];
  const float* Wqd  = (const float*)d_in[3];
  const float* Wku  = (const float*)d_in[4];
  const float* Wqu  = (const float*)d_in[5];
  const float* Wvu  = (const float*)d_in[6];
  const float* Wrk  = (const float*)d_in[7];
  const float* Wrq  = (const float*)d_in[8];
  const float* Wo   = (const float*)d_in[9];
  float* out = (float*)d_out;

  __half *hs16,*wqkv,*wkv,*wq,*wrk,*wob,*dA1,*at1,*qb,*kb,*vb,*kcvf,*krb,*qcqr;
  cudaGetSymbolAddress((void**)&hs16, g_hs16);
  cudaGetSymbolAddress((void**)&wqkv, g_Wqkv);
  cudaGetSymbolAddress((void**)&wkv , g_Wkv);
  cudaGetSymbolAddress((void**)&wq  , g_Wq);
  cudaGetSymbolAddress((void**)&wrk , g_Wrk);
  cudaGetSymbolAddress((void**)&wob , g_Wob);
  cudaGetSymbolAddress((void**)&dA1 , g_dA1);
  cudaGetSymbolAddress((void**)&kcvf, g_kcvf);
  cudaGetSymbolAddress((void**)&qcqr, g_qcqr);
  cudaGetSymbolAddress((void**)&krb , g_krb);
  cudaGetSymbolAddress((void**)&qb  , g_qb);
  cudaGetSymbolAddress((void**)&kb  , g_kb);
  cudaGetSymbolAddress((void**)&vb  , g_vb);
  cudaGetSymbolAddress((void**)&at1 , g_at1);

  // --- input conversions ---
  convA_kernel<<<(TOKn*1536/4)/256, 256>>>((const float4*)hs, hs16);
  {
    ConvJobs J;
    const float* Ws[8] = {Wkvd, Wqd, Wku, Wvu, Wqu, Wrq, Wrk, Wo};
    __half* Bs[8] = {wqkv, wqkv + (size_t)192*1536, wkv,
                     wkv + (size_t)768*192, wq, wq + (size_t)768*192,
                     wrk, wob};
    int Ks[8]  = {1536,1536,192,192,192,192,1536,1536};
    int Nsz[8] = {192,192,768,1536,768,768,768,1536};
    int acc = 0;
    for (int j = 0; j < 8; j++) {
      J.W[j] = Ws[j]; J.Bt[j] = Bs[j];
      J.K[j] = Ks[j]; J.N[j] = Nsz[j];
      J.bstart[j] = acc;
      acc += (Nsz[j]/32)*(Ks[j]/32);
    }
    J.bstart[8] = acc;
    convW_kernel<<<acc, dim3(32,8)>>>(J);
  }

  // --- GEMM smem sizes ---
  const int SM_64  = (128 +  64)*72*2*3;  // 82944
  const int SM_128 = (128 + 128)*72*2*3;  // 110592
  cudaFuncSetAttribute(hgemm_kernel<64,1>,
      cudaFuncAttributeMaxDynamicSharedMemorySize, SM_64);
  cudaFuncSetAttribute(hgemm_kernel<128,3>,
      cudaFuncAttributeMaxDynamicSharedMemorySize, SM_128);

  // --- qkvd: dA1 = hs @ [Wkvd|Wqd]  (single-pass, fp16 out, BN=64) ---
  {
    GJobs J{};
    J.j[0] = {hs16, wqkv, nullptr, dA1, 1536, 384, 1536, 1, 6};
    J.bstart[0] = 0; J.bstart[1] = 192;
    hgemm_kernel<64,1><<<192, 256, SM_64>>>(J);
  }
  // --- batched single-pass: krb | kcvf | qcqr (all fp16 out) ---
  {
    GJobs J{};
    J.j[0] = {hs16,    wrk, nullptr, krb,  1536,  768, 1536, 1,  6};
    J.j[1] = {dA1,     wkv, nullptr, kcvf,  384, 2304,  192, 1, 18};
    J.j[2] = {dA1+192, wq,  nullptr, qcqr,  384, 1536,  192, 1, 12};
    J.bstart[0] = 0; J.bstart[1] = 192; J.bstart[2] = 768; J.bstart[3] = 1152;
    hgemm_kernel<128,3><<<1152, 256, SM_128>>>(J);
  }

  // rope + layout (coalesced)
  assemble_kernel<<<dim3(Sn, Bn), 256>>>(qcqr, kcvf, krb, rot, qb, kb, vb);

  // flash attention: qi slowest -> LPT dispatch order
  cudaFuncSetAttribute(flash_kernel, cudaFuncAttributeMaxDynamicSharedMemorySize,
                       FLASH_SMEM);
  flash_kernel<<<dim3(Hn*Bn, 16), 256, FLASH_SMEM>>>(qb, kb, vb, at1);

  // --- output projection: BN=64 (768 blocks -> finer wave packing) ---
  {
    GJobs J{};
    J.j[0] = {at1, wob, out, nullptr, 1536, 1536, 1536, 0, 24};
    J.bstart[0] = 0; J.bstart[1] = 768;
    hgemm_kernel<64,1><<<768, 256, SM_64>>>(J);
  }
}